// round 9
// baseline (speedup 1.0000x reference)
#include <cuda_runtime.h>
#include <cuda_bf16.h>
#include <math.h>

// ---------------------------------------------------------------------------
// Problem constants
// ---------------------------------------------------------------------------
#define BSZ   16
#define CCH   2048
#define HW    128
#define C8    256
#define NV    16
#define VV    128
#define GNUM  2

// ------------------------- scratch (device globals) ------------------------
__device__ __align__(256) float d_q   [BSZ * C8 * HW];
__device__ __align__(256) float d_k   [BSZ * C8 * HW];
__device__ __align__(256) float d_v   [BSZ * CCH * HW];
__device__ __align__(256) float d_att1[BSZ * HW * HW];
__device__ __align__(256) float d_y1  [BSZ * CCH * HW];
__device__ __align__(256) float d_h   [NV * VV * CCH];
__device__ __align__(256) float d_ip  [NV * VV * VV];
__device__ __align__(256) float d_graph[NV * VV * VV];
__device__ __align__(256) float d_hp  [NV * VV * CCH];
__device__ __align__(256) float d_gbuf[NV * VV * CCH];
__device__ __align__(256) float d_mean[CCH];
__device__ __align__(256) float d_var [CCH];

// ---------------------- shared mma/ldsm/split helpers -----------------------
__device__ __forceinline__ void ldsm4(unsigned* r, unsigned addr) {
    asm volatile("ldmatrix.sync.aligned.m8n8.x4.shared.b16 {%0,%1,%2,%3}, [%4];"
        : "=r"(r[0]), "=r"(r[1]), "=r"(r[2]), "=r"(r[3]) : "r"(addr));
}
__device__ __forceinline__ void ldsm4t(unsigned* r, unsigned addr) {
    asm volatile("ldmatrix.sync.aligned.m8n8.x4.trans.shared.b16 {%0,%1,%2,%3}, [%4];"
        : "=r"(r[0]), "=r"(r[1]), "=r"(r[2]), "=r"(r[3]) : "r"(addr));
}
__device__ __forceinline__ void mma16816(float* c, const unsigned* a, const unsigned* b) {
    asm volatile("mma.sync.aligned.m16n8k16.row.col.f32.bf16.bf16.f32 "
        "{%0,%1,%2,%3}, {%4,%5,%6,%7}, {%8,%9}, {%0,%1,%2,%3};"
        : "+f"(c[0]), "+f"(c[1]), "+f"(c[2]), "+f"(c[3])
        : "r"(a[0]), "r"(a[1]), "r"(a[2]), "r"(a[3]), "r"(b[0]), "r"(b[1]));
}
__device__ __forceinline__ void bsplit(float x, __nv_bfloat16& h, __nv_bfloat16& l) {
    h = __float2bfloat16(x);
    l = __float2bfloat16(x - __bfloat162float(h));
}
__device__ __forceinline__ unsigned packbf(float a, float b) {
    __nv_bfloat162 p; p.x = __float2bfloat16(a); p.y = __float2bfloat16(b);
    return *(unsigned*)&p;
}
__device__ __forceinline__ unsigned packlo(float a, float b, unsigned hipack) {
    __nv_bfloat162 h = *(__nv_bfloat162*)&hipack;
    return packbf(a - __bfloat162float(h.x), b - __bfloat162float(h.y));
}

// ======================= bf16-split tensor-core GEMM ========================
// 128 threads, 4 warps, warp tile 64x64 (fat tiles -> fewer ldsm per mma).
// Block tile 128x128, K-step 32, double-buffered. acc = AhBh + AhBl + AlBh.
#define TST   40
#define TTILE (128 * TST)
#define TSMEM (2 * 4 * TTILE * 2)

template<int TA, int TB>
__global__ __launch_bounds__(128)
void tgemm_kernel(const float* __restrict__ Ag, const float* __restrict__ Bg,
                  float* __restrict__ Cg,
                  int M, int N, int K,
                  long sA, long sB, long sC,
                  const float* __restrict__ bias,
                  const float* __restrict__ Res, long sRes,
                  float alphaH, const float* __restrict__ alphaD)
{
    extern __shared__ __align__(16) __nv_bfloat16 ts[];

    const int bz = blockIdx.z;
    const float* A = Ag + (long)bz * sA;
    const float* B = Bg + (long)bz * sB;
    float*       C = Cg + (long)bz * sC;

    const int m0 = blockIdx.y * 128;
    const int n0 = blockIdx.x * 128;
    const int tid  = threadIdx.x;
    const int wid  = tid >> 5;           // 0..3
    const int lane = tid & 31;
    const int warp_m = (wid >> 1) * 64;
    const int warp_n = (wid & 1) * 64;
    const int mi = lane >> 3, ri = lane & 7;
    const int g  = lane >> 2, t  = lane & 3;

    const unsigned sbase = (unsigned)__cvta_generic_to_shared(ts);

    unsigned aoff[4], boff[4];
#pragma unroll
    for (int fi = 0; fi < 4; fi++)
        aoff[fi] = ((warp_m + fi * 16 + ((mi & 1) << 3) + ri) * TST + ((mi >> 1) << 3)) * 2;
#pragma unroll
    for (int fp = 0; fp < 4; fp++)
        boff[fp] = ((warp_n + fp * 16 + ((mi >> 1) << 3) + ri) * TST + ((mi & 1) << 3)) * 2;

    float acc[4][8][4];
#pragma unroll
    for (int i = 0; i < 4; i++)
#pragma unroll
        for (int j = 0; j < 8; j++)
#pragma unroll
            for (int q = 0; q < 4; q++) acc[i][j][q] = 0.f;

    float4 pa[8], pb[8];
    const int rA = tid;                         // direct: one full 32-col row
    const int kA = tid >> 2, mA = (tid & 3) * 32;  // trans: 8 float4 along M/N

#define LOADG(k0)                                                              \
    do {                                                                       \
        if (TA == 0) {                                                         \
            _Pragma("unroll")                                                  \
            for (int j = 0; j < 8; j++)                                        \
                pa[j] = *(const float4*)&A[(long)(m0 + rA) * K + (k0) + 4 * j]; \
        } else {                                                               \
            _Pragma("unroll")                                                  \
            for (int j = 0; j < 8; j++)                                        \
                pa[j] = *(const float4*)&A[(long)((k0) + kA) * M + m0 + mA + 4 * j]; \
        }                                                                      \
        if (TB == 1) {                                                         \
            _Pragma("unroll")                                                  \
            for (int j = 0; j < 8; j++)                                        \
                pb[j] = *(const float4*)&B[(long)(n0 + rA) * K + (k0) + 4 * j]; \
        } else {                                                               \
            _Pragma("unroll")                                                  \
            for (int j = 0; j < 8; j++)                                        \
                pb[j] = *(const float4*)&B[(long)((k0) + kA) * N + n0 + mA + 4 * j]; \
        }                                                                      \
    } while (0)

#define CVSTORE(bf)                                                            \
    do {                                                                       \
        __nv_bfloat16* Ah = ts + ((bf) * 4 + 0) * TTILE;                       \
        __nv_bfloat16* Al = ts + ((bf) * 4 + 1) * TTILE;                       \
        __nv_bfloat16* Bh = ts + ((bf) * 4 + 2) * TTILE;                       \
        __nv_bfloat16* Bl = ts + ((bf) * 4 + 3) * TTILE;                       \
        _Pragma("unroll")                                                      \
        for (int j = 0; j < 8; j++) {                                          \
            float v[4] = { pa[j].x, pa[j].y, pa[j].z, pa[j].w };               \
            __nv_bfloat16 h[4], l[4];                                          \
            _Pragma("unroll")                                                  \
            for (int i = 0; i < 4; i++) bsplit(v[i], h[i], l[i]);              \
            if (TA == 0) {                                                     \
                int base = rA * TST + 4 * j;                                   \
                __nv_bfloat162 h01; h01.x = h[0]; h01.y = h[1];                \
                __nv_bfloat162 h23; h23.x = h[2]; h23.y = h[3];                \
                __nv_bfloat162 l01; l01.x = l[0]; l01.y = l[1];                \
                __nv_bfloat162 l23; l23.x = l[2]; l23.y = l[3];                \
                *(__nv_bfloat162*)(Ah + base)     = h01;                       \
                *(__nv_bfloat162*)(Ah + base + 2) = h23;                       \
                *(__nv_bfloat162*)(Al + base)     = l01;                       \
                *(__nv_bfloat162*)(Al + base + 2) = l23;                       \
            } else {                                                           \
                _Pragma("unroll")                                              \
                for (int i = 0; i < 4; i++) {                                  \
                    int row = mA + 4 * j + i;                                  \
                    Ah[row * TST + kA] = h[i];                                 \
                    Al[row * TST + kA] = l[i];                                 \
                }                                                              \
            }                                                                  \
        }                                                                      \
        _Pragma("unroll")                                                      \
        for (int j = 0; j < 8; j++) {                                          \
            float v[4] = { pb[j].x, pb[j].y, pb[j].z, pb[j].w };               \
            __nv_bfloat16 h[4], l[4];                                          \
            _Pragma("unroll")                                                  \
            for (int i = 0; i < 4; i++) bsplit(v[i], h[i], l[i]);              \
            if (TB == 1) {                                                     \
                int base = rA * TST + 4 * j;                                   \
                __nv_bfloat162 h01; h01.x = h[0]; h01.y = h[1];                \
                __nv_bfloat162 h23; h23.x = h[2]; h23.y = h[3];                \
                __nv_bfloat162 l01; l01.x = l[0]; l01.y = l[1];                \
                __nv_bfloat162 l23; l23.x = l[2]; l23.y = l[3];                \
                *(__nv_bfloat162*)(Bh + base)     = h01;                       \
                *(__nv_bfloat162*)(Bh + base + 2) = h23;                       \
                *(__nv_bfloat162*)(Bl + base)     = l01;                       \
                *(__nv_bfloat162*)(Bl + base + 2) = l23;                       \
            } else {                                                           \
                _Pragma("unroll")                                              \
                for (int i = 0; i < 4; i++) {                                  \
                    int row = mA + 4 * j + i;                                  \
                    Bh[row * TST + kA] = h[i];                                 \
                    Bl[row * TST + kA] = l[i];                                 \
                }                                                              \
            }                                                                  \
        }                                                                      \
    } while (0)

// B fragments held across the fi loop; A streamed per fi (bounds reg pressure).
#define MMASTEP(bf)                                                            \
    do {                                                                       \
        const unsigned bAh = sbase + ((bf) * 4 + 0) * TTILE * 2;               \
        const unsigned bAl = sbase + ((bf) * 4 + 1) * TTILE * 2;               \
        const unsigned bBh = sbase + ((bf) * 4 + 2) * TTILE * 2;               \
        const unsigned bBl = sbase + ((bf) * 4 + 3) * TTILE * 2;               \
        _Pragma("unroll")                                                      \
        for (int kk = 0; kk < 2; kk++) {                                       \
            unsigned bh[4][4], bl[4][4];                                       \
            _Pragma("unroll")                                                  \
            for (int fp = 0; fp < 4; fp++) {                                   \
                ldsm4(bh[fp], bBh + boff[fp] + kk * 32);                       \
                ldsm4(bl[fp], bBl + boff[fp] + kk * 32);                       \
            }                                                                  \
            _Pragma("unroll")                                                  \
            for (int fi = 0; fi < 4; fi++) {                                   \
                unsigned ah[4], al[4];                                         \
                ldsm4(ah, bAh + aoff[fi] + kk * 32);                           \
                ldsm4(al, bAl + aoff[fi] + kk * 32);                           \
                _Pragma("unroll")                                              \
                for (int fp = 0; fp < 4; fp++)                                 \
                    _Pragma("unroll")                                          \
                    for (int hh = 0; hh < 2; hh++) {                           \
                        float* c = acc[fi][fp * 2 + hh];                       \
                        mma16816(c, ah, &bh[fp][2 * hh]);                      \
                        mma16816(c, ah, &bl[fp][2 * hh]);                      \
                        mma16816(c, al, &bh[fp][2 * hh]);                      \
                    }                                                          \
            }                                                                  \
        }                                                                      \
    } while (0)

    LOADG(0);
    CVSTORE(0);
    __syncthreads();

    const int nt = K / 32;
    for (int tI = 0; tI < nt; tI++) {
        if (tI + 1 < nt) LOADG((tI + 1) * 32);
        MMASTEP(tI & 1);
        if (tI + 1 < nt) {
            CVSTORE((tI + 1) & 1);
            __syncthreads();
        }
    }

    const float alpha = alphaD ? *alphaD : alphaH;
#pragma unroll
    for (int fi = 0; fi < 4; fi++) {
        const int m = m0 + warp_m + fi * 16 + g;
        const float bi0 = bias ? __ldg(&bias[m])     : 0.f;
        const float bi1 = bias ? __ldg(&bias[m + 8]) : 0.f;
#pragma unroll
        for (int fj = 0; fj < 8; fj++) {
            const int n = n0 + warp_n + fj * 8 + t * 2;
            const float* c = acc[fi][fj];
            const long off0 = (long)m * N + n;
            const long off1 = (long)(m + 8) * N + n;
            float2 o0, o1;
            o0.x = alpha * c[0] + bi0; o0.y = alpha * c[1] + bi0;
            o1.x = alpha * c[2] + bi1; o1.y = alpha * c[3] + bi1;
            if (Res) {
                float2 r0 = *(const float2*)&Res[(long)bz * sRes + off0];
                float2 r1 = *(const float2*)&Res[(long)bz * sRes + off1];
                o0.x += r0.x; o0.y += r0.y;
                o1.x += r1.x; o1.y += r1.y;
            }
            *(float2*)&C[off0] = o0;
            *(float2*)&C[off1] = o1;
        }
    }
#undef LOADG
#undef CVSTORE
#undef MMASTEP
}

// --------------------------- reductions ------------------------------------
__device__ __forceinline__ float warpMax(float v) {
#pragma unroll
    for (int o = 16; o; o >>= 1) v = fmaxf(v, __shfl_xor_sync(0xffffffffu, v, o));
    return v;
}
__device__ __forceinline__ float warpSum(float v) {
#pragma unroll
    for (int o = 16; o; o >>= 1) v += __shfl_xor_sync(0xffffffffu, v, o);
    return v;
}

// in-place row softmax; one block per row
__global__ void softmax_kernel(float* __restrict__ d, int ncols)
{
    __shared__ float red[32];
    __shared__ float bcast;
    const long row = blockIdx.x;
    float* p = d + row * (long)ncols;
    const int tid = threadIdx.x, nt = blockDim.x;

    float m = -1e30f;
    for (int i = tid; i < ncols; i += nt) m = fmaxf(m, p[i]);
    m = warpMax(m);
    if ((tid & 31) == 0) red[tid >> 5] = m;
    __syncthreads();
    if (tid < 32) {
        float v = (tid < (nt >> 5)) ? red[tid] : -1e30f;
        v = warpMax(v);
        if (tid == 0) bcast = v;
    }
    __syncthreads();
    m = bcast;

    float s = 0.f;
    for (int i = tid; i < ncols; i += nt) {
        float e = __expf(p[i] - m);
        p[i] = e;
        s += e;
    }
    __syncthreads();
    s = warpSum(s);
    if ((tid & 31) == 0) red[tid >> 5] = s;
    __syncthreads();
    if (tid < 32) {
        float v = (tid < (nt >> 5)) ? red[tid] : 0.f;
        v = warpSum(v);
        if (tid == 0) bcast = v;
    }
    __syncthreads();
    const float inv = 1.f / bcast;
    for (int i = tid; i < ncols; i += nt) p[i] *= inv;
}

// ================= tensor-core fused CAM (flash style) ======================
#define CST   136
#define CTILE (128 * CST)
#define CAM_SMEM (4 * CTILE * 2)

__global__ __launch_bounds__(256)
void cam_tc_kernel(const float* __restrict__ y1g,
                   const float* __restrict__ gptr,
                   float* __restrict__ outg)
{
    extern __shared__ __align__(16) __nv_bfloat16 cs[];
    __nv_bfloat16* Qh = cs;
    __nv_bfloat16* Ql = cs + CTILE;
    __nv_bfloat16* Kh = cs + 2 * CTILE;
    __nv_bfloat16* Kl = cs + 3 * CTILE;

    const int b  = blockIdx.y;
    const int c0 = blockIdx.x * 128;
    const float* Y = y1g + (long)b * CCH * HW;

    const int tid = threadIdx.x, wid = tid >> 5, lane = tid & 31;
    const int mi = lane >> 3, ri = lane & 7, g = lane >> 2, t = lane & 3;

    const unsigned sb  = (unsigned)__cvta_generic_to_shared(cs);
    const unsigned bQh = sb;
    const unsigned bQl = sb + CTILE * 2;
    const unsigned bKh = sb + 2 * CTILE * 2;
    const unsigned bKl = sb + 3 * CTILE * 2;

    const unsigned aoff = ((wid * 16 + ((mi & 1) << 3) + ri) * CST + ((mi >> 1) << 3)) * 2;
    const unsigned bS = ((((mi >> 1) << 3) + ri) * CST + ((mi & 1) << 3)) * 2;
    const unsigned bT = ((((mi & 1) << 3) + ri) * CST + ((mi >> 1) << 3)) * 2;

    for (int idx = tid; idx < 128 * 32; idx += 256) {
        int r = idx >> 5, hw = (idx & 31) * 4;
        float4 v = *(const float4*)&Y[(long)(c0 + r) * HW + hw];
        __nv_bfloat16 h0,l0,h1,l1,h2,l2,h3,l3;
        bsplit(v.x,h0,l0); bsplit(v.y,h1,l1); bsplit(v.z,h2,l2); bsplit(v.w,h3,l3);
        __nv_bfloat162 a; __nv_bfloat162 c;
        __nv_bfloat162* ph = (__nv_bfloat162*)(Qh + r * CST + hw);
        __nv_bfloat162* pl = (__nv_bfloat162*)(Ql + r * CST + hw);
        a.x = h0; a.y = h1; ph[0] = a;  a.x = h2; a.y = h3; ph[1] = a;
        c.x = l0; c.y = l1; pl[0] = c;  c.x = l2; c.y = l3; pl[1] = c;
    }

    float Sa[16][4], Oa[16][4];
    float m0r = -1e30f, m1r = -1e30f, l0r = 0.f, l1r = 0.f;
#pragma unroll
    for (int j = 0; j < 16; j++) { Oa[j][0]=Oa[j][1]=Oa[j][2]=Oa[j][3]=0.f; }

    for (int tI = 0; tI < 16; tI++) {
        __syncthreads();
        for (int idx = tid; idx < 128 * 32; idx += 256) {
            int d = idx >> 5, hw = (idx & 31) * 4;
            float4 v = *(const float4*)&Y[(long)(tI * 128 + d) * HW + hw];
            __nv_bfloat16 h0,l0,h1,l1,h2,l2,h3,l3;
            bsplit(v.x,h0,l0); bsplit(v.y,h1,l1); bsplit(v.z,h2,l2); bsplit(v.w,h3,l3);
            __nv_bfloat162 a; __nv_bfloat162 c;
            __nv_bfloat162* ph = (__nv_bfloat162*)(Kh + d * CST + hw);
            __nv_bfloat162* pl = (__nv_bfloat162*)(Kl + d * CST + hw);
            a.x = h0; a.y = h1; ph[0] = a;  a.x = h2; a.y = h3; ph[1] = a;
            c.x = l0; c.y = l1; pl[0] = c;  c.x = l2; c.y = l3; pl[1] = c;
        }
        __syncthreads();

#pragma unroll
        for (int j = 0; j < 16; j++) { Sa[j][0]=Sa[j][1]=Sa[j][2]=Sa[j][3]=0.f; }
#pragma unroll
        for (int ks = 0; ks < 8; ks++) {
            unsigned ah[4], al[4];
            ldsm4(ah, bQh + aoff + ks * 32);
            ldsm4(al, bQl + aoff + ks * 32);
#pragma unroll
            for (int fp = 0; fp < 8; fp++) {
                unsigned bh[4], bl[4];
                ldsm4(bh, bKh + bS + fp * (16 * CST * 2) + ks * 32);
                ldsm4(bl, bKl + bS + fp * (16 * CST * 2) + ks * 32);
#pragma unroll
                for (int hh = 0; hh < 2; hh++) {
                    float* c = Sa[fp * 2 + hh];
                    mma16816(c, ah, &bh[2 * hh]);
                    mma16816(c, ah, &bl[2 * hh]);
                    mma16816(c, al, &bh[2 * hh]);
                }
            }
        }

        float mx0 = -1e30f, mx1 = -1e30f;
#pragma unroll
        for (int j = 0; j < 16; j++) {
            mx0 = fmaxf(mx0, fmaxf(-Sa[j][0], -Sa[j][1]));
            mx1 = fmaxf(mx1, fmaxf(-Sa[j][2], -Sa[j][3]));
        }
        mx0 = fmaxf(mx0, __shfl_xor_sync(0xffffffffu, mx0, 1));
        mx0 = fmaxf(mx0, __shfl_xor_sync(0xffffffffu, mx0, 2));
        mx1 = fmaxf(mx1, __shfl_xor_sync(0xffffffffu, mx1, 1));
        mx1 = fmaxf(mx1, __shfl_xor_sync(0xffffffffu, mx1, 2));
        const float mn0 = fmaxf(m0r, mx0), mn1 = fmaxf(m1r, mx1);
        const float sc0 = __expf(m0r - mn0), sc1 = __expf(m1r - mn1);
        float rs0 = 0.f, rs1 = 0.f;
#pragma unroll
        for (int j = 0; j < 16; j++) {
            float p0 = __expf(-Sa[j][0] - mn0); Sa[j][0] = p0; rs0 += p0;
            float p1 = __expf(-Sa[j][1] - mn0); Sa[j][1] = p1; rs0 += p1;
            float p2 = __expf(-Sa[j][2] - mn1); Sa[j][2] = p2; rs1 += p2;
            float p3 = __expf(-Sa[j][3] - mn1); Sa[j][3] = p3; rs1 += p3;
        }
        rs0 += __shfl_xor_sync(0xffffffffu, rs0, 1);
        rs0 += __shfl_xor_sync(0xffffffffu, rs0, 2);
        rs1 += __shfl_xor_sync(0xffffffffu, rs1, 1);
        rs1 += __shfl_xor_sync(0xffffffffu, rs1, 2);
        l0r = l0r * sc0 + rs0;  l1r = l1r * sc1 + rs1;
        m0r = mn0;  m1r = mn1;
#pragma unroll
        for (int j = 0; j < 16; j++) {
            Oa[j][0] *= sc0; Oa[j][1] *= sc0;
            Oa[j][2] *= sc1; Oa[j][3] *= sc1;
        }

#pragma unroll
        for (int kp = 0; kp < 8; kp++) {
            const float* p0 = Sa[2 * kp];
            const float* p1 = Sa[2 * kp + 1];
            unsigned aPh[4], aPl[4];
            aPh[0] = packbf(p0[0], p0[1]);
            aPh[1] = packbf(p0[2], p0[3]);
            aPh[2] = packbf(p1[0], p1[1]);
            aPh[3] = packbf(p1[2], p1[3]);
            aPl[0] = packlo(p0[0], p0[1], aPh[0]);
            aPl[1] = packlo(p0[2], p0[3], aPh[1]);
            aPl[2] = packlo(p1[0], p1[1], aPh[2]);
            aPl[3] = packlo(p1[2], p1[3], aPh[3]);
#pragma unroll
            for (int fp = 0; fp < 8; fp++) {
                unsigned vh[4], vl[4];
                ldsm4t(vh, bKh + bT + kp * (16 * CST * 2) + fp * 32);
                ldsm4t(vl, bKl + bT + kp * (16 * CST * 2) + fp * 32);
#pragma unroll
                for (int hh = 0; hh < 2; hh++) {
                    float* c = Oa[fp * 2 + hh];
                    mma16816(c, aPh, &vh[2 * hh]);
                    mma16816(c, aPh, &vl[2 * hh]);
                    mma16816(c, aPl, &vh[2 * hh]);
                }
            }
        }
    }

    const float gam = *gptr;
    const float i0 = gam / l0r, i1 = gam / l1r;
    const int r0 = c0 + wid * 16 + g, r1 = r0 + 8;
    float* O = outg + (long)b * CCH * HW;
#pragma unroll
    for (int j = 0; j < 16; j++) {
        const int col = j * 8 + t * 2;
        const long o0 = (long)r0 * HW + col;
        const long o1 = (long)r1 * HW + col;
        float2 y0 = *(const float2*)&Y[o0];
        float2 y1v = *(const float2*)&Y[o1];
        float2 w0, w1;
        w0.x = Oa[j][0] * i0 + y0.x;  w0.y = Oa[j][1] * i0 + y0.y;
        w1.x = Oa[j][2] * i1 + y1v.x; w1.y = Oa[j][3] * i1 + y1v.y;
        *(float2*)&O[o0] = w0;
        *(float2*)&O[o1] = w1;
    }
}

// ------------------------ graph construction -------------------------------
__global__ void graph_build(const float* __restrict__ ip,
                            const float* __restrict__ adj,
                            float* __restrict__ graph)
{
    __shared__ float reda[4], redb[4];
    const int n = blockIdx.y, v = blockIdx.x, w = threadIdx.x;
    const long base = ((long)n * VV + v) * VV;

    const float sqv = ip[((long)n * VV + v) * VV + v];
    const float sqw = ip[((long)n * VV + w) * VV + w];
    const float e   = ip[base + w];

    float d2   = sqv + sqw - 2.f * e;
    float dist = sqrtf(fmaxf(d2, 1e-12f));
    float sim  = 2.f / (expf(dist) + 1.f);
    float av   = adj[base + w];
    if (w == v) { sim = 0.f; av = 0.f; }

    float s1 = warpSum(fabsf(sim));
    float s2 = warpSum(fabsf(av));
    if ((w & 31) == 0) { reda[w >> 5] = s1; redb[w >> 5] = s2; }
    __syncthreads();
    const float ssum = reda[0] + reda[1] + reda[2] + reda[3];
    const float asum = redb[0] + redb[1] + redb[2] + redb[3];

    graph[base + w] = 0.5f * (av / fmaxf(asum, 1e-12f) + sim / fmaxf(ssum, 1e-12f));
}

// ------------------------- batch-norm stats --------------------------------
__global__ void bn_stats(const float* __restrict__ hp,
                         float* __restrict__ mean, float* __restrict__ var,
                         int rows, int C)
{
    __shared__ float shs[8][32];
    __shared__ float shs2[8][32];
    const int lane = threadIdx.x & 31;
    const int ry   = threadIdx.x >> 5;
    const int c    = blockIdx.x * 32 + lane;

    float s = 0.f, s2 = 0.f;
    for (int r = ry; r < rows; r += 8) {
        float v = hp[(long)r * C + c];
        s += v; s2 += v * v;
    }
    shs[ry][lane] = s; shs2[ry][lane] = s2;
    __syncthreads();
    if (ry == 0) {
#pragma unroll
        for (int j = 1; j < 8; j++) { s += shs[j][lane]; s2 += shs2[j][lane]; }
        float mu = s / rows;
        mean[c] = mu;
        var[c]  = s2 / rows - mu * mu;
    }
}

// ------------------- BN apply + LeakyReLU + residual -----------------------
__global__ void bn_apply(const float* __restrict__ inp,
                         const float* __restrict__ hp,
                         const float* __restrict__ mean,
                         const float* __restrict__ var,
                         const float* __restrict__ bw,
                         const float* __restrict__ bb,
                         const float* __restrict__ gptr,
                         float* __restrict__ out, int total, int C)
{
    const int idx = blockIdx.x * blockDim.x + threadIdx.x;
    if (idx >= total) return;
    const int c = idx & (C - 1);
    const float g = *gptr;
    float vv = (hp[idx] - mean[c]) * rsqrtf(var[c] + 1e-5f) * bw[c] + bb[c];
    float lr = vv > 0.f ? vv : 0.1f * vv;
    out[idx] = inp[idx] + g * lr;
}

// ------------------------------ host side ----------------------------------
static void launch_gemm(int TA, int TB,
                        const float* A, const float* B, float* C,
                        int M, int N, int K,
                        long sA, long sB, long sC, int batch,
                        const float* bias,
                        const float* Res, long sRes,
                        float aH, const float* aD, cudaStream_t st)
{
    dim3 grid(N / 128, M / 128, batch);
    dim3 blk(128);
    if (TA == 0 && TB == 0)
        tgemm_kernel<0, 0><<<grid, blk, TSMEM, st>>>(A, B, C, M, N, K, sA, sB, sC, bias, Res, sRes, aH, aD);
    else if (TA == 1 && TB == 0)
        tgemm_kernel<1, 0><<<grid, blk, TSMEM, st>>>(A, B, C, M, N, K, sA, sB, sC, bias, Res, sRes, aH, aD);
    else
        tgemm_kernel<0, 1><<<grid, blk, TSMEM, st>>>(A, B, C, M, N, K, sA, sB, sC, bias, Res, sRes, aH, aD);
}

extern "C" void kernel_launch(void* const* d_in, const int* in_sizes, int n_in,
                              void* d_out, int out_size)
{
    const float* x     = (const float*)d_in[0];
    const float* vfeat = (const float*)d_in[1];
    const float* adj   = (const float*)d_in[2];
    const float* Wq    = (const float*)d_in[3];
    const float* bq    = (const float*)d_in[4];
    const float* Wk    = (const float*)d_in[5];
    const float* bk    = (const float*)d_in[6];
    const float* Wv    = (const float*)d_in[7];
    const float* bv    = (const float*)d_in[8];
    const float* gpam  = (const float*)d_in[9];
    const float* gcam  = (const float*)d_in[10];
    const float* Wg    = (const float*)d_in[11];
    const float* bnw   = (const float*)d_in[12];
    const float* bnb   = (const float*)d_in[13];
    const float* gg    = (const float*)d_in[14];
    float* out = (float*)d_out;

    float *q, *k, *v, *att1, *y1, *h, *ip, *graph, *hp, *gbuf, *mean, *var;
    cudaGetSymbolAddress((void**)&q,    d_q);
    cudaGetSymbolAddress((void**)&k,    d_k);
    cudaGetSymbolAddress((void**)&v,    d_v);
    cudaGetSymbolAddress((void**)&att1, d_att1);
    cudaGetSymbolAddress((void**)&y1,   d_y1);
    cudaGetSymbolAddress((void**)&h,    d_h);
    cudaGetSymbolAddress((void**)&ip,   d_ip);
    cudaGetSymbolAddress((void**)&graph,d_graph);
    cudaGetSymbolAddress((void**)&hp,   d_hp);
    cudaGetSymbolAddress((void**)&gbuf, d_gbuf);
    cudaGetSymbolAddress((void**)&mean, d_mean);
    cudaGetSymbolAddress((void**)&var,  d_var);

    static int inited = 0;
    if (!inited) {
        cudaFuncSetAttribute(tgemm_kernel<0, 0>,
                             cudaFuncAttributeMaxDynamicSharedMemorySize, TSMEM);
        cudaFuncSetAttribute(tgemm_kernel<1, 0>,
                             cudaFuncAttributeMaxDynamicSharedMemorySize, TSMEM);
        cudaFuncSetAttribute(tgemm_kernel<0, 1>,
                             cudaFuncAttributeMaxDynamicSharedMemorySize, TSMEM);
        cudaFuncSetAttribute(cam_tc_kernel,
                             cudaFuncAttributeMaxDynamicSharedMemorySize, CAM_SMEM);
        inited = 1;
    }
    static cudaStream_t s1 = [](){ cudaStream_t s;
        cudaStreamCreateWithFlags(&s, cudaStreamNonBlocking); return s; }();
    static cudaStream_t s2 = [](){ cudaStream_t s;
        cudaStreamCreateWithFlags(&s, cudaStreamNonBlocking); return s; }();
    static cudaEvent_t evF = [](){ cudaEvent_t e;
        cudaEventCreateWithFlags(&e, cudaEventDisableTiming); return e; }();
    static cudaEvent_t evK = [](){ cudaEvent_t e;
        cudaEventCreateWithFlags(&e, cudaEventDisableTiming); return e; }();
    static cudaEvent_t evV = [](){ cudaEvent_t e;
        cudaEventCreateWithFlags(&e, cudaEventDisableTiming); return e; }();
    static cudaEvent_t evJ = [](){ cudaEvent_t e;
        cudaEventCreateWithFlags(&e, cudaEventDisableTiming); return e; }();

    const long CHW = (long)CCH * HW;          // 262144
    const long QHW = (long)C8 * HW;           // 32768
    const long GST = (long)VV * CCH;          // 262144
    cudaStream_t s0 = 0;

    // ---- fork: s1 gets Wk+Wv, s2 gets graph chain ----
    cudaEventRecord(evF, s0);
    cudaStreamWaitEvent(s1, evF, 0);
    cudaStreamWaitEvent(s2, evF, 0);

    // ---------------- PAM ----------------
    launch_gemm(0, 0, Wq, x, q, C8,  HW, CCH, 0, CHW, QHW, BSZ, bq, nullptr, 0, 1.f, nullptr, s0);
    launch_gemm(0, 0, Wk, x, k, C8,  HW, CCH, 0, CHW, QHW, BSZ, bk, nullptr, 0, 1.f, nullptr, s1);
    cudaEventRecord(evK, s1);
    launch_gemm(0, 0, Wv, x, v, CCH, HW, CCH, 0, CHW, CHW, BSZ, bv, nullptr, 0, 1.f, nullptr, s1);
    cudaEventRecord(evV, s1);

    cudaStreamWaitEvent(s0, evK, 0);
    launch_gemm(1, 0, q, k, att1, HW, HW, C8, QHW, QHW, (long)HW * HW, BSZ,
                nullptr, nullptr, 0, 1.f, nullptr, s0);
    softmax_kernel<<<BSZ * HW, 128, 0, s0>>>(att1, HW);
    cudaStreamWaitEvent(s0, evV, 0);
    launch_gemm(0, 1, v, att1, y1, CCH, HW, HW, CHW, (long)HW * HW, CHW, BSZ,
                nullptr, x, CHW, 0.f, gpam, s0);

    // ---------------- CAM (s0, tensor-core flash) ----------------
    {
        dim3 grid(CCH / 128, BSZ);
        cam_tc_kernel<<<grid, 256, CAM_SMEM, s0>>>(y1, gcam, out);
    }

    // ------------- Graph layers (s2) -------------
    const float* inp = vfeat;
    for (int i = 0; i < GNUM; i++) {
        float* outg = (i == GNUM - 1) ? (out + (long)BSZ * CCH * HW) : gbuf;
        launch_gemm(0, 1, inp, Wg + (long)i * CCH * CCH, h,
                    NV * VV, CCH, CCH, 0, 0, 0, 1, nullptr, nullptr, 0, 1.f, nullptr, s2);
        launch_gemm(0, 1, inp, inp, ip, VV, VV, CCH, GST, GST, (long)VV * VV, NV,
                    nullptr, nullptr, 0, 1.f, nullptr, s2);
        graph_build<<<dim3(VV, NV), VV, 0, s2>>>(ip, adj, graph);
        launch_gemm(0, 0, graph, h, hp, VV, CCH, VV, (long)VV * VV, GST, GST, NV,
                    nullptr, nullptr, 0, 1.f, nullptr, s2);
        bn_stats<<<CCH / 32, 256, 0, s2>>>(hp, mean, var, NV * VV, CCH);
        bn_apply<<<(NV * VV * CCH + 255) / 256, 256, 0, s2>>>(
            inp, hp, mean, var, bnw + (long)i * CCH, bnb + (long)i * CCH,
            gg + i, outg, NV * VV * CCH, CCH);
        inp = outg;
    }

    // ---- join ----
    cudaEventRecord(evJ, s2);
    cudaStreamWaitEvent(s0, evJ, 0);
}

// round 10
// speedup vs baseline: 1.2195x; 1.2195x over previous
#include <cuda_runtime.h>
#include <cuda_bf16.h>
#include <math.h>

// ---------------------------------------------------------------------------
// Problem constants
// ---------------------------------------------------------------------------
#define BSZ   16
#define CCH   2048
#define HW    128
#define C8    256
#define NV    16
#define VV    128
#define GNUM  2

// ------------------------- scratch (device globals) ------------------------
__device__ __align__(256) float d_q   [BSZ * C8 * HW];
__device__ __align__(256) float d_k   [BSZ * C8 * HW];
__device__ __align__(256) float d_v   [BSZ * CCH * HW];
__device__ __align__(256) float d_att1[BSZ * HW * HW];
__device__ __align__(256) float d_y1  [BSZ * CCH * HW];
__device__ __align__(256) float d_h   [NV * VV * CCH];
__device__ __align__(256) float d_ip  [NV * VV * VV];
__device__ __align__(256) float d_graph[NV * VV * VV];
__device__ __align__(256) float d_hp  [NV * VV * CCH];
__device__ __align__(256) float d_gbuf[NV * VV * CCH];
__device__ __align__(256) float d_mean[CCH];
__device__ __align__(256) float d_var [CCH];

// ---------------------- shared mma/ldsm/split helpers -----------------------
__device__ __forceinline__ void ldsm4(unsigned* r, unsigned addr) {
    asm volatile("ldmatrix.sync.aligned.m8n8.x4.shared.b16 {%0,%1,%2,%3}, [%4];"
        : "=r"(r[0]), "=r"(r[1]), "=r"(r[2]), "=r"(r[3]) : "r"(addr));
}
__device__ __forceinline__ void ldsm4t(unsigned* r, unsigned addr) {
    asm volatile("ldmatrix.sync.aligned.m8n8.x4.trans.shared.b16 {%0,%1,%2,%3}, [%4];"
        : "=r"(r[0]), "=r"(r[1]), "=r"(r[2]), "=r"(r[3]) : "r"(addr));
}
__device__ __forceinline__ void mma16816(float* c, const unsigned* a, const unsigned* b) {
    asm volatile("mma.sync.aligned.m16n8k16.row.col.f32.bf16.bf16.f32 "
        "{%0,%1,%2,%3}, {%4,%5,%6,%7}, {%8,%9}, {%0,%1,%2,%3};"
        : "+f"(c[0]), "+f"(c[1]), "+f"(c[2]), "+f"(c[3])
        : "r"(a[0]), "r"(a[1]), "r"(a[2]), "r"(a[3]), "r"(b[0]), "r"(b[1]));
}
__device__ __forceinline__ void bsplit(float x, __nv_bfloat16& h, __nv_bfloat16& l) {
    h = __float2bfloat16(x);
    l = __float2bfloat16(x - __bfloat162float(h));
}
__device__ __forceinline__ unsigned packbf(float a, float b) {
    __nv_bfloat162 p; p.x = __float2bfloat16(a); p.y = __float2bfloat16(b);
    return *(unsigned*)&p;
}
__device__ __forceinline__ unsigned packlo(float a, float b, unsigned hipack) {
    __nv_bfloat162 h = *(__nv_bfloat162*)&hipack;
    return packbf(a - __bfloat162float(h.x), b - __bfloat162float(h.y));
}

// ======================= bf16-split tensor-core GEMM ========================
// 256 threads, 8 warps, warp tile 32x64 (R8-proven). Block 128x128, K-step 32,
// double-buffered. acc = AhBh + AhBl + AlBh.
// Direct operands ([m][k]/[n][k]) stored pitch TST=40, loaded with ldsm4.
// Transpose operands stored NATURALLY as [k][m]/[k][n] pitch TS2=136
// (vectorized conflict-free stores), loaded with ldsm4t (CAM-validated duality).
#define TST   40
#define TS2   136
#define TTILE (128 * TST)          // >= 32*TS2 (4352)
#define TSMEM (2 * 4 * TTILE * 2)

template<int TA, int TB>
__global__ __launch_bounds__(256)
void tgemm_kernel(const float* __restrict__ Ag, const float* __restrict__ Bg,
                  float* __restrict__ Cg,
                  int M, int N, int K,
                  long sA, long sB, long sC,
                  const float* __restrict__ bias,
                  const float* __restrict__ Res, long sRes,
                  float alphaH, const float* __restrict__ alphaD)
{
    extern __shared__ __align__(16) __nv_bfloat16 ts[];

    const int bz = blockIdx.z;
    const float* A = Ag + (long)bz * sA;
    const float* B = Bg + (long)bz * sB;
    float*       C = Cg + (long)bz * sC;

    const int m0 = blockIdx.y * 128;
    const int n0 = blockIdx.x * 128;
    const int tid  = threadIdx.x;
    const int wid  = tid >> 5;
    const int lane = tid & 31;
    const int warp_m = (wid >> 1) * 32;
    const int warp_n = (wid & 1) * 64;
    const int mi = lane >> 3, ri = lane & 7;
    const int g  = lane >> 2, t  = lane & 3;

    const unsigned sbase = (unsigned)__cvta_generic_to_shared(ts);

    // fragment offsets: fragment dims keep their mi-bit roles
    //   A: m-group=(mi&1), k-group=(mi>>1);  B: n-group=(mi>>1), k-group=(mi&1)
    unsigned aoff[2], boff[4];
#pragma unroll
    for (int fi = 0; fi < 2; fi++) {
        if (TA == 0)
            aoff[fi] = ((warp_m + fi * 16 + ((mi & 1) << 3) + ri) * TST + ((mi >> 1) << 3)) * 2;
        else
            aoff[fi] = ((((mi >> 1) << 3) + ri) * TS2 + warp_m + fi * 16 + ((mi & 1) << 3)) * 2;
    }
#pragma unroll
    for (int fp = 0; fp < 4; fp++) {
        if (TB == 1)
            boff[fp] = ((warp_n + fp * 16 + ((mi >> 1) << 3) + ri) * TST + ((mi & 1) << 3)) * 2;
        else
            boff[fp] = ((((mi & 1) << 3) + ri) * TS2 + warp_n + fp * 16 + ((mi >> 1) << 3)) * 2;
    }
    const unsigned akk = (TA == 0) ? 32u : (unsigned)(16 * TS2 * 2);
    const unsigned bkk = (TB == 1) ? 32u : (unsigned)(16 * TS2 * 2);

    float acc[2][8][4];
#pragma unroll
    for (int i = 0; i < 2; i++)
#pragma unroll
        for (int j = 0; j < 8; j++)
#pragma unroll
            for (int q = 0; q < 4; q++) acc[i][j][q] = 0.f;

    float4 pa[4], pb[4];
    const int rA = tid >> 1, cA = (tid & 1) * 16;   // direct path indices
    const int kA = tid >> 3, mA = (tid & 7) * 16;   // transpose path indices

#define LOADG(k0)                                                              \
    do {                                                                       \
        if (TA == 0) {                                                         \
            _Pragma("unroll")                                                  \
            for (int j = 0; j < 4; j++)                                        \
                pa[j] = *(const float4*)&A[(long)(m0 + rA) * K + (k0) + cA + 4 * j]; \
        } else {                                                               \
            _Pragma("unroll")                                                  \
            for (int j = 0; j < 4; j++)                                        \
                pa[j] = *(const float4*)&A[(long)((k0) + kA) * M + m0 + mA + 4 * j]; \
        }                                                                      \
        if (TB == 1) {                                                         \
            _Pragma("unroll")                                                  \
            for (int j = 0; j < 4; j++)                                        \
                pb[j] = *(const float4*)&B[(long)(n0 + rA) * K + (k0) + cA + 4 * j]; \
        } else {                                                               \
            _Pragma("unroll")                                                  \
            for (int j = 0; j < 4; j++)                                        \
                pb[j] = *(const float4*)&B[(long)((k0) + kA) * N + n0 + mA + 4 * j]; \
        }                                                                      \
    } while (0)

#define CVSTORE(bf)                                                            \
    do {                                                                       \
        __nv_bfloat16* Ah = ts + ((bf) * 4 + 0) * TTILE;                       \
        __nv_bfloat16* Al = ts + ((bf) * 4 + 1) * TTILE;                       \
        __nv_bfloat16* Bh = ts + ((bf) * 4 + 2) * TTILE;                       \
        __nv_bfloat16* Bl = ts + ((bf) * 4 + 3) * TTILE;                       \
        _Pragma("unroll")                                                      \
        for (int j = 0; j < 4; j++) {                                          \
            float v[4] = { pa[j].x, pa[j].y, pa[j].z, pa[j].w };               \
            __nv_bfloat16 h[4], l[4];                                          \
            _Pragma("unroll")                                                  \
            for (int i = 0; i < 4; i++) bsplit(v[i], h[i], l[i]);              \
            __nv_bfloat162 h01; h01.x = h[0]; h01.y = h[1];                    \
            __nv_bfloat162 h23; h23.x = h[2]; h23.y = h[3];                    \
            __nv_bfloat162 l01; l01.x = l[0]; l01.y = l[1];                    \
            __nv_bfloat162 l23; l23.x = l[2]; l23.y = l[3];                    \
            int base = (TA == 0) ? (rA * TST + cA + 4 * j)                     \
                                 : (kA * TS2 + mA + 4 * j);                    \
            *(__nv_bfloat162*)(Ah + base)     = h01;                           \
            *(__nv_bfloat162*)(Ah + base + 2) = h23;                           \
            *(__nv_bfloat162*)(Al + base)     = l01;                           \
            *(__nv_bfloat162*)(Al + base + 2) = l23;                           \
        }                                                                      \
        _Pragma("unroll")                                                      \
        for (int j = 0; j < 4; j++) {                                          \
            float v[4] = { pb[j].x, pb[j].y, pb[j].z, pb[j].w };               \
            __nv_bfloat16 h[4], l[4];                                          \
            _Pragma("unroll")                                                  \
            for (int i = 0; i < 4; i++) bsplit(v[i], h[i], l[i]);              \
            __nv_bfloat162 h01; h01.x = h[0]; h01.y = h[1];                    \
            __nv_bfloat162 h23; h23.x = h[2]; h23.y = h[3];                    \
            __nv_bfloat162 l01; l01.x = l[0]; l01.y = l[1];                    \
            __nv_bfloat162 l23; l23.x = l[2]; l23.y = l[3];                    \
            int base = (TB == 1) ? (rA * TST + cA + 4 * j)                     \
                                 : (kA * TS2 + mA + 4 * j);                    \
            *(__nv_bfloat162*)(Bh + base)     = h01;                           \
            *(__nv_bfloat162*)(Bh + base + 2) = h23;                           \
            *(__nv_bfloat162*)(Bl + base)     = l01;                           \
            *(__nv_bfloat162*)(Bl + base + 2) = l23;                           \
        }                                                                      \
    } while (0)

#define MMASTEP(bf)                                                            \
    do {                                                                       \
        const unsigned bAh = sbase + ((bf) * 4 + 0) * TTILE * 2;               \
        const unsigned bAl = sbase + ((bf) * 4 + 1) * TTILE * 2;               \
        const unsigned bBh = sbase + ((bf) * 4 + 2) * TTILE * 2;               \
        const unsigned bBl = sbase + ((bf) * 4 + 3) * TTILE * 2;               \
        _Pragma("unroll")                                                      \
        for (int kk = 0; kk < 2; kk++) {                                       \
            unsigned ah[2][4], al[2][4], bh[4][4], bl[4][4];                   \
            _Pragma("unroll")                                                  \
            for (int fi = 0; fi < 2; fi++) {                                   \
                if (TA == 0) {                                                 \
                    ldsm4(ah[fi], bAh + aoff[fi] + kk * akk);                  \
                    ldsm4(al[fi], bAl + aoff[fi] + kk * akk);                  \
                } else {                                                       \
                    ldsm4t(ah[fi], bAh + aoff[fi] + kk * akk);                 \
                    ldsm4t(al[fi], bAl + aoff[fi] + kk * akk);                 \
                }                                                              \
            }                                                                  \
            _Pragma("unroll")                                                  \
            for (int fp = 0; fp < 4; fp++) {                                   \
                if (TB == 1) {                                                 \
                    ldsm4(bh[fp], bBh + boff[fp] + kk * bkk);                  \
                    ldsm4(bl[fp], bBl + boff[fp] + kk * bkk);                  \
                } else {                                                       \
                    ldsm4t(bh[fp], bBh + boff[fp] + kk * bkk);                 \
                    ldsm4t(bl[fp], bBl + boff[fp] + kk * bkk);                 \
                }                                                              \
            }                                                                  \
            _Pragma("unroll")                                                  \
            for (int fi = 0; fi < 2; fi++)                                     \
                _Pragma("unroll")                                              \
                for (int fp = 0; fp < 4; fp++)                                 \
                    _Pragma("unroll")                                          \
                    for (int hh = 0; hh < 2; hh++) {                           \
                        float* c = acc[fi][fp * 2 + hh];                       \
                        mma16816(c, ah[fi], &bh[fp][2 * hh]);                  \
                        mma16816(c, ah[fi], &bl[fp][2 * hh]);                  \
                        mma16816(c, al[fi], &bh[fp][2 * hh]);                  \
                    }                                                          \
        }                                                                      \
    } while (0)

    LOADG(0);
    CVSTORE(0);
    __syncthreads();

    const int nt = K / 32;
    for (int tI = 0; tI < nt; tI++) {
        if (tI + 1 < nt) LOADG((tI + 1) * 32);
        MMASTEP(tI & 1);
        if (tI + 1 < nt) {
            CVSTORE((tI + 1) & 1);
            __syncthreads();
        }
    }

    const float alpha = alphaD ? *alphaD : alphaH;
#pragma unroll
    for (int fi = 0; fi < 2; fi++) {
        const int m = m0 + warp_m + fi * 16 + g;
        const float bi0 = bias ? __ldg(&bias[m])     : 0.f;
        const float bi1 = bias ? __ldg(&bias[m + 8]) : 0.f;
#pragma unroll
        for (int fj = 0; fj < 8; fj++) {
            const int n = n0 + warp_n + fj * 8 + t * 2;
            const float* c = acc[fi][fj];
            const long off0 = (long)m * N + n;
            const long off1 = (long)(m + 8) * N + n;
            float2 o0, o1;
            o0.x = alpha * c[0] + bi0; o0.y = alpha * c[1] + bi0;
            o1.x = alpha * c[2] + bi1; o1.y = alpha * c[3] + bi1;
            if (Res) {
                float2 r0 = *(const float2*)&Res[(long)bz * sRes + off0];
                float2 r1 = *(const float2*)&Res[(long)bz * sRes + off1];
                o0.x += r0.x; o0.y += r0.y;
                o1.x += r1.x; o1.y += r1.y;
            }
            *(float2*)&C[off0] = o0;
            *(float2*)&C[off1] = o1;
        }
    }
#undef LOADG
#undef CVSTORE
#undef MMASTEP
}

// --------------------------- reductions ------------------------------------
__device__ __forceinline__ float warpMax(float v) {
#pragma unroll
    for (int o = 16; o; o >>= 1) v = fmaxf(v, __shfl_xor_sync(0xffffffffu, v, o));
    return v;
}
__device__ __forceinline__ float warpSum(float v) {
#pragma unroll
    for (int o = 16; o; o >>= 1) v += __shfl_xor_sync(0xffffffffu, v, o);
    return v;
}

// in-place row softmax; one block per row
__global__ void softmax_kernel(float* __restrict__ d, int ncols)
{
    __shared__ float red[32];
    __shared__ float bcast;
    const long row = blockIdx.x;
    float* p = d + row * (long)ncols;
    const int tid = threadIdx.x, nt = blockDim.x;

    float m = -1e30f;
    for (int i = tid; i < ncols; i += nt) m = fmaxf(m, p[i]);
    m = warpMax(m);
    if ((tid & 31) == 0) red[tid >> 5] = m;
    __syncthreads();
    if (tid < 32) {
        float v = (tid < (nt >> 5)) ? red[tid] : -1e30f;
        v = warpMax(v);
        if (tid == 0) bcast = v;
    }
    __syncthreads();
    m = bcast;

    float s = 0.f;
    for (int i = tid; i < ncols; i += nt) {
        float e = __expf(p[i] - m);
        p[i] = e;
        s += e;
    }
    __syncthreads();
    s = warpSum(s);
    if ((tid & 31) == 0) red[tid >> 5] = s;
    __syncthreads();
    if (tid < 32) {
        float v = (tid < (nt >> 5)) ? red[tid] : 0.f;
        v = warpSum(v);
        if (tid == 0) bcast = v;
    }
    __syncthreads();
    const float inv = 1.f / bcast;
    for (int i = tid; i < ncols; i += nt) p[i] *= inv;
}

// ================= tensor-core fused CAM (flash style) ======================
#define CST   136
#define CTILE (128 * CST)
#define CAM_SMEM (4 * CTILE * 2)

__global__ __launch_bounds__(256)
void cam_tc_kernel(const float* __restrict__ y1g,
                   const float* __restrict__ gptr,
                   float* __restrict__ outg)
{
    extern __shared__ __align__(16) __nv_bfloat16 cs[];
    __nv_bfloat16* Qh = cs;
    __nv_bfloat16* Ql = cs + CTILE;
    __nv_bfloat16* Kh = cs + 2 * CTILE;
    __nv_bfloat16* Kl = cs + 3 * CTILE;

    const int b  = blockIdx.y;
    const int c0 = blockIdx.x * 128;
    const float* Y = y1g + (long)b * CCH * HW;

    const int tid = threadIdx.x, wid = tid >> 5, lane = tid & 31;
    const int mi = lane >> 3, ri = lane & 7, g = lane >> 2, t = lane & 3;

    const unsigned sb  = (unsigned)__cvta_generic_to_shared(cs);
    const unsigned bQh = sb;
    const unsigned bQl = sb + CTILE * 2;
    const unsigned bKh = sb + 2 * CTILE * 2;
    const unsigned bKl = sb + 3 * CTILE * 2;

    const unsigned aoff = ((wid * 16 + ((mi & 1) << 3) + ri) * CST + ((mi >> 1) << 3)) * 2;
    const unsigned bS = ((((mi >> 1) << 3) + ri) * CST + ((mi & 1) << 3)) * 2;
    const unsigned bT = ((((mi & 1) << 3) + ri) * CST + ((mi >> 1) << 3)) * 2;

    for (int idx = tid; idx < 128 * 32; idx += 256) {
        int r = idx >> 5, hw = (idx & 31) * 4;
        float4 v = *(const float4*)&Y[(long)(c0 + r) * HW + hw];
        __nv_bfloat16 h0,l0,h1,l1,h2,l2,h3,l3;
        bsplit(v.x,h0,l0); bsplit(v.y,h1,l1); bsplit(v.z,h2,l2); bsplit(v.w,h3,l3);
        __nv_bfloat162 a; __nv_bfloat162 c;
        __nv_bfloat162* ph = (__nv_bfloat162*)(Qh + r * CST + hw);
        __nv_bfloat162* pl = (__nv_bfloat162*)(Ql + r * CST + hw);
        a.x = h0; a.y = h1; ph[0] = a;  a.x = h2; a.y = h3; ph[1] = a;
        c.x = l0; c.y = l1; pl[0] = c;  c.x = l2; c.y = l3; pl[1] = c;
    }

    float Sa[16][4], Oa[16][4];
    float m0r = -1e30f, m1r = -1e30f, l0r = 0.f, l1r = 0.f;
#pragma unroll
    for (int j = 0; j < 16; j++) { Oa[j][0]=Oa[j][1]=Oa[j][2]=Oa[j][3]=0.f; }

    for (int tI = 0; tI < 16; tI++) {
        __syncthreads();
        for (int idx = tid; idx < 128 * 32; idx += 256) {
            int d = idx >> 5, hw = (idx & 31) * 4;
            float4 v = *(const float4*)&Y[(long)(tI * 128 + d) * HW + hw];
            __nv_bfloat16 h0,l0,h1,l1,h2,l2,h3,l3;
            bsplit(v.x,h0,l0); bsplit(v.y,h1,l1); bsplit(v.z,h2,l2); bsplit(v.w,h3,l3);
            __nv_bfloat162 a; __nv_bfloat162 c;
            __nv_bfloat162* ph = (__nv_bfloat162*)(Kh + d * CST + hw);
            __nv_bfloat162* pl = (__nv_bfloat162*)(Kl + d * CST + hw);
            a.x = h0; a.y = h1; ph[0] = a;  a.x = h2; a.y = h3; ph[1] = a;
            c.x = l0; c.y = l1; pl[0] = c;  c.x = l2; c.y = l3; pl[1] = c;
        }
        __syncthreads();

#pragma unroll
        for (int j = 0; j < 16; j++) { Sa[j][0]=Sa[j][1]=Sa[j][2]=Sa[j][3]=0.f; }
#pragma unroll
        for (int ks = 0; ks < 8; ks++) {
            unsigned ah[4], al[4];
            ldsm4(ah, bQh + aoff + ks * 32);
            ldsm4(al, bQl + aoff + ks * 32);
#pragma unroll
            for (int fp = 0; fp < 8; fp++) {
                unsigned bh[4], bl[4];
                ldsm4(bh, bKh + bS + fp * (16 * CST * 2) + ks * 32);
                ldsm4(bl, bKl + bS + fp * (16 * CST * 2) + ks * 32);
#pragma unroll
                for (int hh = 0; hh < 2; hh++) {
                    float* c = Sa[fp * 2 + hh];
                    mma16816(c, ah, &bh[2 * hh]);
                    mma16816(c, ah, &bl[2 * hh]);
                    mma16816(c, al, &bh[2 * hh]);
                }
            }
        }

        float mx0 = -1e30f, mx1 = -1e30f;
#pragma unroll
        for (int j = 0; j < 16; j++) {
            mx0 = fmaxf(mx0, fmaxf(-Sa[j][0], -Sa[j][1]));
            mx1 = fmaxf(mx1, fmaxf(-Sa[j][2], -Sa[j][3]));
        }
        mx0 = fmaxf(mx0, __shfl_xor_sync(0xffffffffu, mx0, 1));
        mx0 = fmaxf(mx0, __shfl_xor_sync(0xffffffffu, mx0, 2));
        mx1 = fmaxf(mx1, __shfl_xor_sync(0xffffffffu, mx1, 1));
        mx1 = fmaxf(mx1, __shfl_xor_sync(0xffffffffu, mx1, 2));
        const float mn0 = fmaxf(m0r, mx0), mn1 = fmaxf(m1r, mx1);
        const float sc0 = __expf(m0r - mn0), sc1 = __expf(m1r - mn1);
        float rs0 = 0.f, rs1 = 0.f;
#pragma unroll
        for (int j = 0; j < 16; j++) {
            float p0 = __expf(-Sa[j][0] - mn0); Sa[j][0] = p0; rs0 += p0;
            float p1 = __expf(-Sa[j][1] - mn0); Sa[j][1] = p1; rs0 += p1;
            float p2 = __expf(-Sa[j][2] - mn1); Sa[j][2] = p2; rs1 += p2;
            float p3 = __expf(-Sa[j][3] - mn1); Sa[j][3] = p3; rs1 += p3;
        }
        rs0 += __shfl_xor_sync(0xffffffffu, rs0, 1);
        rs0 += __shfl_xor_sync(0xffffffffu, rs0, 2);
        rs1 += __shfl_xor_sync(0xffffffffu, rs1, 1);
        rs1 += __shfl_xor_sync(0xffffffffu, rs1, 2);
        l0r = l0r * sc0 + rs0;  l1r = l1r * sc1 + rs1;
        m0r = mn0;  m1r = mn1;
#pragma unroll
        for (int j = 0; j < 16; j++) {
            Oa[j][0] *= sc0; Oa[j][1] *= sc0;
            Oa[j][2] *= sc1; Oa[j][3] *= sc1;
        }

#pragma unroll
        for (int kp = 0; kp < 8; kp++) {
            const float* p0 = Sa[2 * kp];
            const float* p1 = Sa[2 * kp + 1];
            unsigned aPh[4], aPl[4];
            aPh[0] = packbf(p0[0], p0[1]);
            aPh[1] = packbf(p0[2], p0[3]);
            aPh[2] = packbf(p1[0], p1[1]);
            aPh[3] = packbf(p1[2], p1[3]);
            aPl[0] = packlo(p0[0], p0[1], aPh[0]);
            aPl[1] = packlo(p0[2], p0[3], aPh[1]);
            aPl[2] = packlo(p1[0], p1[1], aPh[2]);
            aPl[3] = packlo(p1[2], p1[3], aPh[3]);
#pragma unroll
            for (int fp = 0; fp < 8; fp++) {
                unsigned vh[4], vl[4];
                ldsm4t(vh, bKh + bT + kp * (16 * CST * 2) + fp * 32);
                ldsm4t(vl, bKl + bT + kp * (16 * CST * 2) + fp * 32);
#pragma unroll
                for (int hh = 0; hh < 2; hh++) {
                    float* c = Oa[fp * 2 + hh];
                    mma16816(c, aPh, &vh[2 * hh]);
                    mma16816(c, aPh, &vl[2 * hh]);
                    mma16816(c, aPl, &vh[2 * hh]);
                }
            }
        }
    }

    const float gam = *gptr;
    const float i0 = gam / l0r, i1 = gam / l1r;
    const int r0 = c0 + wid * 16 + g, r1 = r0 + 8;
    float* O = outg + (long)b * CCH * HW;
#pragma unroll
    for (int j = 0; j < 16; j++) {
        const int col = j * 8 + t * 2;
        const long o0 = (long)r0 * HW + col;
        const long o1 = (long)r1 * HW + col;
        float2 y0 = *(const float2*)&Y[o0];
        float2 y1v = *(const float2*)&Y[o1];
        float2 w0, w1;
        w0.x = Oa[j][0] * i0 + y0.x;  w0.y = Oa[j][1] * i0 + y0.y;
        w1.x = Oa[j][2] * i1 + y1v.x; w1.y = Oa[j][3] * i1 + y1v.y;
        *(float2*)&O[o0] = w0;
        *(float2*)&O[o1] = w1;
    }
}

// ------------------------ graph construction -------------------------------
__global__ void graph_build(const float* __restrict__ ip,
                            const float* __restrict__ adj,
                            float* __restrict__ graph)
{
    __shared__ float reda[4], redb[4];
    const int n = blockIdx.y, v = blockIdx.x, w = threadIdx.x;
    const long base = ((long)n * VV + v) * VV;

    const float sqv = ip[((long)n * VV + v) * VV + v];
    const float sqw = ip[((long)n * VV + w) * VV + w];
    const float e   = ip[base + w];

    float d2   = sqv + sqw - 2.f * e;
    float dist = sqrtf(fmaxf(d2, 1e-12f));
    float sim  = 2.f / (expf(dist) + 1.f);
    float av   = adj[base + w];
    if (w == v) { sim = 0.f; av = 0.f; }

    float s1 = warpSum(fabsf(sim));
    float s2 = warpSum(fabsf(av));
    if ((w & 31) == 0) { reda[w >> 5] = s1; redb[w >> 5] = s2; }
    __syncthreads();
    const float ssum = reda[0] + reda[1] + reda[2] + reda[3];
    const float asum = redb[0] + redb[1] + redb[2] + redb[3];

    graph[base + w] = 0.5f * (av / fmaxf(asum, 1e-12f) + sim / fmaxf(ssum, 1e-12f));
}

// ------------------------- batch-norm stats --------------------------------
__global__ void bn_stats(const float* __restrict__ hp,
                         float* __restrict__ mean, float* __restrict__ var,
                         int rows, int C)
{
    __shared__ float shs[8][32];
    __shared__ float shs2[8][32];
    const int lane = threadIdx.x & 31;
    const int ry   = threadIdx.x >> 5;
    const int c    = blockIdx.x * 32 + lane;

    float s = 0.f, s2 = 0.f;
    for (int r = ry; r < rows; r += 8) {
        float v = hp[(long)r * C + c];
        s += v; s2 += v * v;
    }
    shs[ry][lane] = s; shs2[ry][lane] = s2;
    __syncthreads();
    if (ry == 0) {
#pragma unroll
        for (int j = 1; j < 8; j++) { s += shs[j][lane]; s2 += shs2[j][lane]; }
        float mu = s / rows;
        mean[c] = mu;
        var[c]  = s2 / rows - mu * mu;
    }
}

// ------------------- BN apply + LeakyReLU + residual -----------------------
__global__ void bn_apply(const float* __restrict__ inp,
                         const float* __restrict__ hp,
                         const float* __restrict__ mean,
                         const float* __restrict__ var,
                         const float* __restrict__ bw,
                         const float* __restrict__ bb,
                         const float* __restrict__ gptr,
                         float* __restrict__ out, int total, int C)
{
    const int idx = blockIdx.x * blockDim.x + threadIdx.x;
    if (idx >= total) return;
    const int c = idx & (C - 1);
    const float g = *gptr;
    float vv = (hp[idx] - mean[c]) * rsqrtf(var[c] + 1e-5f) * bw[c] + bb[c];
    float lr = vv > 0.f ? vv : 0.1f * vv;
    out[idx] = inp[idx] + g * lr;
}

// ------------------------------ host side ----------------------------------
static void launch_gemm(int TA, int TB,
                        const float* A, const float* B, float* C,
                        int M, int N, int K,
                        long sA, long sB, long sC, int batch,
                        const float* bias,
                        const float* Res, long sRes,
                        float aH, const float* aD, cudaStream_t st)
{
    dim3 grid(N / 128, M / 128, batch);
    dim3 blk(256);
    if (TA == 0 && TB == 0)
        tgemm_kernel<0, 0><<<grid, blk, TSMEM, st>>>(A, B, C, M, N, K, sA, sB, sC, bias, Res, sRes, aH, aD);
    else if (TA == 1 && TB == 0)
        tgemm_kernel<1, 0><<<grid, blk, TSMEM, st>>>(A, B, C, M, N, K, sA, sB, sC, bias, Res, sRes, aH, aD);
    else
        tgemm_kernel<0, 1><<<grid, blk, TSMEM, st>>>(A, B, C, M, N, K, sA, sB, sC, bias, Res, sRes, aH, aD);
}

extern "C" void kernel_launch(void* const* d_in, const int* in_sizes, int n_in,
                              void* d_out, int out_size)
{
    const float* x     = (const float*)d_in[0];
    const float* vfeat = (const float*)d_in[1];
    const float* adj   = (const float*)d_in[2];
    const float* Wq    = (const float*)d_in[3];
    const float* bq    = (const float*)d_in[4];
    const float* Wk    = (const float*)d_in[5];
    const float* bk    = (const float*)d_in[6];
    const float* Wv    = (const float*)d_in[7];
    const float* bv    = (const float*)d_in[8];
    const float* gpam  = (const float*)d_in[9];
    const float* gcam  = (const float*)d_in[10];
    const float* Wg    = (const float*)d_in[11];
    const float* bnw   = (const float*)d_in[12];
    const float* bnb   = (const float*)d_in[13];
    const float* gg    = (const float*)d_in[14];
    float* out = (float*)d_out;

    float *q, *k, *v, *att1, *y1, *h, *ip, *graph, *hp, *gbuf, *mean, *var;
    cudaGetSymbolAddress((void**)&q,    d_q);
    cudaGetSymbolAddress((void**)&k,    d_k);
    cudaGetSymbolAddress((void**)&v,    d_v);
    cudaGetSymbolAddress((void**)&att1, d_att1);
    cudaGetSymbolAddress((void**)&y1,   d_y1);
    cudaGetSymbolAddress((void**)&h,    d_h);
    cudaGetSymbolAddress((void**)&ip,   d_ip);
    cudaGetSymbolAddress((void**)&graph,d_graph);
    cudaGetSymbolAddress((void**)&hp,   d_hp);
    cudaGetSymbolAddress((void**)&gbuf, d_gbuf);
    cudaGetSymbolAddress((void**)&mean, d_mean);
    cudaGetSymbolAddress((void**)&var,  d_var);

    static int inited = 0;
    if (!inited) {
        cudaFuncSetAttribute(tgemm_kernel<0, 0>,
                             cudaFuncAttributeMaxDynamicSharedMemorySize, TSMEM);
        cudaFuncSetAttribute(tgemm_kernel<1, 0>,
                             cudaFuncAttributeMaxDynamicSharedMemorySize, TSMEM);
        cudaFuncSetAttribute(tgemm_kernel<0, 1>,
                             cudaFuncAttributeMaxDynamicSharedMemorySize, TSMEM);
        cudaFuncSetAttribute(cam_tc_kernel,
                             cudaFuncAttributeMaxDynamicSharedMemorySize, CAM_SMEM);
        inited = 1;
    }
    static cudaStream_t s1 = [](){ cudaStream_t s;
        cudaStreamCreateWithFlags(&s, cudaStreamNonBlocking); return s; }();
    static cudaStream_t s2 = [](){ cudaStream_t s;
        cudaStreamCreateWithFlags(&s, cudaStreamNonBlocking); return s; }();
    static cudaEvent_t evF = [](){ cudaEvent_t e;
        cudaEventCreateWithFlags(&e, cudaEventDisableTiming); return e; }();
    static cudaEvent_t evK = [](){ cudaEvent_t e;
        cudaEventCreateWithFlags(&e, cudaEventDisableTiming); return e; }();
    static cudaEvent_t evV = [](){ cudaEvent_t e;
        cudaEventCreateWithFlags(&e, cudaEventDisableTiming); return e; }();
    static cudaEvent_t evJ = [](){ cudaEvent_t e;
        cudaEventCreateWithFlags(&e, cudaEventDisableTiming); return e; }();

    const long CHW = (long)CCH * HW;          // 262144
    const long QHW = (long)C8 * HW;           // 32768
    const long GST = (long)VV * CCH;          // 262144
    cudaStream_t s0 = 0;

    // ---- fork: s1 gets Wk+Wv, s2 gets graph chain ----
    cudaEventRecord(evF, s0);
    cudaStreamWaitEvent(s1, evF, 0);
    cudaStreamWaitEvent(s2, evF, 0);

    // ---------------- PAM ----------------
    launch_gemm(0, 0, Wq, x, q, C8,  HW, CCH, 0, CHW, QHW, BSZ, bq, nullptr, 0, 1.f, nullptr, s0);
    launch_gemm(0, 0, Wk, x, k, C8,  HW, CCH, 0, CHW, QHW, BSZ, bk, nullptr, 0, 1.f, nullptr, s1);
    cudaEventRecord(evK, s1);
    launch_gemm(0, 0, Wv, x, v, CCH, HW, CCH, 0, CHW, CHW, BSZ, bv, nullptr, 0, 1.f, nullptr, s1);
    cudaEventRecord(evV, s1);

    cudaStreamWaitEvent(s0, evK, 0);
    launch_gemm(1, 0, q, k, att1, HW, HW, C8, QHW, QHW, (long)HW * HW, BSZ,
                nullptr, nullptr, 0, 1.f, nullptr, s0);
    softmax_kernel<<<BSZ * HW, 128, 0, s0>>>(att1, HW);
    cudaStreamWaitEvent(s0, evV, 0);
    launch_gemm(0, 1, v, att1, y1, CCH, HW, HW, CHW, (long)HW * HW, CHW, BSZ,
                nullptr, x, CHW, 0.f, gpam, s0);

    // ---------------- CAM (s0, tensor-core flash) ----------------
    {
        dim3 grid(CCH / 128, BSZ);
        cam_tc_kernel<<<grid, 256, CAM_SMEM, s0>>>(y1, gcam, out);
    }

    // ------------- Graph layers (s2) -------------
    const float* inp = vfeat;
    for (int i = 0; i < GNUM; i++) {
        float* outg = (i == GNUM - 1) ? (out + (long)BSZ * CCH * HW) : gbuf;
        launch_gemm(0, 1, inp, Wg + (long)i * CCH * CCH, h,
                    NV * VV, CCH, CCH, 0, 0, 0, 1, nullptr, nullptr, 0, 1.f, nullptr, s2);
        launch_gemm(0, 1, inp, inp, ip, VV, VV, CCH, GST, GST, (long)VV * VV, NV,
                    nullptr, nullptr, 0, 1.f, nullptr, s2);
        graph_build<<<dim3(VV, NV), VV, 0, s2>>>(ip, adj, graph);
        launch_gemm(0, 0, graph, h, hp, VV, CCH, VV, (long)VV * VV, GST, GST, NV,
                    nullptr, nullptr, 0, 1.f, nullptr, s2);
        bn_stats<<<CCH / 32, 256, 0, s2>>>(hp, mean, var, NV * VV, CCH);
        bn_apply<<<(NV * VV * CCH + 255) / 256, 256, 0, s2>>>(
            inp, hp, mean, var, bnw + (long)i * CCH, bnb + (long)i * CCH,
            gg + i, outg, NV * VV * CCH, CCH);
        inp = outg;
    }

    // ---- join ----
    cudaEventRecord(evJ, s2);
    cudaStreamWaitEvent(s0, evJ, 0);
}

// round 11
// speedup vs baseline: 1.2482x; 1.0236x over previous
#include <cuda_runtime.h>
#include <cuda_bf16.h>
#include <math.h>

// ---------------------------------------------------------------------------
// Problem constants
// ---------------------------------------------------------------------------
#define BSZ   16
#define CCH   2048
#define HW    128
#define C8    256
#define NV    16
#define VV    128
#define GNUM  2

// ------------------------- scratch (device globals) ------------------------
__device__ __align__(256) float d_q   [BSZ * C8 * HW];
__device__ __align__(256) float d_k   [BSZ * C8 * HW];
__device__ __align__(256) float d_v   [BSZ * CCH * HW];
__device__ __align__(256) float d_att1[BSZ * HW * HW];
__device__ __align__(256) float d_y1  [BSZ * CCH * HW];
__device__ __align__(256) __nv_bfloat16 d_y1h[BSZ * CCH * HW];
__device__ __align__(256) __nv_bfloat16 d_y1l[BSZ * CCH * HW];
__device__ __align__(256) float d_h   [NV * VV * CCH];
__device__ __align__(256) float d_ip  [NV * VV * VV];
__device__ __align__(256) float d_graph[NV * VV * VV];
__device__ __align__(256) float d_hp  [NV * VV * CCH];
__device__ __align__(256) float d_gbuf[NV * VV * CCH];
__device__ __align__(256) float d_mean[CCH];
__device__ __align__(256) float d_var [CCH];

// ---------------------- shared mma/ldsm/split helpers -----------------------
__device__ __forceinline__ void ldsm4(unsigned* r, unsigned addr) {
    asm volatile("ldmatrix.sync.aligned.m8n8.x4.shared.b16 {%0,%1,%2,%3}, [%4];"
        : "=r"(r[0]), "=r"(r[1]), "=r"(r[2]), "=r"(r[3]) : "r"(addr));
}
__device__ __forceinline__ void ldsm4t(unsigned* r, unsigned addr) {
    asm volatile("ldmatrix.sync.aligned.m8n8.x4.trans.shared.b16 {%0,%1,%2,%3}, [%4];"
        : "=r"(r[0]), "=r"(r[1]), "=r"(r[2]), "=r"(r[3]) : "r"(addr));
}
__device__ __forceinline__ void mma16816(float* c, const unsigned* a, const unsigned* b) {
    asm volatile("mma.sync.aligned.m16n8k16.row.col.f32.bf16.bf16.f32 "
        "{%0,%1,%2,%3}, {%4,%5,%6,%7}, {%8,%9}, {%0,%1,%2,%3};"
        : "+f"(c[0]), "+f"(c[1]), "+f"(c[2]), "+f"(c[3])
        : "r"(a[0]), "r"(a[1]), "r"(a[2]), "r"(a[3]), "r"(b[0]), "r"(b[1]));
}
__device__ __forceinline__ void bsplit(float x, __nv_bfloat16& h, __nv_bfloat16& l) {
    h = __float2bfloat16(x);
    l = __float2bfloat16(x - __bfloat162float(h));
}
__device__ __forceinline__ unsigned packbf(float a, float b) {
    __nv_bfloat162 p; p.x = __float2bfloat16(a); p.y = __float2bfloat16(b);
    return *(unsigned*)&p;
}
__device__ __forceinline__ unsigned packlo(float a, float b, unsigned hipack) {
    __nv_bfloat162 h = *(__nv_bfloat162*)&hipack;
    return packbf(a - __bfloat162float(h.x), b - __bfloat162float(h.y));
}
__device__ __forceinline__ void cpa16(unsigned s, const void* g) {
    asm volatile("cp.async.ca.shared.global [%0], [%1], 16;" :: "r"(s), "l"(g));
}

// ======================= bf16-split tensor-core GEMM ========================
// (R10 winner, unchanged) 256 threads, 8 warps, warp tile 32x64.
#define TST   40
#define TS2   136
#define TTILE (128 * TST)
#define TSMEM (2 * 4 * TTILE * 2)

template<int TA, int TB>
__global__ __launch_bounds__(256)
void tgemm_kernel(const float* __restrict__ Ag, const float* __restrict__ Bg,
                  float* __restrict__ Cg,
                  int M, int N, int K,
                  long sA, long sB, long sC,
                  const float* __restrict__ bias,
                  const float* __restrict__ Res, long sRes,
                  float alphaH, const float* __restrict__ alphaD)
{
    extern __shared__ __align__(16) __nv_bfloat16 ts[];

    const int bz = blockIdx.z;
    const float* A = Ag + (long)bz * sA;
    const float* B = Bg + (long)bz * sB;
    float*       C = Cg + (long)bz * sC;

    const int m0 = blockIdx.y * 128;
    const int n0 = blockIdx.x * 128;
    const int tid  = threadIdx.x;
    const int wid  = tid >> 5;
    const int lane = tid & 31;
    const int warp_m = (wid >> 1) * 32;
    const int warp_n = (wid & 1) * 64;
    const int mi = lane >> 3, ri = lane & 7;
    const int g  = lane >> 2, t  = lane & 3;

    const unsigned sbase = (unsigned)__cvta_generic_to_shared(ts);

    unsigned aoff[2], boff[4];
#pragma unroll
    for (int fi = 0; fi < 2; fi++) {
        if (TA == 0)
            aoff[fi] = ((warp_m + fi * 16 + ((mi & 1) << 3) + ri) * TST + ((mi >> 1) << 3)) * 2;
        else
            aoff[fi] = ((((mi >> 1) << 3) + ri) * TS2 + warp_m + fi * 16 + ((mi & 1) << 3)) * 2;
    }
#pragma unroll
    for (int fp = 0; fp < 4; fp++) {
        if (TB == 1)
            boff[fp] = ((warp_n + fp * 16 + ((mi >> 1) << 3) + ri) * TST + ((mi & 1) << 3)) * 2;
        else
            boff[fp] = ((((mi & 1) << 3) + ri) * TS2 + warp_n + fp * 16 + ((mi >> 1) << 3)) * 2;
    }
    const unsigned akk = (TA == 0) ? 32u : (unsigned)(16 * TS2 * 2);
    const unsigned bkk = (TB == 1) ? 32u : (unsigned)(16 * TS2 * 2);

    float acc[2][8][4];
#pragma unroll
    for (int i = 0; i < 2; i++)
#pragma unroll
        for (int j = 0; j < 8; j++)
#pragma unroll
            for (int q = 0; q < 4; q++) acc[i][j][q] = 0.f;

    float4 pa[4], pb[4];
    const int rA = tid >> 1, cA = (tid & 1) * 16;
    const int kA = tid >> 3, mA = (tid & 7) * 16;

#define LOADG(k0)                                                              \
    do {                                                                       \
        if (TA == 0) {                                                         \
            _Pragma("unroll")                                                  \
            for (int j = 0; j < 4; j++)                                        \
                pa[j] = *(const float4*)&A[(long)(m0 + rA) * K + (k0) + cA + 4 * j]; \
        } else {                                                               \
            _Pragma("unroll")                                                  \
            for (int j = 0; j < 4; j++)                                        \
                pa[j] = *(const float4*)&A[(long)((k0) + kA) * M + m0 + mA + 4 * j]; \
        }                                                                      \
        if (TB == 1) {                                                         \
            _Pragma("unroll")                                                  \
            for (int j = 0; j < 4; j++)                                        \
                pb[j] = *(const float4*)&B[(long)(n0 + rA) * K + (k0) + cA + 4 * j]; \
        } else {                                                               \
            _Pragma("unroll")                                                  \
            for (int j = 0; j < 4; j++)                                        \
                pb[j] = *(const float4*)&B[(long)((k0) + kA) * N + n0 + mA + 4 * j]; \
        }                                                                      \
    } while (0)

#define CVSTORE(bf)                                                            \
    do {                                                                       \
        __nv_bfloat16* Ah = ts + ((bf) * 4 + 0) * TTILE;                       \
        __nv_bfloat16* Al = ts + ((bf) * 4 + 1) * TTILE;                       \
        __nv_bfloat16* Bh = ts + ((bf) * 4 + 2) * TTILE;                       \
        __nv_bfloat16* Bl = ts + ((bf) * 4 + 3) * TTILE;                       \
        _Pragma("unroll")                                                      \
        for (int j = 0; j < 4; j++) {                                          \
            float v[4] = { pa[j].x, pa[j].y, pa[j].z, pa[j].w };               \
            __nv_bfloat16 h[4], l[4];                                          \
            _Pragma("unroll")                                                  \
            for (int i = 0; i < 4; i++) bsplit(v[i], h[i], l[i]);              \
            __nv_bfloat162 h01; h01.x = h[0]; h01.y = h[1];                    \
            __nv_bfloat162 h23; h23.x = h[2]; h23.y = h[3];                    \
            __nv_bfloat162 l01; l01.x = l[0]; l01.y = l[1];                    \
            __nv_bfloat162 l23; l23.x = l[2]; l23.y = l[3];                    \
            int base = (TA == 0) ? (rA * TST + cA + 4 * j)                     \
                                 : (kA * TS2 + mA + 4 * j);                    \
            *(__nv_bfloat162*)(Ah + base)     = h01;                           \
            *(__nv_bfloat162*)(Ah + base + 2) = h23;                           \
            *(__nv_bfloat162*)(Al + base)     = l01;                           \
            *(__nv_bfloat162*)(Al + base + 2) = l23;                           \
        }                                                                      \
        _Pragma("unroll")                                                      \
        for (int j = 0; j < 4; j++) {                                          \
            float v[4] = { pb[j].x, pb[j].y, pb[j].z, pb[j].w };               \
            __nv_bfloat16 h[4], l[4];                                          \
            _Pragma("unroll")                                                  \
            for (int i = 0; i < 4; i++) bsplit(v[i], h[i], l[i]);              \
            __nv_bfloat162 h01; h01.x = h[0]; h01.y = h[1];                    \
            __nv_bfloat162 h23; h23.x = h[2]; h23.y = h[3];                    \
            __nv_bfloat162 l01; l01.x = l[0]; l01.y = l[1];                    \
            __nv_bfloat162 l23; l23.x = l[2]; l23.y = l[3];                    \
            int base = (TB == 1) ? (rA * TST + cA + 4 * j)                     \
                                 : (kA * TS2 + mA + 4 * j);                    \
            *(__nv_bfloat162*)(Bh + base)     = h01;                           \
            *(__nv_bfloat162*)(Bh + base + 2) = h23;                           \
            *(__nv_bfloat162*)(Bl + base)     = l01;                           \
            *(__nv_bfloat162*)(Bl + base + 2) = l23;                           \
        }                                                                      \
    } while (0)

#define MMASTEP(bf)                                                            \
    do {                                                                       \
        const unsigned bAh = sbase + ((bf) * 4 + 0) * TTILE * 2;               \
        const unsigned bAl = sbase + ((bf) * 4 + 1) * TTILE * 2;               \
        const unsigned bBh = sbase + ((bf) * 4 + 2) * TTILE * 2;               \
        const unsigned bBl = sbase + ((bf) * 4 + 3) * TTILE * 2;               \
        _Pragma("unroll")                                                      \
        for (int kk = 0; kk < 2; kk++) {                                       \
            unsigned ah[2][4], al[2][4], bh[4][4], bl[4][4];                   \
            _Pragma("unroll")                                                  \
            for (int fi = 0; fi < 2; fi++) {                                   \
                if (TA == 0) {                                                 \
                    ldsm4(ah[fi], bAh + aoff[fi] + kk * akk);                  \
                    ldsm4(al[fi], bAl + aoff[fi] + kk * akk);                  \
                } else {                                                       \
                    ldsm4t(ah[fi], bAh + aoff[fi] + kk * akk);                 \
                    ldsm4t(al[fi], bAl + aoff[fi] + kk * akk);                 \
                }                                                              \
            }                                                                  \
            _Pragma("unroll")                                                  \
            for (int fp = 0; fp < 4; fp++) {                                   \
                if (TB == 1) {                                                 \
                    ldsm4(bh[fp], bBh + boff[fp] + kk * bkk);                  \
                    ldsm4(bl[fp], bBl + boff[fp] + kk * bkk);                  \
                } else {                                                       \
                    ldsm4t(bh[fp], bBh + boff[fp] + kk * bkk);                 \
                    ldsm4t(bl[fp], bBl + boff[fp] + kk * bkk);                 \
                }                                                              \
            }                                                                  \
            _Pragma("unroll")                                                  \
            for (int fi = 0; fi < 2; fi++)                                     \
                _Pragma("unroll")                                              \
                for (int fp = 0; fp < 4; fp++)                                 \
                    _Pragma("unroll")                                          \
                    for (int hh = 0; hh < 2; hh++) {                           \
                        float* c = acc[fi][fp * 2 + hh];                       \
                        mma16816(c, ah[fi], &bh[fp][2 * hh]);                  \
                        mma16816(c, ah[fi], &bl[fp][2 * hh]);                  \
                        mma16816(c, al[fi], &bh[fp][2 * hh]);                  \
                    }                                                          \
        }                                                                      \
    } while (0)

    LOADG(0);
    CVSTORE(0);
    __syncthreads();

    const int nt = K / 32;
    for (int tI = 0; tI < nt; tI++) {
        if (tI + 1 < nt) LOADG((tI + 1) * 32);
        MMASTEP(tI & 1);
        if (tI + 1 < nt) {
            CVSTORE((tI + 1) & 1);
            __syncthreads();
        }
    }

    const float alpha = alphaD ? *alphaD : alphaH;
#pragma unroll
    for (int fi = 0; fi < 2; fi++) {
        const int m = m0 + warp_m + fi * 16 + g;
        const float bi0 = bias ? __ldg(&bias[m])     : 0.f;
        const float bi1 = bias ? __ldg(&bias[m + 8]) : 0.f;
#pragma unroll
        for (int fj = 0; fj < 8; fj++) {
            const int n = n0 + warp_n + fj * 8 + t * 2;
            const float* c = acc[fi][fj];
            const long off0 = (long)m * N + n;
            const long off1 = (long)(m + 8) * N + n;
            float2 o0, o1;
            o0.x = alpha * c[0] + bi0; o0.y = alpha * c[1] + bi0;
            o1.x = alpha * c[2] + bi1; o1.y = alpha * c[3] + bi1;
            if (Res) {
                float2 r0 = *(const float2*)&Res[(long)bz * sRes + off0];
                float2 r1 = *(const float2*)&Res[(long)bz * sRes + off1];
                o0.x += r0.x; o0.y += r0.y;
                o1.x += r1.x; o1.y += r1.y;
            }
            *(float2*)&C[off0] = o0;
            *(float2*)&C[off1] = o1;
        }
    }
#undef LOADG
#undef CVSTORE
#undef MMASTEP
}

// --------------------------- reductions ------------------------------------
__device__ __forceinline__ float warpMax(float v) {
#pragma unroll
    for (int o = 16; o; o >>= 1) v = fmaxf(v, __shfl_xor_sync(0xffffffffu, v, o));
    return v;
}
__device__ __forceinline__ float warpSum(float v) {
#pragma unroll
    for (int o = 16; o; o >>= 1) v += __shfl_xor_sync(0xffffffffu, v, o);
    return v;
}

// in-place row softmax; one block per row
__global__ void softmax_kernel(float* __restrict__ d, int ncols)
{
    __shared__ float red[32];
    __shared__ float bcast;
    const long row = blockIdx.x;
    float* p = d + row * (long)ncols;
    const int tid = threadIdx.x, nt = blockDim.x;

    float m = -1e30f;
    for (int i = tid; i < ncols; i += nt) m = fmaxf(m, p[i]);
    m = warpMax(m);
    if ((tid & 31) == 0) red[tid >> 5] = m;
    __syncthreads();
    if (tid < 32) {
        float v = (tid < (nt >> 5)) ? red[tid] : -1e30f;
        v = warpMax(v);
        if (tid == 0) bcast = v;
    }
    __syncthreads();
    m = bcast;

    float s = 0.f;
    for (int i = tid; i < ncols; i += nt) {
        float e = __expf(p[i] - m);
        p[i] = e;
        s += e;
    }
    __syncthreads();
    s = warpSum(s);
    if ((tid & 31) == 0) red[tid >> 5] = s;
    __syncthreads();
    if (tid < 32) {
        float v = (tid < (nt >> 5)) ? red[tid] : 0.f;
        v = warpSum(v);
        if (tid == 0) bcast = v;
    }
    __syncthreads();
    const float inv = 1.f / bcast;
    for (int i = tid; i < ncols; i += nt) p[i] *= inv;
}

// ---------------------- y1 -> bf16 hi/lo split (once) -----------------------
__global__ void split_y1_kernel(const float* __restrict__ y1,
                                __nv_bfloat16* __restrict__ yh,
                                __nv_bfloat16* __restrict__ yl)
{
    const int i = (blockIdx.x * blockDim.x + threadIdx.x) * 4;
    float4 v = *(const float4*)&y1[i];
    __nv_bfloat16 h0,l0,h1,l1,h2,l2,h3,l3;
    bsplit(v.x,h0,l0); bsplit(v.y,h1,l1); bsplit(v.z,h2,l2); bsplit(v.w,h3,l3);
    __nv_bfloat162 a;
    a.x = h0; a.y = h1; *(__nv_bfloat162*)&yh[i]     = a;
    a.x = h2; a.y = h3; *(__nv_bfloat162*)&yh[i + 2] = a;
    a.x = l0; a.y = l1; *(__nv_bfloat162*)&yl[i]     = a;
    a.x = l2; a.y = l3; *(__nv_bfloat162*)&yl[i + 2] = a;
}

// ================= tensor-core fused CAM (flash style, v2) ==================
// K tiles streamed as pre-split bf16 via cp.async double-buffering.
// Smem: Qh,Ql + 2x(Kh,Kl) = 6 tiles of [128][136] bf16 = 204 KB.
#define CST   136
#define CTILE (128 * CST)
#define CAM_SMEM (6 * CTILE * 2)

__global__ __launch_bounds__(256)
void cam_tc_kernel(const float* __restrict__ y1g,
                   const __nv_bfloat16* __restrict__ y1hg,
                   const __nv_bfloat16* __restrict__ y1lg,
                   const float* __restrict__ gptr,
                   float* __restrict__ outg)
{
    extern __shared__ __align__(16) __nv_bfloat16 cs[];
    __nv_bfloat16* Qh = cs;
    __nv_bfloat16* Ql = cs + CTILE;

    const int b  = blockIdx.y;
    const int c0 = blockIdx.x * 128;
    const float* Y          = y1g  + (long)b * CCH * HW;
    const __nv_bfloat16* Yh = y1hg + (long)b * CCH * HW;
    const __nv_bfloat16* Yl = y1lg + (long)b * CCH * HW;

    const int tid = threadIdx.x, wid = tid >> 5, lane = tid & 31;
    const int mi = lane >> 3, ri = lane & 7, g = lane >> 2, t = lane & 3;

    const unsigned sb  = (unsigned)__cvta_generic_to_shared(cs);
    const unsigned bQh = sb;
    const unsigned bQl = sb + CTILE * 2;

    const unsigned aoff = ((wid * 16 + ((mi & 1) << 3) + ri) * CST + ((mi >> 1) << 3)) * 2;
    const unsigned bS = ((((mi >> 1) << 3) + ri) * CST + ((mi & 1) << 3)) * 2;
    const unsigned bT = ((((mi & 1) << 3) + ri) * CST + ((mi >> 1) << 3)) * 2;

    // ---- K tile cp.async loader: tile tt -> buffer buf ----
#define LOADK(tt, buf)                                                         \
    do {                                                                       \
        const unsigned dh = sb + (2 + (buf) * 2) * CTILE * 2;                  \
        const unsigned dl = dh + CTILE * 2;                                    \
        _Pragma("unroll")                                                      \
        for (int i = 0; i < 8; i++) {                                          \
            int c = tid + 256 * i;                                             \
            int r = c >> 4, col8 = (c & 15) * 8;                               \
            cpa16(dh + (r * CST + col8) * 2, Yh + (long)((tt) * 128 + r) * HW + col8); \
            cpa16(dl + (r * CST + col8) * 2, Yl + (long)((tt) * 128 + r) * HW + col8); \
        }                                                                      \
    } while (0)

    // ---- load Q tile (direct bf16 copies) + preload K0 ----
    LOADK(0, 0);
    asm volatile("cp.async.commit_group;" ::: "memory");
#pragma unroll
    for (int i = 0; i < 8; i++) {
        int c = tid + 256 * i;
        int r = c >> 4, col8 = (c & 15) * 8;
        *(uint4*)(Qh + r * CST + col8) = *(const uint4*)(Yh + (long)(c0 + r) * HW + col8);
        *(uint4*)(Ql + r * CST + col8) = *(const uint4*)(Yl + (long)(c0 + r) * HW + col8);
    }

    float Sa[16][4], Oa[16][4];
    float m0r = -1e30f, m1r = -1e30f, l0r = 0.f, l1r = 0.f;
#pragma unroll
    for (int j = 0; j < 16; j++) { Oa[j][0]=Oa[j][1]=Oa[j][2]=Oa[j][3]=0.f; }

    for (int tI = 0; tI < 16; tI++) {
        const int buf = tI & 1;
        if (tI < 15) {
            LOADK(tI + 1, buf ^ 1);
            asm volatile("cp.async.commit_group;" ::: "memory");
            asm volatile("cp.async.wait_group 1;" ::: "memory");
        } else {
            asm volatile("cp.async.wait_group 0;" ::: "memory");
        }
        __syncthreads();

        const unsigned bKh = sb + (2 + buf * 2) * CTILE * 2;
        const unsigned bKl = bKh + CTILE * 2;

#pragma unroll
        for (int j = 0; j < 16; j++) { Sa[j][0]=Sa[j][1]=Sa[j][2]=Sa[j][3]=0.f; }
#pragma unroll
        for (int ks = 0; ks < 8; ks++) {
            unsigned ah[4], al[4];
            ldsm4(ah, bQh + aoff + ks * 32);
            ldsm4(al, bQl + aoff + ks * 32);
#pragma unroll
            for (int fp = 0; fp < 8; fp++) {
                unsigned bh[4], bl[4];
                ldsm4(bh, bKh + bS + fp * (16 * CST * 2) + ks * 32);
                ldsm4(bl, bKl + bS + fp * (16 * CST * 2) + ks * 32);
#pragma unroll
                for (int hh = 0; hh < 2; hh++) {
                    float* c = Sa[fp * 2 + hh];
                    mma16816(c, ah, &bh[2 * hh]);
                    mma16816(c, ah, &bl[2 * hh]);
                    mma16816(c, al, &bh[2 * hh]);
                }
            }
        }

        float mx0 = -1e30f, mx1 = -1e30f;
#pragma unroll
        for (int j = 0; j < 16; j++) {
            mx0 = fmaxf(mx0, fmaxf(-Sa[j][0], -Sa[j][1]));
            mx1 = fmaxf(mx1, fmaxf(-Sa[j][2], -Sa[j][3]));
        }
        mx0 = fmaxf(mx0, __shfl_xor_sync(0xffffffffu, mx0, 1));
        mx0 = fmaxf(mx0, __shfl_xor_sync(0xffffffffu, mx0, 2));
        mx1 = fmaxf(mx1, __shfl_xor_sync(0xffffffffu, mx1, 1));
        mx1 = fmaxf(mx1, __shfl_xor_sync(0xffffffffu, mx1, 2));
        const float mn0 = fmaxf(m0r, mx0), mn1 = fmaxf(m1r, mx1);
        const float sc0 = __expf(m0r - mn0), sc1 = __expf(m1r - mn1);
        float rs0 = 0.f, rs1 = 0.f;
#pragma unroll
        for (int j = 0; j < 16; j++) {
            float p0 = __expf(-Sa[j][0] - mn0); Sa[j][0] = p0; rs0 += p0;
            float p1 = __expf(-Sa[j][1] - mn0); Sa[j][1] = p1; rs0 += p1;
            float p2 = __expf(-Sa[j][2] - mn1); Sa[j][2] = p2; rs1 += p2;
            float p3 = __expf(-Sa[j][3] - mn1); Sa[j][3] = p3; rs1 += p3;
        }
        rs0 += __shfl_xor_sync(0xffffffffu, rs0, 1);
        rs0 += __shfl_xor_sync(0xffffffffu, rs0, 2);
        rs1 += __shfl_xor_sync(0xffffffffu, rs1, 1);
        rs1 += __shfl_xor_sync(0xffffffffu, rs1, 2);
        l0r = l0r * sc0 + rs0;  l1r = l1r * sc1 + rs1;
        m0r = mn0;  m1r = mn1;
#pragma unroll
        for (int j = 0; j < 16; j++) {
            Oa[j][0] *= sc0; Oa[j][1] *= sc0;
            Oa[j][2] *= sc1; Oa[j][3] *= sc1;
        }

#pragma unroll
        for (int kp = 0; kp < 8; kp++) {
            const float* p0 = Sa[2 * kp];
            const float* p1 = Sa[2 * kp + 1];
            unsigned aPh[4], aPl[4];
            aPh[0] = packbf(p0[0], p0[1]);
            aPh[1] = packbf(p0[2], p0[3]);
            aPh[2] = packbf(p1[0], p1[1]);
            aPh[3] = packbf(p1[2], p1[3]);
            aPl[0] = packlo(p0[0], p0[1], aPh[0]);
            aPl[1] = packlo(p0[2], p0[3], aPh[1]);
            aPl[2] = packlo(p1[0], p1[1], aPh[2]);
            aPl[3] = packlo(p1[2], p1[3], aPh[3]);
#pragma unroll
            for (int fp = 0; fp < 8; fp++) {
                unsigned vh[4], vl[4];
                ldsm4t(vh, bKh + bT + kp * (16 * CST * 2) + fp * 32);
                ldsm4t(vl, bKl + bT + kp * (16 * CST * 2) + fp * 32);
#pragma unroll
                for (int hh = 0; hh < 2; hh++) {
                    float* c = Oa[fp * 2 + hh];
                    mma16816(c, aPh, &vh[2 * hh]);
                    mma16816(c, aPh, &vl[2 * hh]);
                    mma16816(c, aPl, &vh[2 * hh]);
                }
            }
        }
        __syncthreads();
    }
#undef LOADK

    const float gam = *gptr;
    const float i0 = gam / l0r, i1 = gam / l1r;
    const int r0 = c0 + wid * 16 + g, r1 = r0 + 8;
    float* O = outg + (long)b * CCH * HW;
#pragma unroll
    for (int j = 0; j < 16; j++) {
        const int col = j * 8 + t * 2;
        const long o0 = (long)r0 * HW + col;
        const long o1 = (long)r1 * HW + col;
        float2 y0 = *(const float2*)&Y[o0];
        float2 y1v = *(const float2*)&Y[o1];
        float2 w0, w1;
        w0.x = Oa[j][0] * i0 + y0.x;  w0.y = Oa[j][1] * i0 + y0.y;
        w1.x = Oa[j][2] * i1 + y1v.x; w1.y = Oa[j][3] * i1 + y1v.y;
        *(float2*)&O[o0] = w0;
        *(float2*)&O[o1] = w1;
    }
}

// ------------------------ graph construction -------------------------------
__global__ void graph_build(const float* __restrict__ ip,
                            const float* __restrict__ adj,
                            float* __restrict__ graph)
{
    __shared__ float reda[4], redb[4];
    const int n = blockIdx.y, v = blockIdx.x, w = threadIdx.x;
    const long base = ((long)n * VV + v) * VV;

    const float sqv = ip[((long)n * VV + v) * VV + v];
    const float sqw = ip[((long)n * VV + w) * VV + w];
    const float e   = ip[base + w];

    float d2   = sqv + sqw - 2.f * e;
    float dist = sqrtf(fmaxf(d2, 1e-12f));
    float sim  = 2.f / (expf(dist) + 1.f);
    float av   = adj[base + w];
    if (w == v) { sim = 0.f; av = 0.f; }

    float s1 = warpSum(fabsf(sim));
    float s2 = warpSum(fabsf(av));
    if ((w & 31) == 0) { reda[w >> 5] = s1; redb[w >> 5] = s2; }
    __syncthreads();
    const float ssum = reda[0] + reda[1] + reda[2] + reda[3];
    const float asum = redb[0] + redb[1] + redb[2] + redb[3];

    graph[base + w] = 0.5f * (av / fmaxf(asum, 1e-12f) + sim / fmaxf(ssum, 1e-12f));
}

// ------------------------- batch-norm stats --------------------------------
__global__ void bn_stats(const float* __restrict__ hp,
                         float* __restrict__ mean, float* __restrict__ var,
                         int rows, int C)
{
    __shared__ float shs[8][32];
    __shared__ float shs2[8][32];
    const int lane = threadIdx.x & 31;
    const int ry   = threadIdx.x >> 5;
    const int c    = blockIdx.x * 32 + lane;

    float s = 0.f, s2 = 0.f;
    for (int r = ry; r < rows; r += 8) {
        float v = hp[(long)r * C + c];
        s += v; s2 += v * v;
    }
    shs[ry][lane] = s; shs2[ry][lane] = s2;
    __syncthreads();
    if (ry == 0) {
#pragma unroll
        for (int j = 1; j < 8; j++) { s += shs[j][lane]; s2 += shs2[j][lane]; }
        float mu = s / rows;
        mean[c] = mu;
        var[c]  = s2 / rows - mu * mu;
    }
}

// ------------------- BN apply + LeakyReLU + residual -----------------------
__global__ void bn_apply(const float* __restrict__ inp,
                         const float* __restrict__ hp,
                         const float* __restrict__ mean,
                         const float* __restrict__ var,
                         const float* __restrict__ bw,
                         const float* __restrict__ bb,
                         const float* __restrict__ gptr,
                         float* __restrict__ out, int total, int C)
{
    const int idx = blockIdx.x * blockDim.x + threadIdx.x;
    if (idx >= total) return;
    const int c = idx & (C - 1);
    const float g = *gptr;
    float vv = (hp[idx] - mean[c]) * rsqrtf(var[c] + 1e-5f) * bw[c] + bb[c];
    float lr = vv > 0.f ? vv : 0.1f * vv;
    out[idx] = inp[idx] + g * lr;
}

// ------------------------------ host side ----------------------------------
static void launch_gemm(int TA, int TB,
                        const float* A, const float* B, float* C,
                        int M, int N, int K,
                        long sA, long sB, long sC, int batch,
                        const float* bias,
                        const float* Res, long sRes,
                        float aH, const float* aD, cudaStream_t st)
{
    dim3 grid(N / 128, M / 128, batch);
    dim3 blk(256);
    if (TA == 0 && TB == 0)
        tgemm_kernel<0, 0><<<grid, blk, TSMEM, st>>>(A, B, C, M, N, K, sA, sB, sC, bias, Res, sRes, aH, aD);
    else if (TA == 1 && TB == 0)
        tgemm_kernel<1, 0><<<grid, blk, TSMEM, st>>>(A, B, C, M, N, K, sA, sB, sC, bias, Res, sRes, aH, aD);
    else
        tgemm_kernel<0, 1><<<grid, blk, TSMEM, st>>>(A, B, C, M, N, K, sA, sB, sC, bias, Res, sRes, aH, aD);
}

extern "C" void kernel_launch(void* const* d_in, const int* in_sizes, int n_in,
                              void* d_out, int out_size)
{
    const float* x     = (const float*)d_in[0];
    const float* vfeat = (const float*)d_in[1];
    const float* adj   = (const float*)d_in[2];
    const float* Wq    = (const float*)d_in[3];
    const float* bq    = (const float*)d_in[4];
    const float* Wk    = (const float*)d_in[5];
    const float* bk    = (const float*)d_in[6];
    const float* Wv    = (const float*)d_in[7];
    const float* bv    = (const float*)d_in[8];
    const float* gpam  = (const float*)d_in[9];
    const float* gcam  = (const float*)d_in[10];
    const float* Wg    = (const float*)d_in[11];
    const float* bnw   = (const float*)d_in[12];
    const float* bnb   = (const float*)d_in[13];
    const float* gg    = (const float*)d_in[14];
    float* out = (float*)d_out;

    float *q, *k, *v, *att1, *y1, *h, *ip, *graph, *hp, *gbuf, *mean, *var;
    __nv_bfloat16 *y1h, *y1l;
    cudaGetSymbolAddress((void**)&q,    d_q);
    cudaGetSymbolAddress((void**)&k,    d_k);
    cudaGetSymbolAddress((void**)&v,    d_v);
    cudaGetSymbolAddress((void**)&att1, d_att1);
    cudaGetSymbolAddress((void**)&y1,   d_y1);
    cudaGetSymbolAddress((void**)&y1h,  d_y1h);
    cudaGetSymbolAddress((void**)&y1l,  d_y1l);
    cudaGetSymbolAddress((void**)&h,    d_h);
    cudaGetSymbolAddress((void**)&ip,   d_ip);
    cudaGetSymbolAddress((void**)&graph,d_graph);
    cudaGetSymbolAddress((void**)&hp,   d_hp);
    cudaGetSymbolAddress((void**)&gbuf, d_gbuf);
    cudaGetSymbolAddress((void**)&mean, d_mean);
    cudaGetSymbolAddress((void**)&var,  d_var);

    static int inited = 0;
    if (!inited) {
        cudaFuncSetAttribute(tgemm_kernel<0, 0>,
                             cudaFuncAttributeMaxDynamicSharedMemorySize, TSMEM);
        cudaFuncSetAttribute(tgemm_kernel<1, 0>,
                             cudaFuncAttributeMaxDynamicSharedMemorySize, TSMEM);
        cudaFuncSetAttribute(tgemm_kernel<0, 1>,
                             cudaFuncAttributeMaxDynamicSharedMemorySize, TSMEM);
        cudaFuncSetAttribute(cam_tc_kernel,
                             cudaFuncAttributeMaxDynamicSharedMemorySize, CAM_SMEM);
        inited = 1;
    }
    static cudaStream_t s1 = [](){ cudaStream_t s;
        cudaStreamCreateWithFlags(&s, cudaStreamNonBlocking); return s; }();
    static cudaStream_t s2 = [](){ cudaStream_t s;
        cudaStreamCreateWithFlags(&s, cudaStreamNonBlocking); return s; }();
    static cudaEvent_t evF = [](){ cudaEvent_t e;
        cudaEventCreateWithFlags(&e, cudaEventDisableTiming); return e; }();
    static cudaEvent_t evK = [](){ cudaEvent_t e;
        cudaEventCreateWithFlags(&e, cudaEventDisableTiming); return e; }();
    static cudaEvent_t evV = [](){ cudaEvent_t e;
        cudaEventCreateWithFlags(&e, cudaEventDisableTiming); return e; }();
    static cudaEvent_t evJ = [](){ cudaEvent_t e;
        cudaEventCreateWithFlags(&e, cudaEventDisableTiming); return e; }();

    const long CHW = (long)CCH * HW;          // 262144
    const long QHW = (long)C8 * HW;           // 32768
    const long GST = (long)VV * CCH;          // 262144
    cudaStream_t s0 = 0;

    // ---- fork: s1 gets Wk+Wv, s2 gets graph chain ----
    cudaEventRecord(evF, s0);
    cudaStreamWaitEvent(s1, evF, 0);
    cudaStreamWaitEvent(s2, evF, 0);

    // ---------------- PAM ----------------
    launch_gemm(0, 0, Wq, x, q, C8,  HW, CCH, 0, CHW, QHW, BSZ, bq, nullptr, 0, 1.f, nullptr, s0);
    launch_gemm(0, 0, Wk, x, k, C8,  HW, CCH, 0, CHW, QHW, BSZ, bk, nullptr, 0, 1.f, nullptr, s1);
    cudaEventRecord(evK, s1);
    launch_gemm(0, 0, Wv, x, v, CCH, HW, CCH, 0, CHW, CHW, BSZ, bv, nullptr, 0, 1.f, nullptr, s1);
    cudaEventRecord(evV, s1);

    cudaStreamWaitEvent(s0, evK, 0);
    launch_gemm(1, 0, q, k, att1, HW, HW, C8, QHW, QHW, (long)HW * HW, BSZ,
                nullptr, nullptr, 0, 1.f, nullptr, s0);
    softmax_kernel<<<BSZ * HW, 128, 0, s0>>>(att1, HW);
    cudaStreamWaitEvent(s0, evV, 0);
    launch_gemm(0, 1, v, att1, y1, CCH, HW, HW, CHW, (long)HW * HW, CHW, BSZ,
                nullptr, x, CHW, 0.f, gpam, s0);

    // ---------------- CAM (s0): split y1 once, then tensor-core flash ------
    split_y1_kernel<<<(BSZ * CCH * HW) / (4 * 256), 256, 0, s0>>>(y1, y1h, y1l);
    {
        dim3 grid(CCH / 128, BSZ);
        cam_tc_kernel<<<grid, 256, CAM_SMEM, s0>>>(y1, y1h, y1l, gcam, out);
    }

    // ------------- Graph layers (s2) -------------
    const float* inp = vfeat;
    for (int i = 0; i < GNUM; i++) {
        float* outg = (i == GNUM - 1) ? (out + (long)BSZ * CCH * HW) : gbuf;
        launch_gemm(0, 1, inp, Wg + (long)i * CCH * CCH, h,
                    NV * VV, CCH, CCH, 0, 0, 0, 1, nullptr, nullptr, 0, 1.f, nullptr, s2);
        launch_gemm(0, 1, inp, inp, ip, VV, VV, CCH, GST, GST, (long)VV * VV, NV,
                    nullptr, nullptr, 0, 1.f, nullptr, s2);
        graph_build<<<dim3(VV, NV), VV, 0, s2>>>(ip, adj, graph);
        launch_gemm(0, 0, graph, h, hp, VV, CCH, VV, (long)VV * VV, GST, GST, NV,
                    nullptr, nullptr, 0, 1.f, nullptr, s2);
        bn_stats<<<CCH / 32, 256, 0, s2>>>(hp, mean, var, NV * VV, CCH);
        bn_apply<<<(NV * VV * CCH + 255) / 256, 256, 0, s2>>>(
            inp, hp, mean, var, bnw + (long)i * CCH, bnb + (long)i * CCH,
            gg + i, outg, NV * VV * CCH, CCH);
        inp = outg;
    }

    // ---- join ----
    cudaEventRecord(evJ, s2);
    cudaStreamWaitEvent(s0, evJ, 0);
}

// round 12
// speedup vs baseline: 1.3181x; 1.0559x over previous
#include <cuda_runtime.h>
#include <cuda_bf16.h>
#include <math.h>

// ---------------------------------------------------------------------------
// Problem constants
// ---------------------------------------------------------------------------
#define BSZ   16
#define CCH   2048
#define HW    128
#define C8    256
#define NV    16
#define VV    128
#define GNUM  2

// ------------------------- scratch (device globals) ------------------------
__device__ __align__(256) float d_q   [BSZ * C8 * HW];
__device__ __align__(256) float d_k   [BSZ * C8 * HW];
__device__ __align__(256) float d_v   [BSZ * CCH * HW];
__device__ __align__(256) float d_att1[BSZ * HW * HW];
__device__ __align__(256) float d_y1  [BSZ * CCH * HW];
__device__ __align__(256) __nv_bfloat16 d_y1h[BSZ * CCH * HW];
__device__ __align__(256) __nv_bfloat16 d_y1l[BSZ * CCH * HW];
__device__ __align__(256) float d_ip  [NV * VV * VV];
__device__ __align__(256) float d_hp  [NV * VV * CCH];
__device__ __align__(256) float d_gbuf[NV * VV * CCH];
__device__ __align__(256) float d_mean[CCH];
__device__ __align__(256) float d_var [CCH];
// bf16 hi/lo operand arrays for the graph chain
__device__ __align__(256) __nv_bfloat16 d_vfh[NV * VV * CCH];
__device__ __align__(256) __nv_bfloat16 d_vfl[NV * VV * CCH];
__device__ __align__(256) __nv_bfloat16 d_gbh[NV * VV * CCH];
__device__ __align__(256) __nv_bfloat16 d_gbl[NV * VV * CCH];
__device__ __align__(256) __nv_bfloat16 d_wgh[GNUM * CCH * CCH];
__device__ __align__(256) __nv_bfloat16 d_wgl[GNUM * CCH * CCH];
__device__ __align__(256) __nv_bfloat16 d_hh [NV * VV * CCH];
__device__ __align__(256) __nv_bfloat16 d_hl [NV * VV * CCH];
__device__ __align__(256) __nv_bfloat16 d_gph[NV * VV * VV];
__device__ __align__(256) __nv_bfloat16 d_gpl[NV * VV * VV];

// ---------------------- shared mma/ldsm/split helpers -----------------------
__device__ __forceinline__ void ldsm4(unsigned* r, unsigned addr) {
    asm volatile("ldmatrix.sync.aligned.m8n8.x4.shared.b16 {%0,%1,%2,%3}, [%4];"
        : "=r"(r[0]), "=r"(r[1]), "=r"(r[2]), "=r"(r[3]) : "r"(addr));
}
__device__ __forceinline__ void ldsm4t(unsigned* r, unsigned addr) {
    asm volatile("ldmatrix.sync.aligned.m8n8.x4.trans.shared.b16 {%0,%1,%2,%3}, [%4];"
        : "=r"(r[0]), "=r"(r[1]), "=r"(r[2]), "=r"(r[3]) : "r"(addr));
}
__device__ __forceinline__ void mma16816(float* c, const unsigned* a, const unsigned* b) {
    asm volatile("mma.sync.aligned.m16n8k16.row.col.f32.bf16.bf16.f32 "
        "{%0,%1,%2,%3}, {%4,%5,%6,%7}, {%8,%9}, {%0,%1,%2,%3};"
        : "+f"(c[0]), "+f"(c[1]), "+f"(c[2]), "+f"(c[3])
        : "r"(a[0]), "r"(a[1]), "r"(a[2]), "r"(a[3]), "r"(b[0]), "r"(b[1]));
}
__device__ __forceinline__ void bsplit(float x, __nv_bfloat16& h, __nv_bfloat16& l) {
    h = __float2bfloat16(x);
    l = __float2bfloat16(x - __bfloat162float(h));
}
__device__ __forceinline__ unsigned packbf(float a, float b) {
    __nv_bfloat162 p; p.x = __float2bfloat16(a); p.y = __float2bfloat16(b);
    return *(unsigned*)&p;
}
__device__ __forceinline__ void cpa16(unsigned s, const void* g) {
    asm volatile("cp.async.ca.shared.global [%0], [%1], 16;" :: "r"(s), "l"(g));
}

#define TST   40
#define TS2   136
#define TTILE (128 * TST)
#define TSMEM (2 * 4 * TTILE * 2)

// ======================= bf16-split tensor-core GEMM ========================
// (R10 winner, unchanged) fp32 inputs, in-kernel split. 256 thr, 8 warps.
template<int TA, int TB>
__global__ __launch_bounds__(256)
void tgemm_kernel(const float* __restrict__ Ag, const float* __restrict__ Bg,
                  float* __restrict__ Cg,
                  int M, int N, int K,
                  long sA, long sB, long sC,
                  const float* __restrict__ bias,
                  const float* __restrict__ Res, long sRes,
                  float alphaH, const float* __restrict__ alphaD)
{
    extern __shared__ __align__(16) __nv_bfloat16 ts[];

    const int bz = blockIdx.z;
    const float* A = Ag + (long)bz * sA;
    const float* B = Bg + (long)bz * sB;
    float*       C = Cg + (long)bz * sC;

    const int m0 = blockIdx.y * 128;
    const int n0 = blockIdx.x * 128;
    const int tid  = threadIdx.x;
    const int wid  = tid >> 5;
    const int lane = tid & 31;
    const int warp_m = (wid >> 1) * 32;
    const int warp_n = (wid & 1) * 64;
    const int mi = lane >> 3, ri = lane & 7;
    const int g  = lane >> 2, t  = lane & 3;

    const unsigned sbase = (unsigned)__cvta_generic_to_shared(ts);

    unsigned aoff[2], boff[4];
#pragma unroll
    for (int fi = 0; fi < 2; fi++) {
        if (TA == 0)
            aoff[fi] = ((warp_m + fi * 16 + ((mi & 1) << 3) + ri) * TST + ((mi >> 1) << 3)) * 2;
        else
            aoff[fi] = ((((mi >> 1) << 3) + ri) * TS2 + warp_m + fi * 16 + ((mi & 1) << 3)) * 2;
    }
#pragma unroll
    for (int fp = 0; fp < 4; fp++) {
        if (TB == 1)
            boff[fp] = ((warp_n + fp * 16 + ((mi >> 1) << 3) + ri) * TST + ((mi & 1) << 3)) * 2;
        else
            boff[fp] = ((((mi & 1) << 3) + ri) * TS2 + warp_n + fp * 16 + ((mi >> 1) << 3)) * 2;
    }
    const unsigned akk = (TA == 0) ? 32u : (unsigned)(16 * TS2 * 2);
    const unsigned bkk = (TB == 1) ? 32u : (unsigned)(16 * TS2 * 2);

    float acc[2][8][4];
#pragma unroll
    for (int i = 0; i < 2; i++)
#pragma unroll
        for (int j = 0; j < 8; j++)
#pragma unroll
            for (int q = 0; q < 4; q++) acc[i][j][q] = 0.f;

    float4 pa[4], pb[4];
    const int rA = tid >> 1, cA = (tid & 1) * 16;
    const int kA = tid >> 3, mA = (tid & 7) * 16;

#define LOADG(k0)                                                              \
    do {                                                                       \
        if (TA == 0) {                                                         \
            _Pragma("unroll")                                                  \
            for (int j = 0; j < 4; j++)                                        \
                pa[j] = *(const float4*)&A[(long)(m0 + rA) * K + (k0) + cA + 4 * j]; \
        } else {                                                               \
            _Pragma("unroll")                                                  \
            for (int j = 0; j < 4; j++)                                        \
                pa[j] = *(const float4*)&A[(long)((k0) + kA) * M + m0 + mA + 4 * j]; \
        }                                                                      \
        if (TB == 1) {                                                         \
            _Pragma("unroll")                                                  \
            for (int j = 0; j < 4; j++)                                        \
                pb[j] = *(const float4*)&B[(long)(n0 + rA) * K + (k0) + cA + 4 * j]; \
        } else {                                                               \
            _Pragma("unroll")                                                  \
            for (int j = 0; j < 4; j++)                                        \
                pb[j] = *(const float4*)&B[(long)((k0) + kA) * N + n0 + mA + 4 * j]; \
        }                                                                      \
    } while (0)

#define CVSTORE(bf)                                                            \
    do {                                                                       \
        __nv_bfloat16* Ah = ts + ((bf) * 4 + 0) * TTILE;                       \
        __nv_bfloat16* Al = ts + ((bf) * 4 + 1) * TTILE;                       \
        __nv_bfloat16* Bh = ts + ((bf) * 4 + 2) * TTILE;                       \
        __nv_bfloat16* Bl = ts + ((bf) * 4 + 3) * TTILE;                       \
        _Pragma("unroll")                                                      \
        for (int j = 0; j < 4; j++) {                                          \
            float v[4] = { pa[j].x, pa[j].y, pa[j].z, pa[j].w };               \
            __nv_bfloat16 h[4], l[4];                                          \
            _Pragma("unroll")                                                  \
            for (int i = 0; i < 4; i++) bsplit(v[i], h[i], l[i]);              \
            __nv_bfloat162 h01; h01.x = h[0]; h01.y = h[1];                    \
            __nv_bfloat162 h23; h23.x = h[2]; h23.y = h[3];                    \
            __nv_bfloat162 l01; l01.x = l[0]; l01.y = l[1];                    \
            __nv_bfloat162 l23; l23.x = l[2]; l23.y = l[3];                    \
            int base = (TA == 0) ? (rA * TST + cA + 4 * j)                     \
                                 : (kA * TS2 + mA + 4 * j);                    \
            *(__nv_bfloat162*)(Ah + base)     = h01;                           \
            *(__nv_bfloat162*)(Ah + base + 2) = h23;                           \
            *(__nv_bfloat162*)(Al + base)     = l01;                           \
            *(__nv_bfloat162*)(Al + base + 2) = l23;                           \
        }                                                                      \
        _Pragma("unroll")                                                      \
        for (int j = 0; j < 4; j++) {                                          \
            float v[4] = { pb[j].x, pb[j].y, pb[j].z, pb[j].w };               \
            __nv_bfloat16 h[4], l[4];                                          \
            _Pragma("unroll")                                                  \
            for (int i = 0; i < 4; i++) bsplit(v[i], h[i], l[i]);              \
            __nv_bfloat162 h01; h01.x = h[0]; h01.y = h[1];                    \
            __nv_bfloat162 h23; h23.x = h[2]; h23.y = h[3];                    \
            __nv_bfloat162 l01; l01.x = l[0]; l01.y = l[1];                    \
            __nv_bfloat162 l23; l23.x = l[2]; l23.y = l[3];                    \
            int base = (TB == 1) ? (rA * TST + cA + 4 * j)                     \
                                 : (kA * TS2 + mA + 4 * j);                    \
            *(__nv_bfloat162*)(Bh + base)     = h01;                           \
            *(__nv_bfloat162*)(Bh + base + 2) = h23;                           \
            *(__nv_bfloat162*)(Bl + base)     = l01;                           \
            *(__nv_bfloat162*)(Bl + base + 2) = l23;                           \
        }                                                                      \
    } while (0)

#define MMASTEP(bf)                                                            \
    do {                                                                       \
        const unsigned bAh = sbase + ((bf) * 4 + 0) * TTILE * 2;               \
        const unsigned bAl = sbase + ((bf) * 4 + 1) * TTILE * 2;               \
        const unsigned bBh = sbase + ((bf) * 4 + 2) * TTILE * 2;               \
        const unsigned bBl = sbase + ((bf) * 4 + 3) * TTILE * 2;               \
        _Pragma("unroll")                                                      \
        for (int kk = 0; kk < 2; kk++) {                                       \
            unsigned ah[2][4], al[2][4], bh[4][4], bl[4][4];                   \
            _Pragma("unroll")                                                  \
            for (int fi = 0; fi < 2; fi++) {                                   \
                if (TA == 0) {                                                 \
                    ldsm4(ah[fi], bAh + aoff[fi] + kk * akk);                  \
                    ldsm4(al[fi], bAl + aoff[fi] + kk * akk);                  \
                } else {                                                       \
                    ldsm4t(ah[fi], bAh + aoff[fi] + kk * akk);                 \
                    ldsm4t(al[fi], bAl + aoff[fi] + kk * akk);                 \
                }                                                              \
            }                                                                  \
            _Pragma("unroll")                                                  \
            for (int fp = 0; fp < 4; fp++) {                                   \
                if (TB == 1) {                                                 \
                    ldsm4(bh[fp], bBh + boff[fp] + kk * bkk);                  \
                    ldsm4(bl[fp], bBl + boff[fp] + kk * bkk);                  \
                } else {                                                       \
                    ldsm4t(bh[fp], bBh + boff[fp] + kk * bkk);                 \
                    ldsm4t(bl[fp], bBl + boff[fp] + kk * bkk);                 \
                }                                                              \
            }                                                                  \
            _Pragma("unroll")                                                  \
            for (int fi = 0; fi < 2; fi++)                                     \
                _Pragma("unroll")                                              \
                for (int fp = 0; fp < 4; fp++)                                 \
                    _Pragma("unroll")                                          \
                    for (int hh = 0; hh < 2; hh++) {                           \
                        float* c = acc[fi][fp * 2 + hh];                       \
                        mma16816(c, ah[fi], &bh[fp][2 * hh]);                  \
                        mma16816(c, ah[fi], &bl[fp][2 * hh]);                  \
                        mma16816(c, al[fi], &bh[fp][2 * hh]);                  \
                    }                                                          \
        }                                                                      \
    } while (0)

    LOADG(0);
    CVSTORE(0);
    __syncthreads();

    const int nt = K / 32;
    for (int tI = 0; tI < nt; tI++) {
        if (tI + 1 < nt) LOADG((tI + 1) * 32);
        MMASTEP(tI & 1);
        if (tI + 1 < nt) {
            CVSTORE((tI + 1) & 1);
            __syncthreads();
        }
    }

    const float alpha = alphaD ? *alphaD : alphaH;
#pragma unroll
    for (int fi = 0; fi < 2; fi++) {
        const int m = m0 + warp_m + fi * 16 + g;
        const float bi0 = bias ? __ldg(&bias[m])     : 0.f;
        const float bi1 = bias ? __ldg(&bias[m + 8]) : 0.f;
#pragma unroll
        for (int fj = 0; fj < 8; fj++) {
            const int n = n0 + warp_n + fj * 8 + t * 2;
            const float* c = acc[fi][fj];
            const long off0 = (long)m * N + n;
            const long off1 = (long)(m + 8) * N + n;
            float2 o0, o1;
            o0.x = alpha * c[0] + bi0; o0.y = alpha * c[1] + bi0;
            o1.x = alpha * c[2] + bi1; o1.y = alpha * c[3] + bi1;
            if (Res) {
                float2 r0 = *(const float2*)&Res[(long)bz * sRes + off0];
                float2 r1 = *(const float2*)&Res[(long)bz * sRes + off1];
                o0.x += r0.x; o0.y += r0.y;
                o1.x += r1.x; o1.y += r1.y;
            }
            *(float2*)&C[off0] = o0;
            *(float2*)&C[off1] = o1;
        }
    }
#undef LOADG
#undef CVSTORE
#undef MMASTEP
}

// ================= pre-split bf16-input GEMM (graph chain) ==================
// Inputs already split hi/lo in gmem; cp.async double-buffered loads;
// optional split bf16 output (Chg/Clg) and/or f32 output (Cg).
template<int TA, int TB>
__global__ __launch_bounds__(256, 2)
void tbgemm_kernel(const __nv_bfloat16* __restrict__ Ahg,
                   const __nv_bfloat16* __restrict__ Alg,
                   const __nv_bfloat16* __restrict__ Bhg,
                   const __nv_bfloat16* __restrict__ Blg,
                   float* __restrict__ Cg,
                   __nv_bfloat16* __restrict__ Chg,
                   __nv_bfloat16* __restrict__ Clg,
                   int M, int N, int K,
                   long sA, long sB, long sC)
{
    extern __shared__ __align__(16) __nv_bfloat16 ts[];

    const int bz = blockIdx.z;
    const __nv_bfloat16* Ah = Ahg + (long)bz * sA;
    const __nv_bfloat16* Al = Alg + (long)bz * sA;
    const __nv_bfloat16* Bh = Bhg + (long)bz * sB;
    const __nv_bfloat16* Bl = Blg + (long)bz * sB;

    const int m0 = blockIdx.y * 128;
    const int n0 = blockIdx.x * 128;
    const int tid  = threadIdx.x;
    const int wid  = tid >> 5;
    const int lane = tid & 31;
    const int warp_m = (wid >> 1) * 32;
    const int warp_n = (wid & 1) * 64;
    const int mi = lane >> 3, ri = lane & 7;
    const int g  = lane >> 2, t  = lane & 3;

    const unsigned sbase = (unsigned)__cvta_generic_to_shared(ts);

    unsigned aoff[2], boff[4];
#pragma unroll
    for (int fi = 0; fi < 2; fi++) {
        if (TA == 0)
            aoff[fi] = ((warp_m + fi * 16 + ((mi & 1) << 3) + ri) * TST + ((mi >> 1) << 3)) * 2;
        else
            aoff[fi] = ((((mi >> 1) << 3) + ri) * TS2 + warp_m + fi * 16 + ((mi & 1) << 3)) * 2;
    }
#pragma unroll
    for (int fp = 0; fp < 4; fp++) {
        if (TB == 1)
            boff[fp] = ((warp_n + fp * 16 + ((mi >> 1) << 3) + ri) * TST + ((mi & 1) << 3)) * 2;
        else
            boff[fp] = ((((mi & 1) << 3) + ri) * TS2 + warp_n + fp * 16 + ((mi >> 1) << 3)) * 2;
    }
    const unsigned akk = (TA == 0) ? 32u : (unsigned)(16 * TS2 * 2);
    const unsigned bkk = (TB == 1) ? 32u : (unsigned)(16 * TS2 * 2);

    float acc[2][8][4];
#pragma unroll
    for (int i = 0; i < 2; i++)
#pragma unroll
        for (int j = 0; j < 8; j++)
#pragma unroll
            for (int q = 0; q < 4; q++) acc[i][j][q] = 0.f;

#define CPLOAD(k0, bf)                                                         \
    do {                                                                       \
        const unsigned dAh = sbase + ((bf) * 4 + 0) * TTILE * 2;               \
        const unsigned dAl = sbase + ((bf) * 4 + 1) * TTILE * 2;               \
        const unsigned dBh = sbase + ((bf) * 4 + 2) * TTILE * 2;               \
        const unsigned dBl = sbase + ((bf) * 4 + 3) * TTILE * 2;               \
        if (TA == 0) {                                                         \
            _Pragma("unroll")                                                  \
            for (int i = 0; i < 2; i++) {                                      \
                int idx = tid + 256 * i; int r = idx >> 2, c8 = (idx & 3) * 8; \
                long go = (long)(m0 + r) * K + (k0) + c8;                      \
                cpa16(dAh + (r * TST + c8) * 2, Ah + go);                      \
                cpa16(dAl + (r * TST + c8) * 2, Al + go);                      \
            }                                                                  \
        } else {                                                               \
            _Pragma("unroll")                                                  \
            for (int i = 0; i < 2; i++) {                                      \
                int idx = tid + 256 * i; int r = idx >> 4, c8 = (idx & 15) * 8;\
                long go = (long)((k0) + r) * M + m0 + c8;                      \
                cpa16(dAh + (r * TS2 + c8) * 2, Ah + go);                      \
                cpa16(dAl + (r * TS2 + c8) * 2, Al + go);                      \
            }                                                                  \
        }                                                                      \
        if (TB == 1) {                                                         \
            _Pragma("unroll")                                                  \
            for (int i = 0; i < 2; i++) {                                      \
                int idx = tid + 256 * i; int r = idx >> 2, c8 = (idx & 3) * 8; \
                long go = (long)(n0 + r) * K + (k0) + c8;                      \
                cpa16(dBh + (r * TST + c8) * 2, Bh + go);                      \
                cpa16(dBl + (r * TST + c8) * 2, Bl + go);                      \
            }                                                                  \
        } else {                                                               \
            _Pragma("unroll")                                                  \
            for (int i = 0; i < 2; i++) {                                      \
                int idx = tid + 256 * i; int r = idx >> 4, c8 = (idx & 15) * 8;\
                long go = (long)((k0) + r) * N + n0 + c8;                      \
                cpa16(dBh + (r * TS2 + c8) * 2, Bh + go);                      \
                cpa16(dBl + (r * TS2 + c8) * 2, Bl + go);                      \
            }                                                                  \
        }                                                                      \
    } while (0)

#define MMASTEP(bf)                                                            \
    do {                                                                       \
        const unsigned bAh = sbase + ((bf) * 4 + 0) * TTILE * 2;               \
        const unsigned bAl = sbase + ((bf) * 4 + 1) * TTILE * 2;               \
        const unsigned bBh = sbase + ((bf) * 4 + 2) * TTILE * 2;               \
        const unsigned bBl = sbase + ((bf) * 4 + 3) * TTILE * 2;               \
        _Pragma("unroll")                                                      \
        for (int kk = 0; kk < 2; kk++) {                                       \
            unsigned ah[2][4], al[2][4], bh[4][4], bl[4][4];                   \
            _Pragma("unroll")                                                  \
            for (int fi = 0; fi < 2; fi++) {                                   \
                if (TA == 0) {                                                 \
                    ldsm4(ah[fi], bAh + aoff[fi] + kk * akk);                  \
                    ldsm4(al[fi], bAl + aoff[fi] + kk * akk);                  \
                } else {                                                       \
                    ldsm4t(ah[fi], bAh + aoff[fi] + kk * akk);                 \
                    ldsm4t(al[fi], bAl + aoff[fi] + kk * akk);                 \
                }                                                              \
            }                                                                  \
            _Pragma("unroll")                                                  \
            for (int fp = 0; fp < 4; fp++) {                                   \
                if (TB == 1) {                                                 \
                    ldsm4(bh[fp], bBh + boff[fp] + kk * bkk);                  \
                    ldsm4(bl[fp], bBl + boff[fp] + kk * bkk);                  \
                } else {                                                       \
                    ldsm4t(bh[fp], bBh + boff[fp] + kk * bkk);                 \
                    ldsm4t(bl[fp], bBl + boff[fp] + kk * bkk);                 \
                }                                                              \
            }                                                                  \
            _Pragma("unroll")                                                  \
            for (int fi = 0; fi < 2; fi++)                                     \
                _Pragma("unroll")                                              \
                for (int fp = 0; fp < 4; fp++)                                 \
                    _Pragma("unroll")                                          \
                    for (int hh = 0; hh < 2; hh++) {                           \
                        float* c = acc[fi][fp * 2 + hh];                       \
                        mma16816(c, ah[fi], &bh[fp][2 * hh]);                  \
                        mma16816(c, ah[fi], &bl[fp][2 * hh]);                  \
                        mma16816(c, al[fi], &bh[fp][2 * hh]);                  \
                    }                                                          \
        }                                                                      \
    } while (0)

    CPLOAD(0, 0);
    asm volatile("cp.async.commit_group;" ::: "memory");

    const int nt = K / 32;
    for (int tI = 0; tI < nt; tI++) {
        if (tI + 1 < nt) {
            CPLOAD((tI + 1) * 32, (tI + 1) & 1);
            asm volatile("cp.async.commit_group;" ::: "memory");
            asm volatile("cp.async.wait_group 1;" ::: "memory");
        } else {
            asm volatile("cp.async.wait_group 0;" ::: "memory");
        }
        __syncthreads();
        MMASTEP(tI & 1);
        __syncthreads();
    }

#pragma unroll
    for (int fi = 0; fi < 2; fi++) {
        const int m = m0 + warp_m + fi * 16 + g;
#pragma unroll
        for (int fj = 0; fj < 8; fj++) {
            const int n = n0 + warp_n + fj * 8 + t * 2;
            const float* c = acc[fi][fj];
            const long off0 = (long)bz * sC + (long)m * N + n;
            const long off1 = (long)bz * sC + (long)(m + 8) * N + n;
            if (Cg) {
                float2 o0, o1;
                o0.x = c[0]; o0.y = c[1];
                o1.x = c[2]; o1.y = c[3];
                *(float2*)&Cg[off0] = o0;
                *(float2*)&Cg[off1] = o1;
            }
            if (Chg) {
                __nv_bfloat16 h0, l0, h1, l1;
                __nv_bfloat162 hh, ll;
                bsplit(c[0], h0, l0); bsplit(c[1], h1, l1);
                hh.x = h0; hh.y = h1; *(__nv_bfloat162*)&Chg[off0] = hh;
                ll.x = l0; ll.y = l1; *(__nv_bfloat162*)&Clg[off0] = ll;
                bsplit(c[2], h0, l0); bsplit(c[3], h1, l1);
                hh.x = h0; hh.y = h1; *(__nv_bfloat162*)&Chg[off1] = hh;
                ll.x = l0; ll.y = l1; *(__nv_bfloat162*)&Clg[off1] = ll;
            }
        }
    }
#undef CPLOAD
#undef MMASTEP
}

// --------------------------- reductions ------------------------------------
__device__ __forceinline__ float warpMax(float v) {
#pragma unroll
    for (int o = 16; o; o >>= 1) v = fmaxf(v, __shfl_xor_sync(0xffffffffu, v, o));
    return v;
}
__device__ __forceinline__ float warpSum(float v) {
#pragma unroll
    for (int o = 16; o; o >>= 1) v += __shfl_xor_sync(0xffffffffu, v, o);
    return v;
}

// in-place row softmax; one block per row
__global__ void softmax_kernel(float* __restrict__ d, int ncols)
{
    __shared__ float red[32];
    __shared__ float bcast;
    const long row = blockIdx.x;
    float* p = d + row * (long)ncols;
    const int tid = threadIdx.x, nt = blockDim.x;

    float m = -1e30f;
    for (int i = tid; i < ncols; i += nt) m = fmaxf(m, p[i]);
    m = warpMax(m);
    if ((tid & 31) == 0) red[tid >> 5] = m;
    __syncthreads();
    if (tid < 32) {
        float v = (tid < (nt >> 5)) ? red[tid] : -1e30f;
        v = warpMax(v);
        if (tid == 0) bcast = v;
    }
    __syncthreads();
    m = bcast;

    float s = 0.f;
    for (int i = tid; i < ncols; i += nt) {
        float e = __expf(p[i] - m);
        p[i] = e;
        s += e;
    }
    __syncthreads();
    s = warpSum(s);
    if ((tid & 31) == 0) red[tid >> 5] = s;
    __syncthreads();
    if (tid < 32) {
        float v = (tid < (nt >> 5)) ? red[tid] : 0.f;
        v = warpSum(v);
        if (tid == 0) bcast = v;
    }
    __syncthreads();
    const float inv = 1.f / bcast;
    for (int i = tid; i < ncols; i += nt) p[i] *= inv;
}

// ---------------------- f32 -> bf16 hi/lo split -----------------------------
__global__ void split_f32_kernel(const float* __restrict__ src,
                                 __nv_bfloat16* __restrict__ yh,
                                 __nv_bfloat16* __restrict__ yl)
{
    const int i = (blockIdx.x * blockDim.x + threadIdx.x) * 4;
    float4 v = *(const float4*)&src[i];
    __nv_bfloat16 h0,l0,h1,l1,h2,l2,h3,l3;
    bsplit(v.x,h0,l0); bsplit(v.y,h1,l1); bsplit(v.z,h2,l2); bsplit(v.w,h3,l3);
    __nv_bfloat162 a;
    a.x = h0; a.y = h1; *(__nv_bfloat162*)&yh[i]     = a;
    a.x = h2; a.y = h3; *(__nv_bfloat162*)&yh[i + 2] = a;
    a.x = l0; a.y = l1; *(__nv_bfloat162*)&yl[i]     = a;
    a.x = l2; a.y = l3; *(__nv_bfloat162*)&yl[i + 2] = a;
}

// ================= tensor-core fused CAM (flash style, v2) ==================
#define CST   136
#define CTILE (128 * CST)
#define CAM_SMEM (6 * CTILE * 2)

__global__ __launch_bounds__(256)
void cam_tc_kernel(const float* __restrict__ y1g,
                   const __nv_bfloat16* __restrict__ y1hg,
                   const __nv_bfloat16* __restrict__ y1lg,
                   const float* __restrict__ gptr,
                   float* __restrict__ outg)
{
    extern __shared__ __align__(16) __nv_bfloat16 cs[];
    __nv_bfloat16* Qh = cs;
    __nv_bfloat16* Ql = cs + CTILE;

    const int b  = blockIdx.y;
    const int c0 = blockIdx.x * 128;
    const float* Y          = y1g  + (long)b * CCH * HW;
    const __nv_bfloat16* Yh = y1hg + (long)b * CCH * HW;
    const __nv_bfloat16* Yl = y1lg + (long)b * CCH * HW;

    const int tid = threadIdx.x, wid = tid >> 5, lane = tid & 31;
    const int mi = lane >> 3, ri = lane & 7, g = lane >> 2, t = lane & 3;

    const unsigned sb  = (unsigned)__cvta_generic_to_shared(cs);
    const unsigned bQh = sb;
    const unsigned bQl = sb + CTILE * 2;

    const unsigned aoff = ((wid * 16 + ((mi & 1) << 3) + ri) * CST + ((mi >> 1) << 3)) * 2;
    const unsigned bS = ((((mi >> 1) << 3) + ri) * CST + ((mi & 1) << 3)) * 2;
    const unsigned bT = ((((mi & 1) << 3) + ri) * CST + ((mi >> 1) << 3)) * 2;

#define LOADK(tt, buf)                                                         \
    do {                                                                       \
        const unsigned dh = sb + (2 + (buf) * 2) * CTILE * 2;                  \
        const unsigned dl = dh + CTILE * 2;                                    \
        _Pragma("unroll")                                                      \
        for (int i = 0; i < 8; i++) {                                          \
            int c = tid + 256 * i;                                             \
            int r = c >> 4, col8 = (c & 15) * 8;                               \
            cpa16(dh + (r * CST + col8) * 2, Yh + (long)((tt) * 128 + r) * HW + col8); \
            cpa16(dl + (r * CST + col8) * 2, Yl + (long)((tt) * 128 + r) * HW + col8); \
        }                                                                      \
    } while (0)

    LOADK(0, 0);
    asm volatile("cp.async.commit_group;" ::: "memory");
#pragma unroll
    for (int i = 0; i < 8; i++) {
        int c = tid + 256 * i;
        int r = c >> 4, col8 = (c & 15) * 8;
        *(uint4*)(Qh + r * CST + col8) = *(const uint4*)(Yh + (long)(c0 + r) * HW + col8);
        *(uint4*)(Ql + r * CST + col8) = *(const uint4*)(Yl + (long)(c0 + r) * HW + col8);
    }

    float Sa[16][4], Oa[16][4];
    float m0r = -1e30f, m1r = -1e30f, l0r = 0.f, l1r = 0.f;
#pragma unroll
    for (int j = 0; j < 16; j++) { Oa[j][0]=Oa[j][1]=Oa[j][2]=Oa[j][3]=0.f; }

    for (int tI = 0; tI < 16; tI++) {
        const int buf = tI & 1;
        if (tI < 15) {
            LOADK(tI + 1, buf ^ 1);
            asm volatile("cp.async.commit_group;" ::: "memory");
            asm volatile("cp.async.wait_group 1;" ::: "memory");
        } else {
            asm volatile("cp.async.wait_group 0;" ::: "memory");
        }
        __syncthreads();

        const unsigned bKh = sb + (2 + buf * 2) * CTILE * 2;
        const unsigned bKl = bKh + CTILE * 2;

#pragma unroll
        for (int j = 0; j < 16; j++) { Sa[j][0]=Sa[j][1]=Sa[j][2]=Sa[j][3]=0.f; }
#pragma unroll
        for (int ks = 0; ks < 8; ks++) {
            unsigned ah[4], al[4];
            ldsm4(ah, bQh + aoff + ks * 32);
            ldsm4(al, bQl + aoff + ks * 32);
#pragma unroll
            for (int fp = 0; fp < 8; fp++) {
                unsigned bh[4], bl[4];
                ldsm4(bh, bKh + bS + fp * (16 * CST * 2) + ks * 32);
                ldsm4(bl, bKl + bS + fp * (16 * CST * 2) + ks * 32);
#pragma unroll
                for (int hh = 0; hh < 2; hh++) {
                    float* c = Sa[fp * 2 + hh];
                    mma16816(c, ah, &bh[2 * hh]);
                    mma16816(c, ah, &bl[2 * hh]);
                    mma16816(c, al, &bh[2 * hh]);
                }
            }
        }

        float mx0 = -1e30f, mx1 = -1e30f;
#pragma unroll
        for (int j = 0; j < 16; j++) {
            mx0 = fmaxf(mx0, fmaxf(-Sa[j][0], -Sa[j][1]));
            mx1 = fmaxf(mx1, fmaxf(-Sa[j][2], -Sa[j][3]));
        }
        mx0 = fmaxf(mx0, __shfl_xor_sync(0xffffffffu, mx0, 1));
        mx0 = fmaxf(mx0, __shfl_xor_sync(0xffffffffu, mx0, 2));
        mx1 = fmaxf(mx1, __shfl_xor_sync(0xffffffffu, mx1, 1));
        mx1 = fmaxf(mx1, __shfl_xor_sync(0xffffffffu, mx1, 2));
        const float mn0 = fmaxf(m0r, mx0), mn1 = fmaxf(m1r, mx1);
        const float sc0 = __expf(m0r - mn0), sc1 = __expf(m1r - mn1);
        float rs0 = 0.f, rs1 = 0.f;
#pragma unroll
        for (int j = 0; j < 16; j++) {
            float p0 = __expf(-Sa[j][0] - mn0); Sa[j][0] = p0; rs0 += p0;
            float p1 = __expf(-Sa[j][1] - mn0); Sa[j][1] = p1; rs0 += p1;
            float p2 = __expf(-Sa[j][2] - mn1); Sa[j][2] = p2; rs1 += p2;
            float p3 = __expf(-Sa[j][3] - mn1); Sa[j][3] = p3; rs1 += p3;
        }
        rs0 += __shfl_xor_sync(0xffffffffu, rs0, 1);
        rs0 += __shfl_xor_sync(0xffffffffu, rs0, 2);
        rs1 += __shfl_xor_sync(0xffffffffu, rs1, 1);
        rs1 += __shfl_xor_sync(0xffffffffu, rs1, 2);
        l0r = l0r * sc0 + rs0;  l1r = l1r * sc1 + rs1;
        m0r = mn0;  m1r = mn1;
#pragma unroll
        for (int j = 0; j < 16; j++) {
            Oa[j][0] *= sc0; Oa[j][1] *= sc0;
            Oa[j][2] *= sc1; Oa[j][3] *= sc1;
        }

        // O += P @ V  (2-term: Ph*Vh + Ph*Vl; Pl*Vh dropped, err ~2e-4 after gamma)
#pragma unroll
        for (int kp = 0; kp < 8; kp++) {
            const float* p0 = Sa[2 * kp];
            const float* p1 = Sa[2 * kp + 1];
            unsigned aPh[4];
            aPh[0] = packbf(p0[0], p0[1]);
            aPh[1] = packbf(p0[2], p0[3]);
            aPh[2] = packbf(p1[0], p1[1]);
            aPh[3] = packbf(p1[2], p1[3]);
#pragma unroll
            for (int fp = 0; fp < 8; fp++) {
                unsigned vh[4], vl[4];
                ldsm4t(vh, bKh + bT + kp * (16 * CST * 2) + fp * 32);
                ldsm4t(vl, bKl + bT + kp * (16 * CST * 2) + fp * 32);
#pragma unroll
                for (int hh = 0; hh < 2; hh++) {
                    float* c = Oa[fp * 2 + hh];
                    mma16816(c, aPh, &vh[2 * hh]);
                    mma16816(c, aPh, &vl[2 * hh]);
                }
            }
        }
        __syncthreads();
    }
#undef LOADK

    const float gam = *gptr;
    const float i0 = gam / l0r, i1 = gam / l1r;
    const int r0 = c0 + wid * 16 + g, r1 = r0 + 8;
    float* O = outg + (long)b * CCH * HW;
#pragma unroll
    for (int j = 0; j < 16; j++) {
        const int col = j * 8 + t * 2;
        const long o0 = (long)r0 * HW + col;
        const long o1 = (long)r1 * HW + col;
        float2 y0 = *(const float2*)&Y[o0];
        float2 y1v = *(const float2*)&Y[o1];
        float2 w0, w1;
        w0.x = Oa[j][0] * i0 + y0.x;  w0.y = Oa[j][1] * i0 + y0.y;
        w1.x = Oa[j][2] * i1 + y1v.x; w1.y = Oa[j][3] * i1 + y1v.y;
        *(float2*)&O[o0] = w0;
        *(float2*)&O[o1] = w1;
    }
}

// ------------------------ graph construction -------------------------------
// writes graph as bf16 hi/lo pair (consumed by tbgemm hp)
__global__ void graph_build(const float* __restrict__ ip,
                            const float* __restrict__ adj,
                            __nv_bfloat16* __restrict__ gh,
                            __nv_bfloat16* __restrict__ gl)
{
    __shared__ float reda[4], redb[4];
    const int n = blockIdx.y, v = blockIdx.x, w = threadIdx.x;
    const long base = ((long)n * VV + v) * VV;

    const float sqv = ip[((long)n * VV + v) * VV + v];
    const float sqw = ip[((long)n * VV + w) * VV + w];
    const float e   = ip[base + w];

    float d2   = sqv + sqw - 2.f * e;
    float dist = sqrtf(fmaxf(d2, 1e-12f));
    float sim  = 2.f / (expf(dist) + 1.f);
    float av   = adj[base + w];
    if (w == v) { sim = 0.f; av = 0.f; }

    float s1 = warpSum(fabsf(sim));
    float s2 = warpSum(fabsf(av));
    if ((w & 31) == 0) { reda[w >> 5] = s1; redb[w >> 5] = s2; }
    __syncthreads();
    const float ssum = reda[0] + reda[1] + reda[2] + reda[3];
    const float asum = redb[0] + redb[1] + redb[2] + redb[3];

    float gv = 0.5f * (av / fmaxf(asum, 1e-12f) + sim / fmaxf(ssum, 1e-12f));
    __nv_bfloat16 hh, ll;
    bsplit(gv, hh, ll);
    gh[base + w] = hh;
    gl[base + w] = ll;
}

// ------------------------- batch-norm stats --------------------------------
__global__ void bn_stats(const float* __restrict__ hp,
                         float* __restrict__ mean, float* __restrict__ var,
                         int rows, int C)
{
    __shared__ float shs[8][32];
    __shared__ float shs2[8][32];
    const int lane = threadIdx.x & 31;
    const int ry   = threadIdx.x >> 5;
    const int c    = blockIdx.x * 32 + lane;

    float s = 0.f, s2 = 0.f;
    for (int r = ry; r < rows; r += 8) {
        float v = hp[(long)r * C + c];
        s += v; s2 += v * v;
    }
    shs[ry][lane] = s; shs2[ry][lane] = s2;
    __syncthreads();
    if (ry == 0) {
#pragma unroll
        for (int j = 1; j < 8; j++) { s += shs[j][lane]; s2 += shs2[j][lane]; }
        float mu = s / rows;
        mean[c] = mu;
        var[c]  = s2 / rows - mu * mu;
    }
}

// ------------------- BN apply + LeakyReLU + residual -----------------------
// optional split bf16 output (for the next layer's tbgemm inputs)
__global__ void bn_apply(const float* __restrict__ inp,
                         const float* __restrict__ hp,
                         const float* __restrict__ mean,
                         const float* __restrict__ var,
                         const float* __restrict__ bw,
                         const float* __restrict__ bb,
                         const float* __restrict__ gptr,
                         float* __restrict__ out,
                         __nv_bfloat16* __restrict__ oh,
                         __nv_bfloat16* __restrict__ ol,
                         int total, int C)
{
    const int idx = blockIdx.x * blockDim.x + threadIdx.x;
    if (idx >= total) return;
    const int c = idx & (C - 1);
    const float g = *gptr;
    float vv = (hp[idx] - mean[c]) * rsqrtf(var[c] + 1e-5f) * bw[c] + bb[c];
    float lr = vv > 0.f ? vv : 0.1f * vv;
    float o = inp[idx] + g * lr;
    out[idx] = o;
    if (oh) {
        __nv_bfloat16 hh, ll;
        bsplit(o, hh, ll);
        oh[idx] = hh;
        ol[idx] = ll;
    }
}

// ------------------------------ host side ----------------------------------
static void launch_gemm(int TA, int TB,
                        const float* A, const float* B, float* C,
                        int M, int N, int K,
                        long sA, long sB, long sC, int batch,
                        const float* bias,
                        const float* Res, long sRes,
                        float aH, const float* aD, cudaStream_t st)
{
    dim3 grid(N / 128, M / 128, batch);
    dim3 blk(256);
    if (TA == 0 && TB == 0)
        tgemm_kernel<0, 0><<<grid, blk, TSMEM, st>>>(A, B, C, M, N, K, sA, sB, sC, bias, Res, sRes, aH, aD);
    else if (TA == 1 && TB == 0)
        tgemm_kernel<1, 0><<<grid, blk, TSMEM, st>>>(A, B, C, M, N, K, sA, sB, sC, bias, Res, sRes, aH, aD);
    else
        tgemm_kernel<0, 1><<<grid, blk, TSMEM, st>>>(A, B, C, M, N, K, sA, sB, sC, bias, Res, sRes, aH, aD);
}

extern "C" void kernel_launch(void* const* d_in, const int* in_sizes, int n_in,
                              void* d_out, int out_size)
{
    const float* x     = (const float*)d_in[0];
    const float* vfeat = (const float*)d_in[1];
    const float* adj   = (const float*)d_in[2];
    const float* Wq    = (const float*)d_in[3];
    const float* bq    = (const float*)d_in[4];
    const float* Wk    = (const float*)d_in[5];
    const float* bk    = (const float*)d_in[6];
    const float* Wv    = (const float*)d_in[7];
    const float* bv    = (const float*)d_in[8];
    const float* gpam  = (const float*)d_in[9];
    const float* gcam  = (const float*)d_in[10];
    const float* Wg    = (const float*)d_in[11];
    const float* bnw   = (const float*)d_in[12];
    const float* bnb   = (const float*)d_in[13];
    const float* gg    = (const float*)d_in[14];
    float* out = (float*)d_out;

    float *q, *k, *v, *att1, *y1, *ip, *hp, *gbuf, *mean, *var;
    __nv_bfloat16 *y1h, *y1l, *vfh, *vfl, *gbh, *gbl, *wgh, *wgl, *hh_, *hl_, *gph, *gpl;
    cudaGetSymbolAddress((void**)&q,    d_q);
    cudaGetSymbolAddress((void**)&k,    d_k);
    cudaGetSymbolAddress((void**)&v,    d_v);
    cudaGetSymbolAddress((void**)&att1, d_att1);
    cudaGetSymbolAddress((void**)&y1,   d_y1);
    cudaGetSymbolAddress((void**)&y1h,  d_y1h);
    cudaGetSymbolAddress((void**)&y1l,  d_y1l);
    cudaGetSymbolAddress((void**)&ip,   d_ip);
    cudaGetSymbolAddress((void**)&hp,   d_hp);
    cudaGetSymbolAddress((void**)&gbuf, d_gbuf);
    cudaGetSymbolAddress((void**)&mean, d_mean);
    cudaGetSymbolAddress((void**)&var,  d_var);
    cudaGetSymbolAddress((void**)&vfh,  d_vfh);
    cudaGetSymbolAddress((void**)&vfl,  d_vfl);
    cudaGetSymbolAddress((void**)&gbh,  d_gbh);
    cudaGetSymbolAddress((void**)&gbl,  d_gbl);
    cudaGetSymbolAddress((void**)&wgh,  d_wgh);
    cudaGetSymbolAddress((void**)&wgl,  d_wgl);
    cudaGetSymbolAddress((void**)&hh_,  d_hh);
    cudaGetSymbolAddress((void**)&hl_,  d_hl);
    cudaGetSymbolAddress((void**)&gph,  d_gph);
    cudaGetSymbolAddress((void**)&gpl,  d_gpl);

    static int inited = 0;
    if (!inited) {
        cudaFuncSetAttribute(tgemm_kernel<0, 0>,
                             cudaFuncAttributeMaxDynamicSharedMemorySize, TSMEM);
        cudaFuncSetAttribute(tgemm_kernel<1, 0>,
                             cudaFuncAttributeMaxDynamicSharedMemorySize, TSMEM);
        cudaFuncSetAttribute(tgemm_kernel<0, 1>,
                             cudaFuncAttributeMaxDynamicSharedMemorySize, TSMEM);
        cudaFuncSetAttribute(tbgemm_kernel<0, 1>,
                             cudaFuncAttributeMaxDynamicSharedMemorySize, TSMEM);
        cudaFuncSetAttribute(tbgemm_kernel<0, 0>,
                             cudaFuncAttributeMaxDynamicSharedMemorySize, TSMEM);
        cudaFuncSetAttribute(cam_tc_kernel,
                             cudaFuncAttributeMaxDynamicSharedMemorySize, CAM_SMEM);
        inited = 1;
    }
    static cudaStream_t s1 = [](){ cudaStream_t s;
        cudaStreamCreateWithFlags(&s, cudaStreamNonBlocking); return s; }();
    static cudaStream_t s2 = [](){ cudaStream_t s;
        cudaStreamCreateWithFlags(&s, cudaStreamNonBlocking); return s; }();
    static cudaEvent_t evF = [](){ cudaEvent_t e;
        cudaEventCreateWithFlags(&e, cudaEventDisableTiming); return e; }();
    static cudaEvent_t evK = [](){ cudaEvent_t e;
        cudaEventCreateWithFlags(&e, cudaEventDisableTiming); return e; }();
    static cudaEvent_t evV = [](){ cudaEvent_t e;
        cudaEventCreateWithFlags(&e, cudaEventDisableTiming); return e; }();
    static cudaEvent_t evJ = [](){ cudaEvent_t e;
        cudaEventCreateWithFlags(&e, cudaEventDisableTiming); return e; }();

    const long CHW = (long)CCH * HW;          // 262144
    const long QHW = (long)C8 * HW;           // 32768
    const long GST = (long)VV * CCH;          // 262144
    cudaStream_t s0 = 0;

    // ---- fork ----
    cudaEventRecord(evF, s0);
    cudaStreamWaitEvent(s1, evF, 0);
    cudaStreamWaitEvent(s2, evF, 0);

    // ---------------- PAM ----------------
    launch_gemm(0, 0, Wq, x, q, C8,  HW, CCH, 0, CHW, QHW, BSZ, bq, nullptr, 0, 1.f, nullptr, s0);
    launch_gemm(0, 0, Wk, x, k, C8,  HW, CCH, 0, CHW, QHW, BSZ, bk, nullptr, 0, 1.f, nullptr, s1);
    cudaEventRecord(evK, s1);
    launch_gemm(0, 0, Wv, x, v, CCH, HW, CCH, 0, CHW, CHW, BSZ, bv, nullptr, 0, 1.f, nullptr, s1);
    cudaEventRecord(evV, s1);

    cudaStreamWaitEvent(s0, evK, 0);
    launch_gemm(1, 0, q, k, att1, HW, HW, C8, QHW, QHW, (long)HW * HW, BSZ,
                nullptr, nullptr, 0, 1.f, nullptr, s0);
    softmax_kernel<<<BSZ * HW, 128, 0, s0>>>(att1, HW);
    cudaStreamWaitEvent(s0, evV, 0);
    launch_gemm(0, 1, v, att1, y1, CCH, HW, HW, CHW, (long)HW * HW, CHW, BSZ,
                nullptr, x, CHW, 0.f, gpam, s0);

    // ---------------- CAM (s0) ----------------
    split_f32_kernel<<<(BSZ * CCH * HW) / 1024, 256, 0, s0>>>(y1, y1h, y1l);
    {
        dim3 grid(CCH / 128, BSZ);
        cam_tc_kernel<<<grid, 256, CAM_SMEM, s0>>>(y1, y1h, y1l, gcam, out);
    }

    // ------------- Graph layers (s2, pre-split bf16 GEMMs) -------------
    split_f32_kernel<<<(NV * VV * CCH) / 1024, 256, 0, s2>>>(vfeat, vfh, vfl);
    split_f32_kernel<<<(GNUM * CCH * CCH) / 1024, 256, 0, s2>>>(Wg, wgh, wgl);

    const float* inp = vfeat;
    for (int i = 0; i < GNUM; i++) {
        const __nv_bfloat16* ih = (i == 0) ? vfh : gbh;
        const __nv_bfloat16* il = (i == 0) ? vfl : gbl;
        float* outg = (i == GNUM - 1) ? (out + (long)BSZ * CCH * HW) : gbuf;

        // h = inp @ Wg[i]^T   (split output only; consumed by hp GEMM)
        {
            dim3 grid(CCH / 128, (NV * VV) / 128, 1);
            tbgemm_kernel<0, 1><<<grid, 256, TSMEM, s2>>>(
                ih, il, wgh + (long)i * CCH * CCH, wgl + (long)i * CCH * CCH,
                nullptr, hh_, hl_, NV * VV, CCH, CCH, 0, 0, 0);
        }
        // ip[n] = inp[n] @ inp[n]^T
        {
            dim3 grid(1, 1, NV);
            tbgemm_kernel<0, 1><<<grid, 256, TSMEM, s2>>>(
                ih, il, ih, il, ip, nullptr, nullptr,
                VV, VV, CCH, GST, GST, (long)VV * VV);
        }
        graph_build<<<dim3(VV, NV), VV, 0, s2>>>(ip, adj, gph, gpl);
        // hp[n] = graph[n] @ h[n]
        {
            dim3 grid(CCH / 128, 1, NV);
            tbgemm_kernel<0, 0><<<grid, 256, TSMEM, s2>>>(
                gph, gpl, hh_, hl_, hp, nullptr, nullptr,
                VV, CCH, VV, (long)VV * VV, GST, GST);
        }
        bn_stats<<<CCH / 32, 256, 0, s2>>>(hp, mean, var, NV * VV, CCH);
        bn_apply<<<(NV * VV * CCH + 255) / 256, 256, 0, s2>>>(
            inp, hp, mean, var, bnw + (long)i * CCH, bnb + (long)i * CCH,
            gg + i, outg,
            (i == GNUM - 1) ? nullptr : gbh,
            (i == GNUM - 1) ? nullptr : gbl,
            NV * VV * CCH, CCH);
        inp = outg;
    }

    // ---- join ----
    cudaEventRecord(evJ, s2);
    cudaStreamWaitEvent(s0, evJ, 0);
}

// round 13
// speedup vs baseline: 1.4307x; 1.0855x over previous
#include <cuda_runtime.h>
#include <cuda_bf16.h>
#include <math.h>

// ---------------------------------------------------------------------------
// Problem constants
// ---------------------------------------------------------------------------
#define BSZ   16
#define CCH   2048
#define HW    128
#define C8    256
#define NV    16
#define VV    128
#define GNUM  2

// ------------------------- scratch (device globals) ------------------------
__device__ __align__(256) float d_att1[BSZ * HW * HW];
__device__ __align__(256) float d_y1  [BSZ * CCH * HW];
__device__ __align__(256) __nv_bfloat16 d_y1h[BSZ * CCH * HW];
__device__ __align__(256) __nv_bfloat16 d_y1l[BSZ * CCH * HW];
__device__ __align__(256) float d_ip  [NV * VV * VV];
__device__ __align__(256) float d_hp  [NV * VV * CCH];
__device__ __align__(256) float d_gbuf[NV * VV * CCH];
__device__ __align__(256) float d_mean[CCH];
__device__ __align__(256) float d_var [CCH];
// bf16 hi/lo operand arrays
__device__ __align__(256) __nv_bfloat16 d_xh [BSZ * CCH * HW];
__device__ __align__(256) __nv_bfloat16 d_xl [BSZ * CCH * HW];
__device__ __align__(256) __nv_bfloat16 d_wqh[C8 * CCH];
__device__ __align__(256) __nv_bfloat16 d_wql[C8 * CCH];
__device__ __align__(256) __nv_bfloat16 d_wkh[C8 * CCH];
__device__ __align__(256) __nv_bfloat16 d_wkl[C8 * CCH];
__device__ __align__(256) __nv_bfloat16 d_wvh[CCH * CCH];
__device__ __align__(256) __nv_bfloat16 d_wvl[CCH * CCH];
__device__ __align__(256) __nv_bfloat16 d_qh [BSZ * C8 * HW];
__device__ __align__(256) __nv_bfloat16 d_ql [BSZ * C8 * HW];
__device__ __align__(256) __nv_bfloat16 d_kh [BSZ * C8 * HW];
__device__ __align__(256) __nv_bfloat16 d_kl [BSZ * C8 * HW];
__device__ __align__(256) __nv_bfloat16 d_vh [BSZ * CCH * HW];
__device__ __align__(256) __nv_bfloat16 d_vl [BSZ * CCH * HW];
__device__ __align__(256) __nv_bfloat16 d_a1h[BSZ * HW * HW];
__device__ __align__(256) __nv_bfloat16 d_a1l[BSZ * HW * HW];
__device__ __align__(256) __nv_bfloat16 d_vfh[NV * VV * CCH];
__device__ __align__(256) __nv_bfloat16 d_vfl[NV * VV * CCH];
__device__ __align__(256) __nv_bfloat16 d_gbh[NV * VV * CCH];
__device__ __align__(256) __nv_bfloat16 d_gbl[NV * VV * CCH];
__device__ __align__(256) __nv_bfloat16 d_wgh[GNUM * CCH * CCH];
__device__ __align__(256) __nv_bfloat16 d_wgl[GNUM * CCH * CCH];
__device__ __align__(256) __nv_bfloat16 d_hh [NV * VV * CCH];
__device__ __align__(256) __nv_bfloat16 d_hl [NV * VV * CCH];
__device__ __align__(256) __nv_bfloat16 d_gph[NV * VV * VV];
__device__ __align__(256) __nv_bfloat16 d_gpl[NV * VV * VV];

// ---------------------- shared mma/ldsm/split helpers -----------------------
__device__ __forceinline__ void ldsm4(unsigned* r, unsigned addr) {
    asm volatile("ldmatrix.sync.aligned.m8n8.x4.shared.b16 {%0,%1,%2,%3}, [%4];"
        : "=r"(r[0]), "=r"(r[1]), "=r"(r[2]), "=r"(r[3]) : "r"(addr));
}
__device__ __forceinline__ void ldsm4t(unsigned* r, unsigned addr) {
    asm volatile("ldmatrix.sync.aligned.m8n8.x4.trans.shared.b16 {%0,%1,%2,%3}, [%4];"
        : "=r"(r[0]), "=r"(r[1]), "=r"(r[2]), "=r"(r[3]) : "r"(addr));
}
__device__ __forceinline__ void mma16816(float* c, const unsigned* a, const unsigned* b) {
    asm volatile("mma.sync.aligned.m16n8k16.row.col.f32.bf16.bf16.f32 "
        "{%0,%1,%2,%3}, {%4,%5,%6,%7}, {%8,%9}, {%0,%1,%2,%3};"
        : "+f"(c[0]), "+f"(c[1]), "+f"(c[2]), "+f"(c[3])
        : "r"(a[0]), "r"(a[1]), "r"(a[2]), "r"(a[3]), "r"(b[0]), "r"(b[1]));
}
__device__ __forceinline__ void bsplit(float x, __nv_bfloat16& h, __nv_bfloat16& l) {
    h = __float2bfloat16(x);
    l = __float2bfloat16(x - __bfloat162float(h));
}
__device__ __forceinline__ unsigned packbf(float a, float b) {
    __nv_bfloat162 p; p.x = __float2bfloat16(a); p.y = __float2bfloat16(b);
    return *(unsigned*)&p;
}
__device__ __forceinline__ void cpa16(unsigned s, const void* g) {
    asm volatile("cp.async.ca.shared.global [%0], [%1], 16;" :: "r"(s), "l"(g));
}

#define TST   40
#define TS2   136
#define TTILE (128 * TST)
#define TSMEM (2 * 4 * TTILE * 2)

// ================= pre-split bf16-input GEMM (universal) ====================
// Inputs split hi/lo in gmem; cp.async double-buffered; 2 CTA/SM.
// Epilogue: alpha*acc + bias[m] + Res; writes f32 (Cg) and/or split (Chg/Clg).
template<int TA, int TB>
__global__ __launch_bounds__(256, 2)
void tbgemm_kernel(const __nv_bfloat16* __restrict__ Ahg,
                   const __nv_bfloat16* __restrict__ Alg,
                   const __nv_bfloat16* __restrict__ Bhg,
                   const __nv_bfloat16* __restrict__ Blg,
                   float* __restrict__ Cg,
                   __nv_bfloat16* __restrict__ Chg,
                   __nv_bfloat16* __restrict__ Clg,
                   int M, int N, int K,
                   long sA, long sB, long sC,
                   const float* __restrict__ bias,
                   const float* __restrict__ Res, long sRes,
                   float alphaH, const float* __restrict__ alphaD)
{
    extern __shared__ __align__(16) __nv_bfloat16 ts[];

    const int bz = blockIdx.z;
    const __nv_bfloat16* Ah = Ahg + (long)bz * sA;
    const __nv_bfloat16* Al = Alg + (long)bz * sA;
    const __nv_bfloat16* Bh = Bhg + (long)bz * sB;
    const __nv_bfloat16* Bl = Blg + (long)bz * sB;

    const int m0 = blockIdx.y * 128;
    const int n0 = blockIdx.x * 128;
    const int tid  = threadIdx.x;
    const int wid  = tid >> 5;
    const int lane = tid & 31;
    const int warp_m = (wid >> 1) * 32;
    const int warp_n = (wid & 1) * 64;
    const int mi = lane >> 3, ri = lane & 7;
    const int g  = lane >> 2, t  = lane & 3;

    const unsigned sbase = (unsigned)__cvta_generic_to_shared(ts);

    unsigned aoff[2], boff[4];
#pragma unroll
    for (int fi = 0; fi < 2; fi++) {
        if (TA == 0)
            aoff[fi] = ((warp_m + fi * 16 + ((mi & 1) << 3) + ri) * TST + ((mi >> 1) << 3)) * 2;
        else
            aoff[fi] = ((((mi >> 1) << 3) + ri) * TS2 + warp_m + fi * 16 + ((mi & 1) << 3)) * 2;
    }
#pragma unroll
    for (int fp = 0; fp < 4; fp++) {
        if (TB == 1)
            boff[fp] = ((warp_n + fp * 16 + ((mi >> 1) << 3) + ri) * TST + ((mi & 1) << 3)) * 2;
        else
            boff[fp] = ((((mi & 1) << 3) + ri) * TS2 + warp_n + fp * 16 + ((mi >> 1) << 3)) * 2;
    }
    const unsigned akk = (TA == 0) ? 32u : (unsigned)(16 * TS2 * 2);
    const unsigned bkk = (TB == 1) ? 32u : (unsigned)(16 * TS2 * 2);

    float acc[2][8][4];
#pragma unroll
    for (int i = 0; i < 2; i++)
#pragma unroll
        for (int j = 0; j < 8; j++)
#pragma unroll
            for (int q = 0; q < 4; q++) acc[i][j][q] = 0.f;

#define CPLOAD(k0, bf)                                                         \
    do {                                                                       \
        const unsigned dAh = sbase + ((bf) * 4 + 0) * TTILE * 2;               \
        const unsigned dAl = sbase + ((bf) * 4 + 1) * TTILE * 2;               \
        const unsigned dBh = sbase + ((bf) * 4 + 2) * TTILE * 2;               \
        const unsigned dBl = sbase + ((bf) * 4 + 3) * TTILE * 2;               \
        if (TA == 0) {                                                         \
            _Pragma("unroll")                                                  \
            for (int i = 0; i < 2; i++) {                                      \
                int idx = tid + 256 * i; int r = idx >> 2, c8 = (idx & 3) * 8; \
                long go = (long)(m0 + r) * K + (k0) + c8;                      \
                cpa16(dAh + (r * TST + c8) * 2, Ah + go);                      \
                cpa16(dAl + (r * TST + c8) * 2, Al + go);                      \
            }                                                                  \
        } else {                                                               \
            _Pragma("unroll")                                                  \
            for (int i = 0; i < 2; i++) {                                      \
                int idx = tid + 256 * i; int r = idx >> 4, c8 = (idx & 15) * 8;\
                long go = (long)((k0) + r) * M + m0 + c8;                      \
                cpa16(dAh + (r * TS2 + c8) * 2, Ah + go);                      \
                cpa16(dAl + (r * TS2 + c8) * 2, Al + go);                      \
            }                                                                  \
        }                                                                      \
        if (TB == 1) {                                                         \
            _Pragma("unroll")                                                  \
            for (int i = 0; i < 2; i++) {                                      \
                int idx = tid + 256 * i; int r = idx >> 2, c8 = (idx & 3) * 8; \
                long go = (long)(n0 + r) * K + (k0) + c8;                      \
                cpa16(dBh + (r * TST + c8) * 2, Bh + go);                      \
                cpa16(dBl + (r * TST + c8) * 2, Bl + go);                      \
            }                                                                  \
        } else {                                                               \
            _Pragma("unroll")                                                  \
            for (int i = 0; i < 2; i++) {                                      \
                int idx = tid + 256 * i; int r = idx >> 4, c8 = (idx & 15) * 8;\
                long go = (long)((k0) + r) * N + n0 + c8;                      \
                cpa16(dBh + (r * TS2 + c8) * 2, Bh + go);                      \
                cpa16(dBl + (r * TS2 + c8) * 2, Bl + go);                      \
            }                                                                  \
        }                                                                      \
    } while (0)

#define MMASTEP(bf)                                                            \
    do {                                                                       \
        const unsigned bAh = sbase + ((bf) * 4 + 0) * TTILE * 2;               \
        const unsigned bAl = sbase + ((bf) * 4 + 1) * TTILE * 2;               \
        const unsigned bBh = sbase + ((bf) * 4 + 2) * TTILE * 2;               \
        const unsigned bBl = sbase + ((bf) * 4 + 3) * TTILE * 2;               \
        _Pragma("unroll")                                                      \
        for (int kk = 0; kk < 2; kk++) {                                       \
            unsigned ah[2][4], al[2][4], bh[4][4], bl[4][4];                   \
            _Pragma("unroll")                                                  \
            for (int fi = 0; fi < 2; fi++) {                                   \
                if (TA == 0) {                                                 \
                    ldsm4(ah[fi], bAh + aoff[fi] + kk * akk);                  \
                    ldsm4(al[fi], bAl + aoff[fi] + kk * akk);                  \
                } else {                                                       \
                    ldsm4t(ah[fi], bAh + aoff[fi] + kk * akk);                 \
                    ldsm4t(al[fi], bAl + aoff[fi] + kk * akk);                 \
                }                                                              \
            }                                                                  \
            _Pragma("unroll")                                                  \
            for (int fp = 0; fp < 4; fp++) {                                   \
                if (TB == 1) {                                                 \
                    ldsm4(bh[fp], bBh + boff[fp] + kk * bkk);                  \
                    ldsm4(bl[fp], bBl + boff[fp] + kk * bkk);                  \
                } else {                                                       \
                    ldsm4t(bh[fp], bBh + boff[fp] + kk * bkk);                 \
                    ldsm4t(bl[fp], bBl + boff[fp] + kk * bkk);                 \
                }                                                              \
            }                                                                  \
            _Pragma("unroll")                                                  \
            for (int fi = 0; fi < 2; fi++)                                     \
                _Pragma("unroll")                                              \
                for (int fp = 0; fp < 4; fp++)                                 \
                    _Pragma("unroll")                                          \
                    for (int hh = 0; hh < 2; hh++) {                           \
                        float* c = acc[fi][fp * 2 + hh];                       \
                        mma16816(c, ah[fi], &bh[fp][2 * hh]);                  \
                        mma16816(c, ah[fi], &bl[fp][2 * hh]);                  \
                        mma16816(c, al[fi], &bh[fp][2 * hh]);                  \
                    }                                                          \
        }                                                                      \
    } while (0)

    CPLOAD(0, 0);
    asm volatile("cp.async.commit_group;" ::: "memory");

    const int nt = K / 32;
    for (int tI = 0; tI < nt; tI++) {
        if (tI + 1 < nt) {
            CPLOAD((tI + 1) * 32, (tI + 1) & 1);
            asm volatile("cp.async.commit_group;" ::: "memory");
            asm volatile("cp.async.wait_group 1;" ::: "memory");
        } else {
            asm volatile("cp.async.wait_group 0;" ::: "memory");
        }
        __syncthreads();
        MMASTEP(tI & 1);
        __syncthreads();
    }

    const float alpha = alphaD ? *alphaD : alphaH;
#pragma unroll
    for (int fi = 0; fi < 2; fi++) {
        const int m = m0 + warp_m + fi * 16 + g;
        const float bi0 = bias ? __ldg(&bias[m])     : 0.f;
        const float bi1 = bias ? __ldg(&bias[m + 8]) : 0.f;
#pragma unroll
        for (int fj = 0; fj < 8; fj++) {
            const int n = n0 + warp_n + fj * 8 + t * 2;
            const float* c = acc[fi][fj];
            const long off0 = (long)bz * sC + (long)m * N + n;
            const long off1 = (long)bz * sC + (long)(m + 8) * N + n;
            float v0 = alpha * c[0] + bi0, v1 = alpha * c[1] + bi0;
            float v2 = alpha * c[2] + bi1, v3 = alpha * c[3] + bi1;
            if (Res) {
                const long ro0 = (long)bz * sRes + (long)m * N + n;
                const long ro1 = (long)bz * sRes + (long)(m + 8) * N + n;
                float2 r0 = *(const float2*)&Res[ro0];
                float2 r1 = *(const float2*)&Res[ro1];
                v0 += r0.x; v1 += r0.y; v2 += r1.x; v3 += r1.y;
            }
            if (Cg) {
                float2 o0, o1;
                o0.x = v0; o0.y = v1; o1.x = v2; o1.y = v3;
                *(float2*)&Cg[off0] = o0;
                *(float2*)&Cg[off1] = o1;
            }
            if (Chg) {
                __nv_bfloat16 h0, l0, h1, l1;
                __nv_bfloat162 hh, ll;
                bsplit(v0, h0, l0); bsplit(v1, h1, l1);
                hh.x = h0; hh.y = h1; *(__nv_bfloat162*)&Chg[off0] = hh;
                ll.x = l0; ll.y = l1; *(__nv_bfloat162*)&Clg[off0] = ll;
                bsplit(v2, h0, l0); bsplit(v3, h1, l1);
                hh.x = h0; hh.y = h1; *(__nv_bfloat162*)&Chg[off1] = hh;
                ll.x = l0; ll.y = l1; *(__nv_bfloat162*)&Clg[off1] = ll;
            }
        }
    }
#undef CPLOAD
#undef MMASTEP
}

// --------------------------- reductions ------------------------------------
__device__ __forceinline__ float warpMax(float v) {
#pragma unroll
    for (int o = 16; o; o >>= 1) v = fmaxf(v, __shfl_xor_sync(0xffffffffu, v, o));
    return v;
}
__device__ __forceinline__ float warpSum(float v) {
#pragma unroll
    for (int o = 16; o; o >>= 1) v += __shfl_xor_sync(0xffffffffu, v, o);
    return v;
}

// in-place row softmax; optional bf16 hi/lo outputs
__global__ void softmax_kernel(float* __restrict__ d,
                               __nv_bfloat16* __restrict__ dh,
                               __nv_bfloat16* __restrict__ dl,
                               int ncols)
{
    __shared__ float red[32];
    __shared__ float bcast;
    const long row = blockIdx.x;
    float* p = d + row * (long)ncols;
    const int tid = threadIdx.x, nt = blockDim.x;

    float m = -1e30f;
    for (int i = tid; i < ncols; i += nt) m = fmaxf(m, p[i]);
    m = warpMax(m);
    if ((tid & 31) == 0) red[tid >> 5] = m;
    __syncthreads();
    if (tid < 32) {
        float v = (tid < (nt >> 5)) ? red[tid] : -1e30f;
        v = warpMax(v);
        if (tid == 0) bcast = v;
    }
    __syncthreads();
    m = bcast;

    float s = 0.f;
    for (int i = tid; i < ncols; i += nt) {
        float e = __expf(p[i] - m);
        p[i] = e;
        s += e;
    }
    __syncthreads();
    s = warpSum(s);
    if ((tid & 31) == 0) red[tid >> 5] = s;
    __syncthreads();
    if (tid < 32) {
        float v = (tid < (nt >> 5)) ? red[tid] : 0.f;
        v = warpSum(v);
        if (tid == 0) bcast = v;
    }
    __syncthreads();
    const float inv = 1.f / bcast;
    for (int i = tid; i < ncols; i += nt) {
        float pv = p[i] * inv;
        p[i] = pv;
        if (dh) {
            __nv_bfloat16 hh, ll;
            bsplit(pv, hh, ll);
            dh[row * (long)ncols + i] = hh;
            dl[row * (long)ncols + i] = ll;
        }
    }
}

// ---------------------- f32 -> bf16 hi/lo split -----------------------------
__global__ void split_f32_kernel(const float* __restrict__ src,
                                 __nv_bfloat16* __restrict__ yh,
                                 __nv_bfloat16* __restrict__ yl)
{
    const int i = (blockIdx.x * blockDim.x + threadIdx.x) * 4;
    float4 v = *(const float4*)&src[i];
    __nv_bfloat16 h0,l0,h1,l1,h2,l2,h3,l3;
    bsplit(v.x,h0,l0); bsplit(v.y,h1,l1); bsplit(v.z,h2,l2); bsplit(v.w,h3,l3);
    __nv_bfloat162 a;
    a.x = h0; a.y = h1; *(__nv_bfloat162*)&yh[i]     = a;
    a.x = h2; a.y = h3; *(__nv_bfloat162*)&yh[i + 2] = a;
    a.x = l0; a.y = l1; *(__nv_bfloat162*)&yl[i]     = a;
    a.x = l2; a.y = l3; *(__nv_bfloat162*)&yl[i + 2] = a;
}

// ================= tensor-core fused CAM (flash style, v2) ==================
#define CST   136
#define CTILE (128 * CST)
#define CAM_SMEM (6 * CTILE * 2)

__global__ __launch_bounds__(256)
void cam_tc_kernel(const float* __restrict__ y1g,
                   const __nv_bfloat16* __restrict__ y1hg,
                   const __nv_bfloat16* __restrict__ y1lg,
                   const float* __restrict__ gptr,
                   float* __restrict__ outg)
{
    extern __shared__ __align__(16) __nv_bfloat16 cs[];
    __nv_bfloat16* Qh = cs;
    __nv_bfloat16* Ql = cs + CTILE;

    const int b  = blockIdx.y;
    const int c0 = blockIdx.x * 128;
    const float* Y          = y1g  + (long)b * CCH * HW;
    const __nv_bfloat16* Yh = y1hg + (long)b * CCH * HW;
    const __nv_bfloat16* Yl = y1lg + (long)b * CCH * HW;

    const int tid = threadIdx.x, wid = tid >> 5, lane = tid & 31;
    const int mi = lane >> 3, ri = lane & 7, g = lane >> 2, t = lane & 3;

    const unsigned sb  = (unsigned)__cvta_generic_to_shared(cs);
    const unsigned bQh = sb;
    const unsigned bQl = sb + CTILE * 2;

    const unsigned aoff = ((wid * 16 + ((mi & 1) << 3) + ri) * CST + ((mi >> 1) << 3)) * 2;
    const unsigned bS = ((((mi >> 1) << 3) + ri) * CST + ((mi & 1) << 3)) * 2;
    const unsigned bT = ((((mi & 1) << 3) + ri) * CST + ((mi >> 1) << 3)) * 2;

#define LOADK(tt, buf)                                                         \
    do {                                                                       \
        const unsigned dh = sb + (2 + (buf) * 2) * CTILE * 2;                  \
        const unsigned dl = dh + CTILE * 2;                                    \
        _Pragma("unroll")                                                      \
        for (int i = 0; i < 8; i++) {                                          \
            int c = tid + 256 * i;                                             \
            int r = c >> 4, col8 = (c & 15) * 8;                               \
            cpa16(dh + (r * CST + col8) * 2, Yh + (long)((tt) * 128 + r) * HW + col8); \
            cpa16(dl + (r * CST + col8) * 2, Yl + (long)((tt) * 128 + r) * HW + col8); \
        }                                                                      \
    } while (0)

    LOADK(0, 0);
    asm volatile("cp.async.commit_group;" ::: "memory");
#pragma unroll
    for (int i = 0; i < 8; i++) {
        int c = tid + 256 * i;
        int r = c >> 4, col8 = (c & 15) * 8;
        *(uint4*)(Qh + r * CST + col8) = *(const uint4*)(Yh + (long)(c0 + r) * HW + col8);
        *(uint4*)(Ql + r * CST + col8) = *(const uint4*)(Yl + (long)(c0 + r) * HW + col8);
    }

    float Sa[16][4], Oa[16][4];
    float m0r = -1e30f, m1r = -1e30f, l0r = 0.f, l1r = 0.f;
#pragma unroll
    for (int j = 0; j < 16; j++) { Oa[j][0]=Oa[j][1]=Oa[j][2]=Oa[j][3]=0.f; }

    for (int tI = 0; tI < 16; tI++) {
        const int buf = tI & 1;
        if (tI < 15) {
            LOADK(tI + 1, buf ^ 1);
            asm volatile("cp.async.commit_group;" ::: "memory");
            asm volatile("cp.async.wait_group 1;" ::: "memory");
        } else {
            asm volatile("cp.async.wait_group 0;" ::: "memory");
        }
        __syncthreads();

        const unsigned bKh = sb + (2 + buf * 2) * CTILE * 2;
        const unsigned bKl = bKh + CTILE * 2;

#pragma unroll
        for (int j = 0; j < 16; j++) { Sa[j][0]=Sa[j][1]=Sa[j][2]=Sa[j][3]=0.f; }
#pragma unroll
        for (int ks = 0; ks < 8; ks++) {
            unsigned ah[4], al[4];
            ldsm4(ah, bQh + aoff + ks * 32);
            ldsm4(al, bQl + aoff + ks * 32);
#pragma unroll
            for (int fp = 0; fp < 8; fp++) {
                unsigned bh[4], bl[4];
                ldsm4(bh, bKh + bS + fp * (16 * CST * 2) + ks * 32);
                ldsm4(bl, bKl + bS + fp * (16 * CST * 2) + ks * 32);
#pragma unroll
                for (int hh = 0; hh < 2; hh++) {
                    float* c = Sa[fp * 2 + hh];
                    mma16816(c, ah, &bh[2 * hh]);
                    mma16816(c, ah, &bl[2 * hh]);
                    mma16816(c, al, &bh[2 * hh]);
                }
            }
        }

        float mx0 = -1e30f, mx1 = -1e30f;
#pragma unroll
        for (int j = 0; j < 16; j++) {
            mx0 = fmaxf(mx0, fmaxf(-Sa[j][0], -Sa[j][1]));
            mx1 = fmaxf(mx1, fmaxf(-Sa[j][2], -Sa[j][3]));
        }
        mx0 = fmaxf(mx0, __shfl_xor_sync(0xffffffffu, mx0, 1));
        mx0 = fmaxf(mx0, __shfl_xor_sync(0xffffffffu, mx0, 2));
        mx1 = fmaxf(mx1, __shfl_xor_sync(0xffffffffu, mx1, 1));
        mx1 = fmaxf(mx1, __shfl_xor_sync(0xffffffffu, mx1, 2));
        const float mn0 = fmaxf(m0r, mx0), mn1 = fmaxf(m1r, mx1);
        const float sc0 = __expf(m0r - mn0), sc1 = __expf(m1r - mn1);
        float rs0 = 0.f, rs1 = 0.f;
#pragma unroll
        for (int j = 0; j < 16; j++) {
            float p0 = __expf(-Sa[j][0] - mn0); Sa[j][0] = p0; rs0 += p0;
            float p1 = __expf(-Sa[j][1] - mn0); Sa[j][1] = p1; rs0 += p1;
            float p2 = __expf(-Sa[j][2] - mn1); Sa[j][2] = p2; rs1 += p2;
            float p3 = __expf(-Sa[j][3] - mn1); Sa[j][3] = p3; rs1 += p3;
        }
        rs0 += __shfl_xor_sync(0xffffffffu, rs0, 1);
        rs0 += __shfl_xor_sync(0xffffffffu, rs0, 2);
        rs1 += __shfl_xor_sync(0xffffffffu, rs1, 1);
        rs1 += __shfl_xor_sync(0xffffffffu, rs1, 2);
        l0r = l0r * sc0 + rs0;  l1r = l1r * sc1 + rs1;
        m0r = mn0;  m1r = mn1;
#pragma unroll
        for (int j = 0; j < 16; j++) {
            Oa[j][0] *= sc0; Oa[j][1] *= sc0;
            Oa[j][2] *= sc1; Oa[j][3] *= sc1;
        }

#pragma unroll
        for (int kp = 0; kp < 8; kp++) {
            const float* p0 = Sa[2 * kp];
            const float* p1 = Sa[2 * kp + 1];
            unsigned aPh[4];
            aPh[0] = packbf(p0[0], p0[1]);
            aPh[1] = packbf(p0[2], p0[3]);
            aPh[2] = packbf(p1[0], p1[1]);
            aPh[3] = packbf(p1[2], p1[3]);
#pragma unroll
            for (int fp = 0; fp < 8; fp++) {
                unsigned vh[4], vl[4];
                ldsm4t(vh, bKh + bT + kp * (16 * CST * 2) + fp * 32);
                ldsm4t(vl, bKl + bT + kp * (16 * CST * 2) + fp * 32);
#pragma unroll
                for (int hh = 0; hh < 2; hh++) {
                    float* c = Oa[fp * 2 + hh];
                    mma16816(c, aPh, &vh[2 * hh]);
                    mma16816(c, aPh, &vl[2 * hh]);
                }
            }
        }
        __syncthreads();
    }
#undef LOADK

    const float gam = *gptr;
    const float i0 = gam / l0r, i1 = gam / l1r;
    const int r0 = c0 + wid * 16 + g, r1 = r0 + 8;
    float* O = outg + (long)b * CCH * HW;
#pragma unroll
    for (int j = 0; j < 16; j++) {
        const int col = j * 8 + t * 2;
        const long o0 = (long)r0 * HW + col;
        const long o1 = (long)r1 * HW + col;
        float2 y0 = *(const float2*)&Y[o0];
        float2 y1v = *(const float2*)&Y[o1];
        float2 w0, w1;
        w0.x = Oa[j][0] * i0 + y0.x;  w0.y = Oa[j][1] * i0 + y0.y;
        w1.x = Oa[j][2] * i1 + y1v.x; w1.y = Oa[j][3] * i1 + y1v.y;
        *(float2*)&O[o0] = w0;
        *(float2*)&O[o1] = w1;
    }
}

// ------------------------ graph construction -------------------------------
__global__ void graph_build(const float* __restrict__ ip,
                            const float* __restrict__ adj,
                            __nv_bfloat16* __restrict__ gh,
                            __nv_bfloat16* __restrict__ gl)
{
    __shared__ float reda[4], redb[4];
    const int n = blockIdx.y, v = blockIdx.x, w = threadIdx.x;
    const long base = ((long)n * VV + v) * VV;

    const float sqv = ip[((long)n * VV + v) * VV + v];
    const float sqw = ip[((long)n * VV + w) * VV + w];
    const float e   = ip[base + w];

    float d2   = sqv + sqw - 2.f * e;
    float dist = sqrtf(fmaxf(d2, 1e-12f));
    float sim  = 2.f / (expf(dist) + 1.f);
    float av   = adj[base + w];
    if (w == v) { sim = 0.f; av = 0.f; }

    float s1 = warpSum(fabsf(sim));
    float s2 = warpSum(fabsf(av));
    if ((w & 31) == 0) { reda[w >> 5] = s1; redb[w >> 5] = s2; }
    __syncthreads();
    const float ssum = reda[0] + reda[1] + reda[2] + reda[3];
    const float asum = redb[0] + redb[1] + redb[2] + redb[3];

    float gv = 0.5f * (av / fmaxf(asum, 1e-12f) + sim / fmaxf(ssum, 1e-12f));
    __nv_bfloat16 hh, ll;
    bsplit(gv, hh, ll);
    gh[base + w] = hh;
    gl[base + w] = ll;
}

// ------------------------- batch-norm stats --------------------------------
__global__ void bn_stats(const float* __restrict__ hp,
                         float* __restrict__ mean, float* __restrict__ var,
                         int rows, int C)
{
    __shared__ float shs[8][32];
    __shared__ float shs2[8][32];
    const int lane = threadIdx.x & 31;
    const int ry   = threadIdx.x >> 5;
    const int c    = blockIdx.x * 32 + lane;

    float s = 0.f, s2 = 0.f;
    for (int r = ry; r < rows; r += 8) {
        float v = hp[(long)r * C + c];
        s += v; s2 += v * v;
    }
    shs[ry][lane] = s; shs2[ry][lane] = s2;
    __syncthreads();
    if (ry == 0) {
#pragma unroll
        for (int j = 1; j < 8; j++) { s += shs[j][lane]; s2 += shs2[j][lane]; }
        float mu = s / rows;
        mean[c] = mu;
        var[c]  = s2 / rows - mu * mu;
    }
}

// ------------------- BN apply + LeakyReLU + residual -----------------------
__global__ void bn_apply(const float* __restrict__ inp,
                         const float* __restrict__ hp,
                         const float* __restrict__ mean,
                         const float* __restrict__ var,
                         const float* __restrict__ bw,
                         const float* __restrict__ bb,
                         const float* __restrict__ gptr,
                         float* __restrict__ out,
                         __nv_bfloat16* __restrict__ oh,
                         __nv_bfloat16* __restrict__ ol,
                         int total, int C)
{
    const int idx = blockIdx.x * blockDim.x + threadIdx.x;
    if (idx >= total) return;
    const int c = idx & (C - 1);
    const float g = *gptr;
    float vv = (hp[idx] - mean[c]) * rsqrtf(var[c] + 1e-5f) * bw[c] + bb[c];
    float lr = vv > 0.f ? vv : 0.1f * vv;
    float o = inp[idx] + g * lr;
    out[idx] = o;
    if (oh) {
        __nv_bfloat16 hh, ll;
        bsplit(o, hh, ll);
        oh[idx] = hh;
        ol[idx] = ll;
    }
}

// ------------------------------ host side ----------------------------------
typedef __nv_bfloat16 bf;

static void launch_tb(int TA, int TB,
                      const bf* Ah, const bf* Al, const bf* Bh, const bf* Bl,
                      float* C, bf* Ch, bf* Cl,
                      int M, int N, int K,
                      long sA, long sB, long sC, int batch,
                      const float* bias, const float* Res, long sRes,
                      float aH, const float* aD, cudaStream_t st)
{
    dim3 grid(N / 128, M / 128, batch);
    dim3 blk(256);
    if (TA == 0 && TB == 0)
        tbgemm_kernel<0, 0><<<grid, blk, TSMEM, st>>>(Ah, Al, Bh, Bl, C, Ch, Cl,
            M, N, K, sA, sB, sC, bias, Res, sRes, aH, aD);
    else if (TA == 1 && TB == 0)
        tbgemm_kernel<1, 0><<<grid, blk, TSMEM, st>>>(Ah, Al, Bh, Bl, C, Ch, Cl,
            M, N, K, sA, sB, sC, bias, Res, sRes, aH, aD);
    else
        tbgemm_kernel<0, 1><<<grid, blk, TSMEM, st>>>(Ah, Al, Bh, Bl, C, Ch, Cl,
            M, N, K, sA, sB, sC, bias, Res, sRes, aH, aD);
}

extern "C" void kernel_launch(void* const* d_in, const int* in_sizes, int n_in,
                              void* d_out, int out_size)
{
    const float* x     = (const float*)d_in[0];
    const float* vfeat = (const float*)d_in[1];
    const float* adj   = (const float*)d_in[2];
    const float* Wq    = (const float*)d_in[3];
    const float* bq    = (const float*)d_in[4];
    const float* Wk    = (const float*)d_in[5];
    const float* bk    = (const float*)d_in[6];
    const float* Wv    = (const float*)d_in[7];
    const float* bv    = (const float*)d_in[8];
    const float* gpam  = (const float*)d_in[9];
    const float* gcam  = (const float*)d_in[10];
    const float* Wg    = (const float*)d_in[11];
    const float* bnw   = (const float*)d_in[12];
    const float* bnb   = (const float*)d_in[13];
    const float* gg    = (const float*)d_in[14];
    float* out = (float*)d_out;

    float *att1, *y1, *ip, *hp, *gbuf, *mean, *var;
    bf *y1h, *y1l, *xh, *xl, *wqh, *wql, *wkh, *wkl, *wvh, *wvl;
    bf *qh, *ql, *kh, *kl, *vh, *vl, *a1h, *a1l;
    bf *vfh, *vfl, *gbh, *gbl, *wgh, *wgl, *hh_, *hl_, *gph, *gpl;
    cudaGetSymbolAddress((void**)&att1, d_att1);
    cudaGetSymbolAddress((void**)&y1,   d_y1);
    cudaGetSymbolAddress((void**)&y1h,  d_y1h);
    cudaGetSymbolAddress((void**)&y1l,  d_y1l);
    cudaGetSymbolAddress((void**)&ip,   d_ip);
    cudaGetSymbolAddress((void**)&hp,   d_hp);
    cudaGetSymbolAddress((void**)&gbuf, d_gbuf);
    cudaGetSymbolAddress((void**)&mean, d_mean);
    cudaGetSymbolAddress((void**)&var,  d_var);
    cudaGetSymbolAddress((void**)&xh,   d_xh);
    cudaGetSymbolAddress((void**)&xl,   d_xl);
    cudaGetSymbolAddress((void**)&wqh,  d_wqh);
    cudaGetSymbolAddress((void**)&wql,  d_wql);
    cudaGetSymbolAddress((void**)&wkh,  d_wkh);
    cudaGetSymbolAddress((void**)&wkl,  d_wkl);
    cudaGetSymbolAddress((void**)&wvh,  d_wvh);
    cudaGetSymbolAddress((void**)&wvl,  d_wvl);
    cudaGetSymbolAddress((void**)&qh,   d_qh);
    cudaGetSymbolAddress((void**)&ql,   d_ql);
    cudaGetSymbolAddress((void**)&kh,   d_kh);
    cudaGetSymbolAddress((void**)&kl,   d_kl);
    cudaGetSymbolAddress((void**)&vh,   d_vh);
    cudaGetSymbolAddress((void**)&vl,   d_vl);
    cudaGetSymbolAddress((void**)&a1h,  d_a1h);
    cudaGetSymbolAddress((void**)&a1l,  d_a1l);
    cudaGetSymbolAddress((void**)&vfh,  d_vfh);
    cudaGetSymbolAddress((void**)&vfl,  d_vfl);
    cudaGetSymbolAddress((void**)&gbh,  d_gbh);
    cudaGetSymbolAddress((void**)&gbl,  d_gbl);
    cudaGetSymbolAddress((void**)&wgh,  d_wgh);
    cudaGetSymbolAddress((void**)&wgl,  d_wgl);
    cudaGetSymbolAddress((void**)&hh_,  d_hh);
    cudaGetSymbolAddress((void**)&hl_,  d_hl);
    cudaGetSymbolAddress((void**)&gph,  d_gph);
    cudaGetSymbolAddress((void**)&gpl,  d_gpl);

    static int inited = 0;
    if (!inited) {
        cudaFuncSetAttribute(tbgemm_kernel<0, 0>,
                             cudaFuncAttributeMaxDynamicSharedMemorySize, TSMEM);
        cudaFuncSetAttribute(tbgemm_kernel<1, 0>,
                             cudaFuncAttributeMaxDynamicSharedMemorySize, TSMEM);
        cudaFuncSetAttribute(tbgemm_kernel<0, 1>,
                             cudaFuncAttributeMaxDynamicSharedMemorySize, TSMEM);
        cudaFuncSetAttribute(cam_tc_kernel,
                             cudaFuncAttributeMaxDynamicSharedMemorySize, CAM_SMEM);
        inited = 1;
    }
    static cudaStream_t s1 = [](){ cudaStream_t s;
        cudaStreamCreateWithFlags(&s, cudaStreamNonBlocking); return s; }();
    static cudaStream_t s2 = [](){ cudaStream_t s;
        cudaStreamCreateWithFlags(&s, cudaStreamNonBlocking); return s; }();
    static cudaEvent_t evF = [](){ cudaEvent_t e;
        cudaEventCreateWithFlags(&e, cudaEventDisableTiming); return e; }();
    static cudaEvent_t evK = [](){ cudaEvent_t e;
        cudaEventCreateWithFlags(&e, cudaEventDisableTiming); return e; }();
    static cudaEvent_t evV = [](){ cudaEvent_t e;
        cudaEventCreateWithFlags(&e, cudaEventDisableTiming); return e; }();
    static cudaEvent_t evJ = [](){ cudaEvent_t e;
        cudaEventCreateWithFlags(&e, cudaEventDisableTiming); return e; }();

    const long CHW = (long)CCH * HW;          // 262144
    const long QHW = (long)C8 * HW;           // 32768
    const long GST = (long)VV * CCH;          // 262144
    cudaStream_t s0 = 0;

    // ---- split x first (all projections need it), then fork ----
    split_f32_kernel<<<(BSZ * CCH * HW) / 1024, 256, 0, s0>>>(x, xh, xl);
    cudaEventRecord(evF, s0);
    cudaStreamWaitEvent(s1, evF, 0);
    cudaStreamWaitEvent(s2, evF, 0);

    // ---------------- PAM ----------------
    split_f32_kernel<<<(C8 * CCH) / 1024, 256, 0, s0>>>(Wq, wqh, wql);
    launch_tb(0, 0, wqh, wql, xh, xl, nullptr, qh, ql,
              C8, HW, CCH, 0, CHW, QHW, BSZ, bq, nullptr, 0, 1.f, nullptr, s0);

    split_f32_kernel<<<(C8 * CCH) / 1024, 256, 0, s1>>>(Wk, wkh, wkl);
    launch_tb(0, 0, wkh, wkl, xh, xl, nullptr, kh, kl,
              C8, HW, CCH, 0, CHW, QHW, BSZ, bk, nullptr, 0, 1.f, nullptr, s1);
    cudaEventRecord(evK, s1);
    split_f32_kernel<<<(CCH * CCH) / 1024, 256, 0, s1>>>(Wv, wvh, wvl);
    launch_tb(0, 0, wvh, wvl, xh, xl, nullptr, vh, vl,
              CCH, HW, CCH, 0, CHW, CHW, BSZ, bv, nullptr, 0, 1.f, nullptr, s1);
    cudaEventRecord(evV, s1);

    cudaStreamWaitEvent(s0, evK, 0);
    launch_tb(1, 0, qh, ql, kh, kl, att1, nullptr, nullptr,
              HW, HW, C8, QHW, QHW, (long)HW * HW, BSZ,
              nullptr, nullptr, 0, 1.f, nullptr, s0);
    softmax_kernel<<<BSZ * HW, 128, 0, s0>>>(att1, a1h, a1l, HW);
    cudaStreamWaitEvent(s0, evV, 0);
    // y1 = gamma_pam * (v @ att1^T) + x  (f32 + split outputs)
    launch_tb(0, 1, vh, vl, a1h, a1l, y1, y1h, y1l,
              CCH, HW, HW, CHW, (long)HW * HW, CHW, BSZ,
              nullptr, x, CHW, 0.f, gpam, s0);

    // ---------------- CAM (s0) ----------------
    {
        dim3 grid(CCH / 128, BSZ);
        cam_tc_kernel<<<grid, 256, CAM_SMEM, s0>>>(y1, y1h, y1l, gcam, out);
    }

    // ------------- Graph layers (s2) -------------
    split_f32_kernel<<<(NV * VV * CCH) / 1024, 256, 0, s2>>>(vfeat, vfh, vfl);
    split_f32_kernel<<<(GNUM * CCH * CCH) / 1024, 256, 0, s2>>>(Wg, wgh, wgl);

    const float* inp = vfeat;
    for (int i = 0; i < GNUM; i++) {
        const bf* ih = (i == 0) ? vfh : gbh;
        const bf* il = (i == 0) ? vfl : gbl;
        float* outg = (i == GNUM - 1) ? (out + (long)BSZ * CCH * HW) : gbuf;

        launch_tb(0, 1, ih, il, wgh + (long)i * CCH * CCH, wgl + (long)i * CCH * CCH,
                  nullptr, hh_, hl_, NV * VV, CCH, CCH, 0, 0, 0, 1,
                  nullptr, nullptr, 0, 1.f, nullptr, s2);
        launch_tb(0, 1, ih, il, ih, il, ip, nullptr, nullptr,
                  VV, VV, CCH, GST, GST, (long)VV * VV, NV,
                  nullptr, nullptr, 0, 1.f, nullptr, s2);
        graph_build<<<dim3(VV, NV), VV, 0, s2>>>(ip, adj, gph, gpl);
        launch_tb(0, 0, gph, gpl, hh_, hl_, hp, nullptr, nullptr,
                  VV, CCH, VV, (long)VV * VV, GST, GST, NV,
                  nullptr, nullptr, 0, 1.f, nullptr, s2);
        bn_stats<<<CCH / 32, 256, 0, s2>>>(hp, mean, var, NV * VV, CCH);
        bn_apply<<<(NV * VV * CCH + 255) / 256, 256, 0, s2>>>(
            inp, hp, mean, var, bnw + (long)i * CCH, bnb + (long)i * CCH,
            gg + i, outg,
            (i == GNUM - 1) ? nullptr : gbh,
            (i == GNUM - 1) ? nullptr : gbl,
            NV * VV * CCH, CCH);
        inp = outg;
    }

    // ---- join ----
    cudaEventRecord(evJ, s2);
    cudaStreamWaitEvent(s0, evJ, 0);
}

// round 17
// speedup vs baseline: 1.6864x; 1.1787x over previous
#include <cuda_runtime.h>
#include <cuda_bf16.h>
#include <math.h>

// ---------------------------------------------------------------------------
// Problem constants
// ---------------------------------------------------------------------------
#define BSZ   16
#define CCH   2048
#define HW    128
#define C8    256
#define NV    16
#define VV    128
#define GNUM  2

// ------------------------- scratch (device globals) ------------------------
__device__ __align__(256) float d_att1[BSZ * HW * HW];
__device__ __align__(256) float d_y1  [BSZ * CCH * HW];
__device__ __align__(256) __nv_bfloat16 d_y1h[BSZ * CCH * HW];
__device__ __align__(256) __nv_bfloat16 d_y1l[BSZ * CCH * HW];
__device__ __align__(256) float d_ip  [NV * VV * VV];
__device__ __align__(256) float d_hp  [NV * VV * CCH];
__device__ __align__(256) float d_gbuf[NV * VV * CCH];
__device__ __align__(256) float d_mean[CCH];
__device__ __align__(256) float d_var [CCH];
__device__ __align__(256) __nv_bfloat16 d_xh [BSZ * CCH * HW];
__device__ __align__(256) __nv_bfloat16 d_xl [BSZ * CCH * HW];
__device__ __align__(256) __nv_bfloat16 d_wqh[C8 * CCH];
__device__ __align__(256) __nv_bfloat16 d_wql[C8 * CCH];
__device__ __align__(256) __nv_bfloat16 d_wkh[C8 * CCH];
__device__ __align__(256) __nv_bfloat16 d_wkl[C8 * CCH];
__device__ __align__(256) __nv_bfloat16 d_wvh[CCH * CCH];
__device__ __align__(256) __nv_bfloat16 d_wvl[CCH * CCH];
__device__ __align__(256) __nv_bfloat16 d_qh [BSZ * C8 * HW];
__device__ __align__(256) __nv_bfloat16 d_ql [BSZ * C8 * HW];
__device__ __align__(256) __nv_bfloat16 d_kh [BSZ * C8 * HW];
__device__ __align__(256) __nv_bfloat16 d_kl [BSZ * C8 * HW];
__device__ __align__(256) __nv_bfloat16 d_vh [BSZ * CCH * HW];
__device__ __align__(256) __nv_bfloat16 d_vl [BSZ * CCH * HW];
__device__ __align__(256) __nv_bfloat16 d_a1h[BSZ * HW * HW];
__device__ __align__(256) __nv_bfloat16 d_a1l[BSZ * HW * HW];
__device__ __align__(256) __nv_bfloat16 d_vfh[NV * VV * CCH];
__device__ __align__(256) __nv_bfloat16 d_vfl[NV * VV * CCH];
__device__ __align__(256) __nv_bfloat16 d_gbh[NV * VV * CCH];
__device__ __align__(256) __nv_bfloat16 d_gbl[NV * VV * CCH];
__device__ __align__(256) __nv_bfloat16 d_wgh[GNUM * CCH * CCH];
__device__ __align__(256) __nv_bfloat16 d_wgl[GNUM * CCH * CCH];
__device__ __align__(256) __nv_bfloat16 d_hh [NV * VV * CCH];
__device__ __align__(256) __nv_bfloat16 d_hl [NV * VV * CCH];
__device__ __align__(256) __nv_bfloat16 d_gph[NV * VV * VV];
__device__ __align__(256) __nv_bfloat16 d_gpl[NV * VV * VV];

// ---------------------- shared mma/ldsm/split helpers -----------------------
__device__ __forceinline__ void ldsm4(unsigned* r, unsigned addr) {
    asm volatile("ldmatrix.sync.aligned.m8n8.x4.shared.b16 {%0,%1,%2,%3}, [%4];"
        : "=r"(r[0]), "=r"(r[1]), "=r"(r[2]), "=r"(r[3]) : "r"(addr));
}
__device__ __forceinline__ void ldsm4t(unsigned* r, unsigned addr) {
    asm volatile("ldmatrix.sync.aligned.m8n8.x4.trans.shared.b16 {%0,%1,%2,%3}, [%4];"
        : "=r"(r[0]), "=r"(r[1]), "=r"(r[2]), "=r"(r[3]) : "r"(addr));
}
__device__ __forceinline__ void mma16816(float* c, const unsigned* a, const unsigned* b) {
    asm volatile("mma.sync.aligned.m16n8k16.row.col.f32.bf16.bf16.f32 "
        "{%0,%1,%2,%3}, {%4,%5,%6,%7}, {%8,%9}, {%0,%1,%2,%3};"
        : "+f"(c[0]), "+f"(c[1]), "+f"(c[2]), "+f"(c[3])
        : "r"(a[0]), "r"(a[1]), "r"(a[2]), "r"(a[3]), "r"(b[0]), "r"(b[1]));
}
__device__ __forceinline__ void bsplit(float x, __nv_bfloat16& h, __nv_bfloat16& l) {
    h = __float2bfloat16(x);
    l = __float2bfloat16(x - __bfloat162float(h));
}
__device__ __forceinline__ unsigned packbf(float a, float b) {
    __nv_bfloat162 p; p.x = __float2bfloat16(a); p.y = __float2bfloat16(b);
    return *(unsigned*)&p;
}
__device__ __forceinline__ void cpa16(unsigned s, const void* g) {
    asm volatile("cp.async.cg.shared.global [%0], [%1], 16;" :: "r"(s), "l"(g));
}

#define TST   40
#define TS2   136
#define TTILE (128 * TST)
#define TSMEM (2 * 4 * TTILE * 2)

// ================= pre-split bf16-input GEMM (universal) ====================
template<int TA, int TB>
__global__ __launch_bounds__(256, 2)
void tbgemm_kernel(const __nv_bfloat16* __restrict__ Ahg,
                   const __nv_bfloat16* __restrict__ Alg,
                   const __nv_bfloat16* __restrict__ Bhg,
                   const __nv_bfloat16* __restrict__ Blg,
                   float* __restrict__ Cg,
                   __nv_bfloat16* __restrict__ Chg,
                   __nv_bfloat16* __restrict__ Clg,
                   int M, int N, int K,
                   long sA, long sB, long sC,
                   const float* __restrict__ bias,
                   const float* __restrict__ Res, long sRes,
                   float alphaH, const float* __restrict__ alphaD)
{
    extern __shared__ __align__(16) __nv_bfloat16 ts[];

    const int bz = blockIdx.z;
    const __nv_bfloat16* Ah = Ahg + (long)bz * sA;
    const __nv_bfloat16* Al = Alg + (long)bz * sA;
    const __nv_bfloat16* Bh = Bhg + (long)bz * sB;
    const __nv_bfloat16* Bl = Blg + (long)bz * sB;

    const int m0 = blockIdx.y * 128;
    const int n0 = blockIdx.x * 128;
    const int tid  = threadIdx.x;
    const int wid  = tid >> 5;
    const int lane = tid & 31;
    const int warp_m = (wid >> 1) * 32;
    const int warp_n = (wid & 1) * 64;
    const int mi = lane >> 3, ri = lane & 7;
    const int g  = lane >> 2, t  = lane & 3;

    const unsigned sbase = (unsigned)__cvta_generic_to_shared(ts);

    unsigned aoff[2], boff[4];
#pragma unroll
    for (int fi = 0; fi < 2; fi++) {
        if (TA == 0)
            aoff[fi] = ((warp_m + fi * 16 + ((mi & 1) << 3) + ri) * TST + ((mi >> 1) << 3)) * 2;
        else
            aoff[fi] = ((((mi >> 1) << 3) + ri) * TS2 + warp_m + fi * 16 + ((mi & 1) << 3)) * 2;
    }
#pragma unroll
    for (int fp = 0; fp < 4; fp++) {
        if (TB == 1)
            boff[fp] = ((warp_n + fp * 16 + ((mi >> 1) << 3) + ri) * TST + ((mi & 1) << 3)) * 2;
        else
            boff[fp] = ((((mi & 1) << 3) + ri) * TS2 + warp_n + fp * 16 + ((mi >> 1) << 3)) * 2;
    }
    const unsigned akk = (TA == 0) ? 32u : (unsigned)(16 * TS2 * 2);
    const unsigned bkk = (TB == 1) ? 32u : (unsigned)(16 * TS2 * 2);

    float acc[2][8][4];
#pragma unroll
    for (int i = 0; i < 2; i++)
#pragma unroll
        for (int j = 0; j < 8; j++)
#pragma unroll
            for (int q = 0; q < 4; q++) acc[i][j][q] = 0.f;

#define CPLOAD(k0, bf)                                                         \
    do {                                                                       \
        const unsigned dAh = sbase + ((bf) * 4 + 0) * TTILE * 2;               \
        const unsigned dAl = sbase + ((bf) * 4 + 1) * TTILE * 2;               \
        const unsigned dBh = sbase + ((bf) * 4 + 2) * TTILE * 2;               \
        const unsigned dBl = sbase + ((bf) * 4 + 3) * TTILE * 2;               \
        if (TA == 0) {                                                         \
            _Pragma("unroll")                                                  \
            for (int i = 0; i < 2; i++) {                                      \
                int idx = tid + 256 * i; int r = idx >> 2, c8 = (idx & 3) * 8; \
                long go = (long)(m0 + r) * K + (k0) + c8;                      \
                cpa16(dAh + (r * TST + c8) * 2, Ah + go);                      \
                cpa16(dAl + (r * TST + c8) * 2, Al + go);                      \
            }                                                                  \
        } else {                                                               \
            _Pragma("unroll")                                                  \
            for (int i = 0; i < 2; i++) {                                      \
                int idx = tid + 256 * i; int r = idx >> 4, c8 = (idx & 15) * 8;\
                long go = (long)((k0) + r) * M + m0 + c8;                      \
                cpa16(dAh + (r * TS2 + c8) * 2, Ah + go);                      \
                cpa16(dAl + (r * TS2 + c8) * 2, Al + go);                      \
            }                                                                  \
        }                                                                      \
        if (TB == 1) {                                                         \
            _Pragma("unroll")                                                  \
            for (int i = 0; i < 2; i++) {                                      \
                int idx = tid + 256 * i; int r = idx >> 2, c8 = (idx & 3) * 8; \
                long go = (long)(n0 + r) * K + (k0) + c8;                      \
                cpa16(dBh + (r * TST + c8) * 2, Bh + go);                      \
                cpa16(dBl + (r * TST + c8) * 2, Bl + go);                      \
            }                                                                  \
        } else {                                                               \
            _Pragma("unroll")                                                  \
            for (int i = 0; i < 2; i++) {                                      \
                int idx = tid + 256 * i; int r = idx >> 4, c8 = (idx & 15) * 8;\
                long go = (long)((k0) + r) * N + n0 + c8;                      \
                cpa16(dBh + (r * TS2 + c8) * 2, Bh + go);                      \
                cpa16(dBl + (r * TS2 + c8) * 2, Bl + go);                      \
            }                                                                  \
        }                                                                      \
    } while (0)

#define MMASTEP(bf)                                                            \
    do {                                                                       \
        const unsigned bAh = sbase + ((bf) * 4 + 0) * TTILE * 2;               \
        const unsigned bAl = sbase + ((bf) * 4 + 1) * TTILE * 2;               \
        const unsigned bBh = sbase + ((bf) * 4 + 2) * TTILE * 2;               \
        const unsigned bBl = sbase + ((bf) * 4 + 3) * TTILE * 2;               \
        _Pragma("unroll")                                                      \
        for (int kk = 0; kk < 2; kk++) {                                       \
            unsigned ah[2][4], al[2][4], bh[4][4], bl[4][4];                   \
            _Pragma("unroll")                                                  \
            for (int fi = 0; fi < 2; fi++) {                                   \
                if (TA == 0) {                                                 \
                    ldsm4(ah[fi], bAh + aoff[fi] + kk * akk);                  \
                    ldsm4(al[fi], bAl + aoff[fi] + kk * akk);                  \
                } else {                                                       \
                    ldsm4t(ah[fi], bAh + aoff[fi] + kk * akk);                 \
                    ldsm4t(al[fi], bAl + aoff[fi] + kk * akk);                 \
                }                                                              \
            }                                                                  \
            _Pragma("unroll")                                                  \
            for (int fp = 0; fp < 4; fp++) {                                   \
                if (TB == 1) {                                                 \
                    ldsm4(bh[fp], bBh + boff[fp] + kk * bkk);                  \
                    ldsm4(bl[fp], bBl + boff[fp] + kk * bkk);                  \
                } else {                                                       \
                    ldsm4t(bh[fp], bBh + boff[fp] + kk * bkk);                 \
                    ldsm4t(bl[fp], bBl + boff[fp] + kk * bkk);                 \
                }                                                              \
            }                                                                  \
            _Pragma("unroll")                                                  \
            for (int fi = 0; fi < 2; fi++)                                     \
                _Pragma("unroll")                                              \
                for (int fp = 0; fp < 4; fp++)                                 \
                    _Pragma("unroll")                                          \
                    for (int hh = 0; hh < 2; hh++) {                           \
                        float* c = acc[fi][fp * 2 + hh];                       \
                        mma16816(c, ah[fi], &bh[fp][2 * hh]);                  \
                        mma16816(c, ah[fi], &bl[fp][2 * hh]);                  \
                        mma16816(c, al[fi], &bh[fp][2 * hh]);                  \
                    }                                                          \
        }                                                                      \
    } while (0)

    CPLOAD(0, 0);
    asm volatile("cp.async.commit_group;" ::: "memory");

    const int nt = K / 32;
    for (int tI = 0; tI < nt; tI++) {
        if (tI + 1 < nt) {
            CPLOAD((tI + 1) * 32, (tI + 1) & 1);
            asm volatile("cp.async.commit_group;" ::: "memory");
            asm volatile("cp.async.wait_group 1;" ::: "memory");
        } else {
            asm volatile("cp.async.wait_group 0;" ::: "memory");
        }
        __syncthreads();
        MMASTEP(tI & 1);
        __syncthreads();
    }

    const float alpha = alphaD ? *alphaD : alphaH;
#pragma unroll
    for (int fi = 0; fi < 2; fi++) {
        const int m = m0 + warp_m + fi * 16 + g;
        const float bi0 = bias ? __ldg(&bias[m])     : 0.f;
        const float bi1 = bias ? __ldg(&bias[m + 8]) : 0.f;
#pragma unroll
        for (int fj = 0; fj < 8; fj++) {
            const int n = n0 + warp_n + fj * 8 + t * 2;
            const float* c = acc[fi][fj];
            const long off0 = (long)bz * sC + (long)m * N + n;
            const long off1 = (long)bz * sC + (long)(m + 8) * N + n;
            float v0 = alpha * c[0] + bi0, v1 = alpha * c[1] + bi0;
            float v2 = alpha * c[2] + bi1, v3 = alpha * c[3] + bi1;
            if (Res) {
                const long ro0 = (long)bz * sRes + (long)m * N + n;
                const long ro1 = (long)bz * sRes + (long)(m + 8) * N + n;
                float2 r0 = *(const float2*)&Res[ro0];
                float2 r1 = *(const float2*)&Res[ro1];
                v0 += r0.x; v1 += r0.y; v2 += r1.x; v3 += r1.y;
            }
            if (Cg) {
                float2 o0, o1;
                o0.x = v0; o0.y = v1; o1.x = v2; o1.y = v3;
                *(float2*)&Cg[off0] = o0;
                *(float2*)&Cg[off1] = o1;
            }
            if (Chg) {
                __nv_bfloat16 h0, l0, h1, l1;
                __nv_bfloat162 hh, ll;
                bsplit(v0, h0, l0); bsplit(v1, h1, l1);
                hh.x = h0; hh.y = h1; *(__nv_bfloat162*)&Chg[off0] = hh;
                ll.x = l0; ll.y = l1; *(__nv_bfloat162*)&Clg[off0] = ll;
                bsplit(v2, h0, l0); bsplit(v3, h1, l1);
                hh.x = h0; hh.y = h1; *(__nv_bfloat162*)&Chg[off1] = hh;
                ll.x = l0; ll.y = l1; *(__nv_bfloat162*)&Clg[off1] = ll;
            }
        }
    }
#undef CPLOAD
#undef MMASTEP
}

// --------------------------- reductions ------------------------------------
__device__ __forceinline__ float warpMax(float v) {
#pragma unroll
    for (int o = 16; o; o >>= 1) v = fmaxf(v, __shfl_xor_sync(0xffffffffu, v, o));
    return v;
}
__device__ __forceinline__ float warpSum(float v) {
#pragma unroll
    for (int o = 16; o; o >>= 1) v += __shfl_xor_sync(0xffffffffu, v, o);
    return v;
}

// in-place row softmax; optional bf16 hi/lo outputs
__global__ void softmax_kernel(float* __restrict__ d,
                               __nv_bfloat16* __restrict__ dh,
                               __nv_bfloat16* __restrict__ dl,
                               int ncols)
{
    __shared__ float red[32];
    __shared__ float bcast;
    const long row = blockIdx.x;
    float* p = d + row * (long)ncols;
    const int tid = threadIdx.x, nt = blockDim.x;

    float m = -1e30f;
    for (int i = tid; i < ncols; i += nt) m = fmaxf(m, p[i]);
    m = warpMax(m);
    if ((tid & 31) == 0) red[tid >> 5] = m;
    __syncthreads();
    if (tid < 32) {
        float v = (tid < (nt >> 5)) ? red[tid] : -1e30f;
        v = warpMax(v);
        if (tid == 0) bcast = v;
    }
    __syncthreads();
    m = bcast;

    float s = 0.f;
    for (int i = tid; i < ncols; i += nt) {
        float e = __expf(p[i] - m);
        p[i] = e;
        s += e;
    }
    __syncthreads();
    s = warpSum(s);
    if ((tid & 31) == 0) red[tid >> 5] = s;
    __syncthreads();
    if (tid < 32) {
        float v = (tid < (nt >> 5)) ? red[tid] : 0.f;
        v = warpSum(v);
        if (tid == 0) bcast = v;
    }
    __syncthreads();
    const float inv = 1.f / bcast;
    for (int i = tid; i < ncols; i += nt) {
        float pv = p[i] * inv;
        p[i] = pv;
        if (dh) {
            __nv_bfloat16 hh, ll;
            bsplit(pv, hh, ll);
            dh[row * (long)ncols + i] = hh;
            dl[row * (long)ncols + i] = ll;
        }
    }
}

// ---------------------- f32 -> bf16 hi/lo split -----------------------------
__global__ void split_f32_kernel(const float* __restrict__ src,
                                 __nv_bfloat16* __restrict__ yh,
                                 __nv_bfloat16* __restrict__ yl)
{
    const int i = (blockIdx.x * blockDim.x + threadIdx.x) * 4;
    float4 v = *(const float4*)&src[i];
    __nv_bfloat16 h0,l0,h1,l1,h2,l2,h3,l3;
    bsplit(v.x,h0,l0); bsplit(v.y,h1,l1); bsplit(v.z,h2,l2); bsplit(v.w,h3,l3);
    __nv_bfloat162 a;
    a.x = h0; a.y = h1; *(__nv_bfloat162*)&yh[i]     = a;
    a.x = h2; a.y = h3; *(__nv_bfloat162*)&yh[i + 2] = a;
    a.x = l0; a.y = l1; *(__nv_bfloat162*)&yl[i]     = a;
    a.x = l2; a.y = l3; *(__nv_bfloat162*)&yl[i + 2] = a;
}

// ================= tensor-core fused CAM (flash style, v3) ==================
// Q tile loaded via cp.async (same commit group as K0).
#define CST   136
#define CTILE (128 * CST)
#define CAM_SMEM (6 * CTILE * 2)

__global__ __launch_bounds__(256)
void cam_tc_kernel(const float* __restrict__ y1g,
                   const __nv_bfloat16* __restrict__ y1hg,
                   const __nv_bfloat16* __restrict__ y1lg,
                   const float* __restrict__ gptr,
                   float* __restrict__ outg)
{
    extern __shared__ __align__(16) __nv_bfloat16 cs[];

    const int b  = blockIdx.y;
    const int c0 = blockIdx.x * 128;
    const float* Y          = y1g  + (long)b * CCH * HW;
    const __nv_bfloat16* Yh = y1hg + (long)b * CCH * HW;
    const __nv_bfloat16* Yl = y1lg + (long)b * CCH * HW;

    const int tid = threadIdx.x, wid = tid >> 5, lane = tid & 31;
    const int mi = lane >> 3, ri = lane & 7, g = lane >> 2, t = lane & 3;

    const unsigned sb  = (unsigned)__cvta_generic_to_shared(cs);
    const unsigned bQh = sb;
    const unsigned bQl = sb + CTILE * 2;

    const unsigned aoff = ((wid * 16 + ((mi & 1) << 3) + ri) * CST + ((mi >> 1) << 3)) * 2;
    const unsigned bS = ((((mi >> 1) << 3) + ri) * CST + ((mi & 1) << 3)) * 2;
    const unsigned bT = ((((mi & 1) << 3) + ri) * CST + ((mi >> 1) << 3)) * 2;

#define LOADK(tt, buf)                                                         \
    do {                                                                       \
        const unsigned dh = sb + (2 + (buf) * 2) * CTILE * 2;                  \
        const unsigned dl = dh + CTILE * 2;                                    \
        _Pragma("unroll")                                                      \
        for (int i = 0; i < 8; i++) {                                          \
            int c = tid + 256 * i;                                             \
            int r = c >> 4, col8 = (c & 15) * 8;                               \
            cpa16(dh + (r * CST + col8) * 2, Yh + (long)((tt) * 128 + r) * HW + col8); \
            cpa16(dl + (r * CST + col8) * 2, Yl + (long)((tt) * 128 + r) * HW + col8); \
        }                                                                      \
    } while (0)

    // K0 + Q in one commit group (first wait covers both)
    LOADK(0, 0);
#pragma unroll
    for (int i = 0; i < 8; i++) {
        int c = tid + 256 * i;
        int r = c >> 4, col8 = (c & 15) * 8;
        cpa16(bQh + (r * CST + col8) * 2, Yh + (long)(c0 + r) * HW + col8);
        cpa16(bQl + (r * CST + col8) * 2, Yl + (long)(c0 + r) * HW + col8);
    }
    asm volatile("cp.async.commit_group;" ::: "memory");

    float Sa[16][4], Oa[16][4];
    float m0r = -1e30f, m1r = -1e30f, l0r = 0.f, l1r = 0.f;
#pragma unroll
    for (int j = 0; j < 16; j++) { Oa[j][0]=Oa[j][1]=Oa[j][2]=Oa[j][3]=0.f; }

    for (int tI = 0; tI < 16; tI++) {
        const int buf = tI & 1;
        if (tI < 15) {
            LOADK(tI + 1, buf ^ 1);
            asm volatile("cp.async.commit_group;" ::: "memory");
            asm volatile("cp.async.wait_group 1;" ::: "memory");
        } else {
            asm volatile("cp.async.wait_group 0;" ::: "memory");
        }
        __syncthreads();

        const unsigned bKh = sb + (2 + buf * 2) * CTILE * 2;
        const unsigned bKl = bKh + CTILE * 2;

#pragma unroll
        for (int j = 0; j < 16; j++) { Sa[j][0]=Sa[j][1]=Sa[j][2]=Sa[j][3]=0.f; }
#pragma unroll
        for (int ks = 0; ks < 8; ks++) {
            unsigned ah[4], al[4];
            ldsm4(ah, bQh + aoff + ks * 32);
            ldsm4(al, bQl + aoff + ks * 32);
#pragma unroll
            for (int fp = 0; fp < 8; fp++) {
                unsigned bh[4], bl[4];
                ldsm4(bh, bKh + bS + fp * (16 * CST * 2) + ks * 32);
                ldsm4(bl, bKl + bS + fp * (16 * CST * 2) + ks * 32);
#pragma unroll
                for (int hh = 0; hh < 2; hh++) {
                    float* c = Sa[fp * 2 + hh];
                    mma16816(c, ah, &bh[2 * hh]);
                    mma16816(c, ah, &bl[2 * hh]);
                    mma16816(c, al, &bh[2 * hh]);
                }
            }
        }

        float mx0 = -1e30f, mx1 = -1e30f;
#pragma unroll
        for (int j = 0; j < 16; j++) {
            mx0 = fmaxf(mx0, fmaxf(-Sa[j][0], -Sa[j][1]));
            mx1 = fmaxf(mx1, fmaxf(-Sa[j][2], -Sa[j][3]));
        }
        mx0 = fmaxf(mx0, __shfl_xor_sync(0xffffffffu, mx0, 1));
        mx0 = fmaxf(mx0, __shfl_xor_sync(0xffffffffu, mx0, 2));
        mx1 = fmaxf(mx1, __shfl_xor_sync(0xffffffffu, mx1, 1));
        mx1 = fmaxf(mx1, __shfl_xor_sync(0xffffffffu, mx1, 2));
        const float mn0 = fmaxf(m0r, mx0), mn1 = fmaxf(m1r, mx1);
        const float sc0 = __expf(m0r - mn0), sc1 = __expf(m1r - mn1);
        float rs0 = 0.f, rs1 = 0.f;
#pragma unroll
        for (int j = 0; j < 16; j++) {
            float p0 = __expf(-Sa[j][0] - mn0); Sa[j][0] = p0; rs0 += p0;
            float p1 = __expf(-Sa[j][1] - mn0); Sa[j][1] = p1; rs0 += p1;
            float p2 = __expf(-Sa[j][2] - mn1); Sa[j][2] = p2; rs1 += p2;
            float p3 = __expf(-Sa[j][3] - mn1); Sa[j][3] = p3; rs1 += p3;
        }
        rs0 += __shfl_xor_sync(0xffffffffu, rs0, 1);
        rs0 += __shfl_xor_sync(0xffffffffu, rs0, 2);
        rs1 += __shfl_xor_sync(0xffffffffu, rs1, 1);
        rs1 += __shfl_xor_sync(0xffffffffu, rs1, 2);
        l0r = l0r * sc0 + rs0;  l1r = l1r * sc1 + rs1;
        m0r = mn0;  m1r = mn1;
#pragma unroll
        for (int j = 0; j < 16; j++) {
            Oa[j][0] *= sc0; Oa[j][1] *= sc0;
            Oa[j][2] *= sc1; Oa[j][3] *= sc1;
        }

#pragma unroll
        for (int kp = 0; kp < 8; kp++) {
            const float* p0 = Sa[2 * kp];
            const float* p1 = Sa[2 * kp + 1];
            unsigned aPh[4];
            aPh[0] = packbf(p0[0], p0[1]);
            aPh[1] = packbf(p0[2], p0[3]);
            aPh[2] = packbf(p1[0], p1[1]);
            aPh[3] = packbf(p1[2], p1[3]);
#pragma unroll
            for (int fp = 0; fp < 8; fp++) {
                unsigned vh[4], vl[4];
                ldsm4t(vh, bKh + bT + kp * (16 * CST * 2) + fp * 32);
                ldsm4t(vl, bKl + bT + kp * (16 * CST * 2) + fp * 32);
#pragma unroll
                for (int hh = 0; hh < 2; hh++) {
                    float* c = Oa[fp * 2 + hh];
                    mma16816(c, aPh, &vh[2 * hh]);
                    mma16816(c, aPh, &vl[2 * hh]);
                }
            }
        }
        __syncthreads();
    }
#undef LOADK

    const float gam = *gptr;
    const float i0 = gam / l0r, i1 = gam / l1r;
    const int r0 = c0 + wid * 16 + g, r1 = r0 + 8;
    float* O = outg + (long)b * CCH * HW;
#pragma unroll
    for (int j = 0; j < 16; j++) {
        const int col = j * 8 + t * 2;
        const long o0 = (long)r0 * HW + col;
        const long o1 = (long)r1 * HW + col;
        float2 y0 = *(const float2*)&Y[o0];
        float2 y1v = *(const float2*)&Y[o1];
        float2 w0, w1;
        w0.x = Oa[j][0] * i0 + y0.x;  w0.y = Oa[j][1] * i0 + y0.y;
        w1.x = Oa[j][2] * i1 + y1v.x; w1.y = Oa[j][3] * i1 + y1v.y;
        *(float2*)&O[o0] = w0;
        *(float2*)&O[o1] = w1;
    }
}

// ------------------------ graph construction -------------------------------
__global__ void graph_build(const float* __restrict__ ip,
                            const float* __restrict__ adj,
                            __nv_bfloat16* __restrict__ gh,
                            __nv_bfloat16* __restrict__ gl)
{
    __shared__ float reda[4], redb[4];
    const int n = blockIdx.y, v = blockIdx.x, w = threadIdx.x;
    const long base = ((long)n * VV + v) * VV;

    const float sqv = ip[((long)n * VV + v) * VV + v];
    const float sqw = ip[((long)n * VV + w) * VV + w];
    const float e   = ip[base + w];

    float d2   = sqv + sqw - 2.f * e;
    float dist = sqrtf(fmaxf(d2, 1e-12f));
    float sim  = 2.f / (expf(dist) + 1.f);
    float av   = adj[base + w];
    if (w == v) { sim = 0.f; av = 0.f; }

    float s1 = warpSum(fabsf(sim));
    float s2 = warpSum(fabsf(av));
    if ((w & 31) == 0) { reda[w >> 5] = s1; redb[w >> 5] = s2; }
    __syncthreads();
    const float ssum = reda[0] + reda[1] + reda[2] + reda[3];
    const float asum = redb[0] + redb[1] + redb[2] + redb[3];

    float gv = 0.5f * (av / fmaxf(asum, 1e-12f) + sim / fmaxf(ssum, 1e-12f));
    __nv_bfloat16 hh, ll;
    bsplit(gv, hh, ll);
    gh[base + w] = hh;
    gl[base + w] = ll;
}

// ------------------------- batch-norm stats --------------------------------
__global__ void bn_stats(const float* __restrict__ hp,
                         float* __restrict__ mean, float* __restrict__ var,
                         int rows, int C)
{
    __shared__ float shs[8][32];
    __shared__ float shs2[8][32];
    const int lane = threadIdx.x & 31;
    const int ry   = threadIdx.x >> 5;
    const int c    = blockIdx.x * 32 + lane;

    float s = 0.f, s2 = 0.f;
    for (int r = ry; r < rows; r += 8) {
        float v = hp[(long)r * C + c];
        s += v; s2 += v * v;
    }
    shs[ry][lane] = s; shs2[ry][lane] = s2;
    __syncthreads();
    if (ry == 0) {
#pragma unroll
        for (int j = 1; j < 8; j++) { s += shs[j][lane]; s2 += shs2[j][lane]; }
        float mu = s / rows;
        mean[c] = mu;
        var[c]  = s2 / rows - mu * mu;
    }
}

// ------------------- BN apply + LeakyReLU + residual -----------------------
__global__ void bn_apply(const float* __restrict__ inp,
                         const float* __restrict__ hp,
                         const float* __restrict__ mean,
                         const float* __restrict__ var,
                         const float* __restrict__ bw,
                         const float* __restrict__ bb,
                         const float* __restrict__ gptr,
                         float* __restrict__ out,
                         __nv_bfloat16* __restrict__ oh,
                         __nv_bfloat16* __restrict__ ol,
                         int total, int C)
{
    const int idx = blockIdx.x * blockDim.x + threadIdx.x;
    if (idx >= total) return;
    const int c = idx & (C - 1);
    const float g = *gptr;
    float vv = (hp[idx] - mean[c]) * rsqrtf(var[c] + 1e-5f) * bw[c] + bb[c];
    float lr = vv > 0.f ? vv : 0.1f * vv;
    float o = inp[idx] + g * lr;
    out[idx] = o;
    if (oh) {
        __nv_bfloat16 hh, ll;
        bsplit(o, hh, ll);
        oh[idx] = hh;
        ol[idx] = ll;
    }
}

// ------------------------------ host side ----------------------------------
typedef __nv_bfloat16 bf;

static void launch_tb(int TA, int TB,
                      const bf* Ah, const bf* Al, const bf* Bh, const bf* Bl,
                      float* C, bf* Ch, bf* Cl,
                      int M, int N, int K,
                      long sA, long sB, long sC, int batch,
                      const float* bias, const float* Res, long sRes,
                      float aH, const float* aD, cudaStream_t st)
{
    dim3 grid(N / 128, M / 128, batch);
    dim3 blk(256);
    if (TA == 0 && TB == 0)
        tbgemm_kernel<0, 0><<<grid, blk, TSMEM, st>>>(Ah, Al, Bh, Bl, C, Ch, Cl,
            M, N, K, sA, sB, sC, bias, Res, sRes, aH, aD);
    else if (TA == 1 && TB == 0)
        tbgemm_kernel<1, 0><<<grid, blk, TSMEM, st>>>(Ah, Al, Bh, Bl, C, Ch, Cl,
            M, N, K, sA, sB, sC, bias, Res, sRes, aH, aD);
    else
        tbgemm_kernel<0, 1><<<grid, blk, TSMEM, st>>>(Ah, Al, Bh, Bl, C, Ch, Cl,
            M, N, K, sA, sB, sC, bias, Res, sRes, aH, aD);
}

extern "C" void kernel_launch(void* const* d_in, const int* in_sizes, int n_in,
                              void* d_out, int out_size)
{
    const float* x     = (const float*)d_in[0];
    const float* vfeat = (const float*)d_in[1];
    const float* adj   = (const float*)d_in[2];
    const float* Wq    = (const float*)d_in[3];
    const float* bq    = (const float*)d_in[4];
    const float* Wk    = (const float*)d_in[5];
    const float* bk    = (const float*)d_in[6];
    const float* Wv    = (const float*)d_in[7];
    const float* bv    = (const float*)d_in[8];
    const float* gpam  = (const float*)d_in[9];
    const float* gcam  = (const float*)d_in[10];
    const float* Wg    = (const float*)d_in[11];
    const float* bnw   = (const float*)d_in[12];
    const float* bnb   = (const float*)d_in[13];
    const float* gg    = (const float*)d_in[14];
    float* out = (float*)d_out;

    float *att1, *y1, *ip, *hp, *gbuf, *mean, *var;
    bf *y1h, *y1l, *xh, *xl, *wqh, *wql, *wkh, *wkl, *wvh, *wvl;
    bf *qh, *ql, *kh, *kl, *vh, *vl, *a1h, *a1l;
    bf *vfh, *vfl, *gbh, *gbl, *wgh, *wgl, *hh_, *hl_, *gph, *gpl;
    cudaGetSymbolAddress((void**)&att1, d_att1);
    cudaGetSymbolAddress((void**)&y1,   d_y1);
    cudaGetSymbolAddress((void**)&y1h,  d_y1h);
    cudaGetSymbolAddress((void**)&y1l,  d_y1l);
    cudaGetSymbolAddress((void**)&ip,   d_ip);
    cudaGetSymbolAddress((void**)&hp,   d_hp);
    cudaGetSymbolAddress((void**)&gbuf, d_gbuf);
    cudaGetSymbolAddress((void**)&mean, d_mean);
    cudaGetSymbolAddress((void**)&var,  d_var);
    cudaGetSymbolAddress((void**)&xh,   d_xh);
    cudaGetSymbolAddress((void**)&xl,   d_xl);
    cudaGetSymbolAddress((void**)&wqh,  d_wqh);
    cudaGetSymbolAddress((void**)&wql,  d_wql);
    cudaGetSymbolAddress((void**)&wkh,  d_wkh);
    cudaGetSymbolAddress((void**)&wkl,  d_wkl);
    cudaGetSymbolAddress((void**)&wvh,  d_wvh);
    cudaGetSymbolAddress((void**)&wvl,  d_wvl);
    cudaGetSymbolAddress((void**)&qh,   d_qh);
    cudaGetSymbolAddress((void**)&ql,   d_ql);
    cudaGetSymbolAddress((void**)&kh,   d_kh);
    cudaGetSymbolAddress((void**)&kl,   d_kl);
    cudaGetSymbolAddress((void**)&vh,   d_vh);
    cudaGetSymbolAddress((void**)&vl,   d_vl);
    cudaGetSymbolAddress((void**)&a1h,  d_a1h);
    cudaGetSymbolAddress((void**)&a1l,  d_a1l);
    cudaGetSymbolAddress((void**)&vfh,  d_vfh);
    cudaGetSymbolAddress((void**)&vfl,  d_vfl);
    cudaGetSymbolAddress((void**)&gbh,  d_gbh);
    cudaGetSymbolAddress((void**)&gbl,  d_gbl);
    cudaGetSymbolAddress((void**)&wgh,  d_wgh);
    cudaGetSymbolAddress((void**)&wgl,  d_wgl);
    cudaGetSymbolAddress((void**)&hh_,  d_hh);
    cudaGetSymbolAddress((void**)&hl_,  d_hl);
    cudaGetSymbolAddress((void**)&gph,  d_gph);
    cudaGetSymbolAddress((void**)&gpl,  d_gpl);

    static int inited = 0;
    if (!inited) {
        cudaFuncSetAttribute(tbgemm_kernel<0, 0>,
                             cudaFuncAttributeMaxDynamicSharedMemorySize, TSMEM);
        cudaFuncSetAttribute(tbgemm_kernel<1, 0>,
                             cudaFuncAttributeMaxDynamicSharedMemorySize, TSMEM);
        cudaFuncSetAttribute(tbgemm_kernel<0, 1>,
                             cudaFuncAttributeMaxDynamicSharedMemorySize, TSMEM);
        cudaFuncSetAttribute(cam_tc_kernel,
                             cudaFuncAttributeMaxDynamicSharedMemorySize, CAM_SMEM);
        inited = 1;
    }
    static cudaStream_t s1 = [](){ cudaStream_t s;
        cudaStreamCreateWithFlags(&s, cudaStreamNonBlocking); return s; }();
    static cudaStream_t s2 = [](){ cudaStream_t s;
        cudaStreamCreateWithFlags(&s, cudaStreamNonBlocking); return s; }();
    static cudaStream_t s3 = [](){ cudaStream_t s;
        cudaStreamCreateWithFlags(&s, cudaStreamNonBlocking); return s; }();
    static cudaEvent_t evF = [](){ cudaEvent_t e;
        cudaEventCreateWithFlags(&e, cudaEventDisableTiming); return e; }();
    static cudaEvent_t evK = [](){ cudaEvent_t e;
        cudaEventCreateWithFlags(&e, cudaEventDisableTiming); return e; }();
    static cudaEvent_t evV = [](){ cudaEvent_t e;
        cudaEventCreateWithFlags(&e, cudaEventDisableTiming); return e; }();
    static cudaEvent_t evSP = [](){ cudaEvent_t e;
        cudaEventCreateWithFlags(&e, cudaEventDisableTiming); return e; }();
    static cudaEvent_t evG0 = [](){ cudaEvent_t e;
        cudaEventCreateWithFlags(&e, cudaEventDisableTiming); return e; }();
    static cudaEvent_t evG1 = [](){ cudaEvent_t e;
        cudaEventCreateWithFlags(&e, cudaEventDisableTiming); return e; }();
    static cudaEvent_t evL0 = [](){ cudaEvent_t e;
        cudaEventCreateWithFlags(&e, cudaEventDisableTiming); return e; }();
    static cudaEvent_t evJ = [](){ cudaEvent_t e;
        cudaEventCreateWithFlags(&e, cudaEventDisableTiming); return e; }();
    static cudaEvent_t evJ3 = [](){ cudaEvent_t e;
        cudaEventCreateWithFlags(&e, cudaEventDisableTiming); return e; }();

    const long CHW = (long)CCH * HW;          // 262144
    const long QHW = (long)C8 * HW;           // 32768
    const long GST = (long)VV * CCH;          // 262144
    cudaStream_t s0 = 0;

    // ---- split x first (all projections need it), then fork ----
    split_f32_kernel<<<(BSZ * CCH * HW) / 1024, 256, 0, s0>>>(x, xh, xl);
    cudaEventRecord(evF, s0);
    cudaStreamWaitEvent(s1, evF, 0);
    cudaStreamWaitEvent(s2, evF, 0);

    // ---------------- PAM ----------------
    split_f32_kernel<<<(C8 * CCH) / 1024, 256, 0, s0>>>(Wq, wqh, wql);
    launch_tb(0, 0, wqh, wql, xh, xl, nullptr, qh, ql,
              C8, HW, CCH, 0, CHW, QHW, BSZ, bq, nullptr, 0, 1.f, nullptr, s0);

    split_f32_kernel<<<(C8 * CCH) / 1024, 256, 0, s1>>>(Wk, wkh, wkl);
    launch_tb(0, 0, wkh, wkl, xh, xl, nullptr, kh, kl,
              C8, HW, CCH, 0, CHW, QHW, BSZ, bk, nullptr, 0, 1.f, nullptr, s1);
    cudaEventRecord(evK, s1);
    split_f32_kernel<<<(CCH * CCH) / 1024, 256, 0, s1>>>(Wv, wvh, wvl);
    launch_tb(0, 0, wvh, wvl, xh, xl, nullptr, vh, vl,
              CCH, HW, CCH, 0, CHW, CHW, BSZ, bv, nullptr, 0, 1.f, nullptr, s1);
    cudaEventRecord(evV, s1);

    cudaStreamWaitEvent(s0, evK, 0);
    launch_tb(1, 0, qh, ql, kh, kl, att1, nullptr, nullptr,
              HW, HW, C8, QHW, QHW, (long)HW * HW, BSZ,
              nullptr, nullptr, 0, 1.f, nullptr, s0);
    softmax_kernel<<<BSZ * HW, 128, 0, s0>>>(att1, a1h, a1l, HW);
    cudaStreamWaitEvent(s0, evV, 0);
    launch_tb(0, 1, vh, vl, a1h, a1l, y1, y1h, y1l,
              CCH, HW, HW, CHW, (long)HW * HW, CHW, BSZ,
              nullptr, x, CHW, 0.f, gpam, s0);

    // ---------------- CAM (s0) ----------------
    {
        dim3 grid(CCH / 128, BSZ);
        cam_tc_kernel<<<grid, 256, CAM_SMEM, s0>>>(y1, y1h, y1l, gcam, out);
    }

    // ------------- Graph layers: s2 = h/hp/bn, s3 = ip/graph -------------
    split_f32_kernel<<<(NV * VV * CCH) / 1024, 256, 0, s2>>>(vfeat, vfh, vfl);
    split_f32_kernel<<<(GNUM * CCH * CCH) / 1024, 256, 0, s2>>>(Wg, wgh, wgl);
    cudaEventRecord(evSP, s2);
    cudaStreamWaitEvent(s3, evSP, 0);

    for (int i = 0; i < GNUM; i++) {
        const bf* ih = (i == 0) ? vfh : gbh;
        const bf* il = (i == 0) ? vfl : gbl;
        const float* inp = (i == 0) ? vfeat : gbuf;
        float* outg = (i == GNUM - 1) ? (out + (long)BSZ * CCH * HW) : gbuf;
        cudaEvent_t evG = (i == 0) ? evG0 : evG1;

        // s3: ip + graph_build (parallel with s2's big h-GEMM)
        if (i == 1) cudaStreamWaitEvent(s3, evL0, 0);   // needs gbh from layer 0
        launch_tb(0, 1, ih, il, ih, il, ip, nullptr, nullptr,
                  VV, VV, CCH, GST, GST, (long)VV * VV, NV,
                  nullptr, nullptr, 0, 1.f, nullptr, s3);
        graph_build<<<dim3(VV, NV), VV, 0, s3>>>(ip, adj, gph, gpl);
        cudaEventRecord(evG, s3);

        // s2: h-GEMM, then hp (after graph ready)
        launch_tb(0, 1, ih, il, wgh + (long)i * CCH * CCH, wgl + (long)i * CCH * CCH,
                  nullptr, hh_, hl_, NV * VV, CCH, CCH, 0, 0, 0, 1,
                  nullptr, nullptr, 0, 1.f, nullptr, s2);
        cudaStreamWaitEvent(s2, evG, 0);
        launch_tb(0, 0, gph, gpl, hh_, hl_, hp, nullptr, nullptr,
                  VV, CCH, VV, (long)VV * VV, GST, GST, NV,
                  nullptr, nullptr, 0, 1.f, nullptr, s2);
        bn_stats<<<CCH / 32, 256, 0, s2>>>(hp, mean, var, NV * VV, CCH);
        bn_apply<<<(NV * VV * CCH + 255) / 256, 256, 0, s2>>>(
            inp, hp, mean, var, bnw + (long)i * CCH, bnb + (long)i * CCH,
            gg + i, outg,
            (i == GNUM - 1) ? nullptr : gbh,
            (i == GNUM - 1) ? nullptr : gbl,
            NV * VV * CCH, CCH);
        if (i == 0) cudaEventRecord(evL0, s2);
    }

    // ---- join ----
    cudaEventRecord(evJ, s2);
    cudaStreamWaitEvent(s0, evJ, 0);
    cudaEventRecord(evJ3, s3);
    cudaStreamWaitEvent(s0, evJ3, 0);
}